// round 4
// baseline (speedup 1.0000x reference)
#include <cuda_runtime.h>
#include <cuda_bf16.h>
#include <math.h>

// Problem constants
#define Bb 2
#define LL 2048
#define DD 256
#define KK 32
#define FF 64          // 2*K feature dim
#define MM (Bb*LL)     // 4096 rows
#define CC 128         // chunk size
#define NC (LL/CC)     // 16 chunks per batch
#define PI_F 3.14159265358979323846f

// ---------------- scratch (device globals; no allocation allowed) ----------------
__device__ float g_hk[MM*DD];
__device__ float g_hq[MM*DD];
__device__ float g_vc[MM*DD];
__device__ float g_vp[MM*DD];
__device__ float g_g1[MM*64];
__device__ float g_kf[MM*FF];
__device__ float g_qf[MM*FF];
__device__ float g_gates[MM*2];
__device__ float g_Spart[Bb*NC*4*FF*DD];   // per-32-row content state partials
__device__ float g_P[Bb*NC*FF*DD];         // chunk-level exclusive prefix of states
__device__ float g_psnap[Bb*64*4*2*DD];    // pos accum snapshots every 8 rows (inclusive)
__device__ float g_pprefix[Bb*64*2*DD];    // exclusive prefix at 32-row granularity
__device__ float g_scores[Bb*NC*CC*CC];    // intra-chunk masked scores
__device__ float g_cont[MM*DD];
__device__ float g_norm[MM*DD];

// ---------------- tf32 helpers ----------------
__device__ __forceinline__ float f2tf32f(float f) {
    unsigned u;
    asm("cvt.rna.tf32.f32 %0, %1;" : "=r"(u) : "f"(f));
    return __uint_as_float(u);
}

__device__ __forceinline__ void mma_tf32(float c[4],
    unsigned a0, unsigned a1, unsigned a2, unsigned a3,
    unsigned b0, unsigned b1)
{
    asm volatile(
        "mma.sync.aligned.m16n8k8.row.col.f32.tf32.tf32.f32 "
        "{%0,%1,%2,%3}, {%4,%5,%6,%7}, {%8,%9}, {%0,%1,%2,%3};"
        : "+f"(c[0]), "+f"(c[1]), "+f"(c[2]), "+f"(c[3])
        : "r"(a0), "r"(a1), "r"(a2), "r"(a3), "r"(b0), "r"(b1));
}

// ================= Kernel 1: fused first-layer GEMMs, 128x128 tiles =================
// grid (32, 8): y>>1 = segment {hk(tanh)|hq(tanh)|vc|vp}, (y&1)*128 = col half
__global__ __launch_bounds__(256) void k1_mma(
    const float* __restrict__ x,
    const float* __restrict__ Wk1, const float* __restrict__ bk1,
    const float* __restrict__ Wq1, const float* __restrict__ bq1,
    const float* __restrict__ Wvc, const float* __restrict__ bvc,
    const float* __restrict__ Wvp, const float* __restrict__ bvp)
{
    __shared__ float As[2][128][20];
    __shared__ float Bs[2][16][132];
    int ct = blockIdx.y;
    int seg = ct >> 1;
    int colbase = (ct & 1) * 128;
    const float* W; const float* bias; float* outp; int act;
    if (seg == 0)      { W = Wk1; bias = bk1; outp = g_hk; act = 1; }
    else if (seg == 1) { W = Wq1; bias = bq1; outp = g_hq; act = 1; }
    else if (seg == 2) { W = Wvc; bias = bvc; outp = g_vc; act = 0; }
    else               { W = Wvp; bias = bvp; outp = g_vp; act = 0; }
    int row0 = blockIdx.x * 128;
    int tid = threadIdx.x;
    int w = tid >> 5, lane = tid & 31;
    int wm = (w & 3) * 32, wn = (w >> 2) * 64;
    int lq = lane >> 2, lr = lane & 3;
    int r0 = tid >> 2, c4 = (tid & 3) * 4;
    int rB = tid >> 5, cB = (tid & 31) * 4;
    float c[2][8][4] = {};
    float4 av0, av1, bv0, bv1;

    av0 = *(const float4*)&x[(row0 + r0) * 256 + c4];
    av1 = *(const float4*)&x[(row0 + r0 + 64) * 256 + c4];
    bv0 = *(const float4*)&W[rB * 256 + colbase + cB];
    bv1 = *(const float4*)&W[(rB + 8) * 256 + colbase + cB];
    As[0][r0][c4+0]=f2tf32f(av0.x); As[0][r0][c4+1]=f2tf32f(av0.y);
    As[0][r0][c4+2]=f2tf32f(av0.z); As[0][r0][c4+3]=f2tf32f(av0.w);
    As[0][r0+64][c4+0]=f2tf32f(av1.x); As[0][r0+64][c4+1]=f2tf32f(av1.y);
    As[0][r0+64][c4+2]=f2tf32f(av1.z); As[0][r0+64][c4+3]=f2tf32f(av1.w);
    Bs[0][rB][cB+0]=f2tf32f(bv0.x); Bs[0][rB][cB+1]=f2tf32f(bv0.y);
    Bs[0][rB][cB+2]=f2tf32f(bv0.z); Bs[0][rB][cB+3]=f2tf32f(bv0.w);
    Bs[0][rB+8][cB+0]=f2tf32f(bv1.x); Bs[0][rB+8][cB+1]=f2tf32f(bv1.y);
    Bs[0][rB+8][cB+2]=f2tf32f(bv1.z); Bs[0][rB+8][cB+3]=f2tf32f(bv1.w);
    __syncthreads();

    for (int s = 0; s < 16; s++) {
        int cur = s & 1;
        if (s < 15) {
            int kn = (s + 1) * 16;
            av0 = *(const float4*)&x[(row0 + r0) * 256 + kn + c4];
            av1 = *(const float4*)&x[(row0 + r0 + 64) * 256 + kn + c4];
            bv0 = *(const float4*)&W[(kn + rB) * 256 + colbase + cB];
            bv1 = *(const float4*)&W[(kn + rB + 8) * 256 + colbase + cB];
        }
        #pragma unroll
        for (int ks = 0; ks < 2; ks++) {
            unsigned a[2][4];
            #pragma unroll
            for (int mt = 0; mt < 2; mt++) {
                int rr = wm + mt*16 + lq;
                int cc = ks*8 + lr;
                a[mt][0] = __float_as_uint(As[cur][rr][cc]);
                a[mt][1] = __float_as_uint(As[cur][rr+8][cc]);
                a[mt][2] = __float_as_uint(As[cur][rr][cc+4]);
                a[mt][3] = __float_as_uint(As[cur][rr+8][cc+4]);
            }
            #pragma unroll
            for (int nt = 0; nt < 8; nt++) {
                int bn = wn + nt*8 + lq;
                unsigned b0 = __float_as_uint(Bs[cur][ks*8+lr][bn]);
                unsigned b1 = __float_as_uint(Bs[cur][ks*8+lr+4][bn]);
                #pragma unroll
                for (int mt = 0; mt < 2; mt++)
                    mma_tf32(c[mt][nt], a[mt][0], a[mt][1], a[mt][2], a[mt][3], b0, b1);
            }
        }
        if (s < 15) {
            int nb = cur ^ 1;
            As[nb][r0][c4+0]=f2tf32f(av0.x); As[nb][r0][c4+1]=f2tf32f(av0.y);
            As[nb][r0][c4+2]=f2tf32f(av0.z); As[nb][r0][c4+3]=f2tf32f(av0.w);
            As[nb][r0+64][c4+0]=f2tf32f(av1.x); As[nb][r0+64][c4+1]=f2tf32f(av1.y);
            As[nb][r0+64][c4+2]=f2tf32f(av1.z); As[nb][r0+64][c4+3]=f2tf32f(av1.w);
            Bs[nb][rB][cB+0]=f2tf32f(bv0.x); Bs[nb][rB][cB+1]=f2tf32f(bv0.y);
            Bs[nb][rB][cB+2]=f2tf32f(bv0.z); Bs[nb][rB][cB+3]=f2tf32f(bv0.w);
            Bs[nb][rB+8][cB+0]=f2tf32f(bv1.x); Bs[nb][rB+8][cB+1]=f2tf32f(bv1.y);
            Bs[nb][rB+8][cB+2]=f2tf32f(bv1.z); Bs[nb][rB+8][cB+3]=f2tf32f(bv1.w);
        }
        __syncthreads();
    }
    #pragma unroll
    for (int mt = 0; mt < 2; mt++) {
        #pragma unroll
        for (int nt = 0; nt < 8; nt++) {
            int r = row0 + wm + mt*16 + lq;
            int cc = colbase + wn + nt*8 + lr*2;
            float b0v = bias[cc], b1v = bias[cc+1];
            float v00 = c[mt][nt][0] + b0v, v01 = c[mt][nt][1] + b1v;
            float v10 = c[mt][nt][2] + b0v, v11 = c[mt][nt][3] + b1v;
            if (act == 1) { v00 = tanhf(v00); v01 = tanhf(v01); v10 = tanhf(v10); v11 = tanhf(v11); }
            *(float2*)&outp[r * 256 + cc] = make_float2(v00, v01);
            *(float2*)&outp[(r+8) * 256 + cc] = make_float2(v10, v11);
        }
    }
}

// ================= Kernel 1g: g1 = relu(x @ Wg1 + bg1), 128x64 tiles =================
__global__ __launch_bounds__(256) void k1g_mma(
    const float* __restrict__ x,
    const float* __restrict__ Wg1, const float* __restrict__ bg1)
{
    __shared__ float As[2][128][20];
    __shared__ float Bs[2][16][68];
    int row0 = blockIdx.x * 128;
    int tid = threadIdx.x;
    int w = tid >> 5, lane = tid & 31;
    int wm = (w & 3) * 32;
    int wn = (w >> 2) * 32;
    int lq = lane >> 2, lr = lane & 3;
    int r0 = tid >> 2, c4 = (tid & 3) * 4;
    int br = tid >> 4, bc4 = (tid & 15) * 4;
    float c[2][4][4] = {};
    float4 av0, av1, bv;

    av0 = *(const float4*)&x[(row0 + r0) * 256 + c4];
    av1 = *(const float4*)&x[(row0 + r0 + 64) * 256 + c4];
    bv  = *(const float4*)&Wg1[br * 64 + bc4];
    As[0][r0][c4+0]=f2tf32f(av0.x); As[0][r0][c4+1]=f2tf32f(av0.y);
    As[0][r0][c4+2]=f2tf32f(av0.z); As[0][r0][c4+3]=f2tf32f(av0.w);
    As[0][r0+64][c4+0]=f2tf32f(av1.x); As[0][r0+64][c4+1]=f2tf32f(av1.y);
    As[0][r0+64][c4+2]=f2tf32f(av1.z); As[0][r0+64][c4+3]=f2tf32f(av1.w);
    Bs[0][br][bc4+0]=f2tf32f(bv.x); Bs[0][br][bc4+1]=f2tf32f(bv.y);
    Bs[0][br][bc4+2]=f2tf32f(bv.z); Bs[0][br][bc4+3]=f2tf32f(bv.w);
    __syncthreads();

    for (int s = 0; s < 16; s++) {
        int cur = s & 1;
        if (s < 15) {
            int kn = (s + 1) * 16;
            av0 = *(const float4*)&x[(row0 + r0) * 256 + kn + c4];
            av1 = *(const float4*)&x[(row0 + r0 + 64) * 256 + kn + c4];
            bv  = *(const float4*)&Wg1[(kn + br) * 64 + bc4];
        }
        #pragma unroll
        for (int ks = 0; ks < 2; ks++) {
            unsigned a[2][4];
            #pragma unroll
            for (int mt = 0; mt < 2; mt++) {
                int rr = wm + mt*16 + lq;
                int cc = ks*8 + lr;
                a[mt][0] = __float_as_uint(As[cur][rr][cc]);
                a[mt][1] = __float_as_uint(As[cur][rr+8][cc]);
                a[mt][2] = __float_as_uint(As[cur][rr][cc+4]);
                a[mt][3] = __float_as_uint(As[cur][rr+8][cc+4]);
            }
            #pragma unroll
            for (int nt = 0; nt < 4; nt++) {
                int bn = wn + nt*8 + lq;
                unsigned b0 = __float_as_uint(Bs[cur][ks*8+lr][bn]);
                unsigned b1 = __float_as_uint(Bs[cur][ks*8+lr+4][bn]);
                #pragma unroll
                for (int mt = 0; mt < 2; mt++)
                    mma_tf32(c[mt][nt], a[mt][0], a[mt][1], a[mt][2], a[mt][3], b0, b1);
            }
        }
        if (s < 15) {
            int nb = cur ^ 1;
            As[nb][r0][c4+0]=f2tf32f(av0.x); As[nb][r0][c4+1]=f2tf32f(av0.y);
            As[nb][r0][c4+2]=f2tf32f(av0.z); As[nb][r0][c4+3]=f2tf32f(av0.w);
            As[nb][r0+64][c4+0]=f2tf32f(av1.x); As[nb][r0+64][c4+1]=f2tf32f(av1.y);
            As[nb][r0+64][c4+2]=f2tf32f(av1.z); As[nb][r0+64][c4+3]=f2tf32f(av1.w);
            Bs[nb][br][bc4+0]=f2tf32f(bv.x); Bs[nb][br][bc4+1]=f2tf32f(bv.y);
            Bs[nb][br][bc4+2]=f2tf32f(bv.z); Bs[nb][br][bc4+3]=f2tf32f(bv.w);
        }
        __syncthreads();
    }
    #pragma unroll
    for (int mt = 0; mt < 2; mt++) {
        #pragma unroll
        for (int nt = 0; nt < 4; nt++) {
            int r = row0 + wm + mt*16 + lq;
            int cc = wn + nt*8 + lr*2;
            float b0v = bg1[cc], b1v = bg1[cc+1];
            *(float2*)&g_g1[r * 64 + cc] =
                make_float2(fmaxf(c[mt][nt][0] + b0v, 0.f), fmaxf(c[mt][nt][1] + b1v, 0.f));
            *(float2*)&g_g1[(r+8) * 64 + cc] =
                make_float2(fmaxf(c[mt][nt][2] + b0v, 0.f), fmaxf(c[mt][nt][3] + b1v, 0.f));
        }
    }
}

// ================= Kernel 2: phase features (tf32 mma) + gates =================
__global__ __launch_bounds__(256) void k2_mma(
    const float* __restrict__ Wk2, const float* __restrict__ bk2,
    const float* __restrict__ Wq2, const float* __restrict__ bq2,
    const float* __restrict__ Wg2, const float* __restrict__ bg2)
{
    __shared__ float Ak[2][128][17];
    __shared__ float Aq[2][128][17];
    __shared__ float Bs[2][16][68];
    int tid = threadIdx.x;
    int w = tid >> 5, lane = tid & 31;
    int row0 = blockIdx.x * 128;
    int wm = (w & 3) * 32;
    bool isq = (w >= 4);
    int lq = lane >> 2, lr = lane & 3;
    int r0 = tid >> 2, c4 = (tid & 3) * 4;
    int br = tid >> 4, bc4 = (tid & 15) * 4;
    float c[2][4][4] = {};
    float4 ak0, ak1, aq0, aq1, bv;

    ak0 = *(const float4*)&g_hk[(row0 + r0) * 256 + c4];
    ak1 = *(const float4*)&g_hk[(row0 + r0 + 64) * 256 + c4];
    aq0 = *(const float4*)&g_hq[(row0 + r0) * 256 + c4];
    aq1 = *(const float4*)&g_hq[(row0 + r0 + 64) * 256 + c4];
    bv  = (bc4 < 32) ? *(const float4*)&Wk2[br * 32 + bc4]
                     : *(const float4*)&Wq2[br * 32 + bc4 - 32];
    {
        Ak[0][r0][c4+0]=f2tf32f(ak0.x); Ak[0][r0][c4+1]=f2tf32f(ak0.y);
        Ak[0][r0][c4+2]=f2tf32f(ak0.z); Ak[0][r0][c4+3]=f2tf32f(ak0.w);
        Ak[0][r0+64][c4+0]=f2tf32f(ak1.x); Ak[0][r0+64][c4+1]=f2tf32f(ak1.y);
        Ak[0][r0+64][c4+2]=f2tf32f(ak1.z); Ak[0][r0+64][c4+3]=f2tf32f(ak1.w);
        Aq[0][r0][c4+0]=f2tf32f(aq0.x); Aq[0][r0][c4+1]=f2tf32f(aq0.y);
        Aq[0][r0][c4+2]=f2tf32f(aq0.z); Aq[0][r0][c4+3]=f2tf32f(aq0.w);
        Aq[0][r0+64][c4+0]=f2tf32f(aq1.x); Aq[0][r0+64][c4+1]=f2tf32f(aq1.y);
        Aq[0][r0+64][c4+2]=f2tf32f(aq1.z); Aq[0][r0+64][c4+3]=f2tf32f(aq1.w);
        Bs[0][br][bc4+0]=f2tf32f(bv.x); Bs[0][br][bc4+1]=f2tf32f(bv.y);
        Bs[0][br][bc4+2]=f2tf32f(bv.z); Bs[0][br][bc4+3]=f2tf32f(bv.w);
    }
    __syncthreads();

    for (int s = 0; s < 16; s++) {
        int cur = s & 1;
        if (s < 15) {
            int kn = (s + 1) * 16;
            ak0 = *(const float4*)&g_hk[(row0 + r0) * 256 + kn + c4];
            ak1 = *(const float4*)&g_hk[(row0 + r0 + 64) * 256 + kn + c4];
            aq0 = *(const float4*)&g_hq[(row0 + r0) * 256 + kn + c4];
            aq1 = *(const float4*)&g_hq[(row0 + r0 + 64) * 256 + kn + c4];
            bv  = (bc4 < 32) ? *(const float4*)&Wk2[(kn + br) * 32 + bc4]
                             : *(const float4*)&Wq2[(kn + br) * 32 + bc4 - 32];
        }
        const float (*A)[17] = isq ? Aq[cur] : Ak[cur];
        #pragma unroll
        for (int ks = 0; ks < 2; ks++) {
            unsigned a[2][4];
            #pragma unroll
            for (int mt = 0; mt < 2; mt++) {
                int rr = wm + mt*16 + lq;
                int cc = ks*8 + lr;
                a[mt][0] = __float_as_uint(A[rr][cc]);
                a[mt][1] = __float_as_uint(A[rr+8][cc]);
                a[mt][2] = __float_as_uint(A[rr][cc+4]);
                a[mt][3] = __float_as_uint(A[rr+8][cc+4]);
            }
            #pragma unroll
            for (int nt = 0; nt < 4; nt++) {
                int bn = (isq ? 32 : 0) + nt*8 + lq;
                unsigned b0 = __float_as_uint(Bs[cur][ks*8+lr][bn]);
                unsigned b1 = __float_as_uint(Bs[cur][ks*8+lr+4][bn]);
                #pragma unroll
                for (int mt = 0; mt < 2; mt++)
                    mma_tf32(c[mt][nt], a[mt][0], a[mt][1], a[mt][2], a[mt][3], b0, b1);
            }
        }
        if (s < 15) {
            int nb = cur ^ 1;
            Ak[nb][r0][c4+0]=f2tf32f(ak0.x); Ak[nb][r0][c4+1]=f2tf32f(ak0.y);
            Ak[nb][r0][c4+2]=f2tf32f(ak0.z); Ak[nb][r0][c4+3]=f2tf32f(ak0.w);
            Ak[nb][r0+64][c4+0]=f2tf32f(ak1.x); Ak[nb][r0+64][c4+1]=f2tf32f(ak1.y);
            Ak[nb][r0+64][c4+2]=f2tf32f(ak1.z); Ak[nb][r0+64][c4+3]=f2tf32f(ak1.w);
            Aq[nb][r0][c4+0]=f2tf32f(aq0.x); Aq[nb][r0][c4+1]=f2tf32f(aq0.y);
            Aq[nb][r0][c4+2]=f2tf32f(aq0.z); Aq[nb][r0][c4+3]=f2tf32f(aq0.w);
            Aq[nb][r0+64][c4+0]=f2tf32f(aq1.x); Aq[nb][r0+64][c4+1]=f2tf32f(aq1.y);
            Aq[nb][r0+64][c4+2]=f2tf32f(aq1.z); Aq[nb][r0+64][c4+3]=f2tf32f(aq1.w);
            Bs[nb][br][bc4+0]=f2tf32f(bv.x); Bs[nb][br][bc4+1]=f2tf32f(bv.y);
            Bs[nb][br][bc4+2]=f2tf32f(bv.z); Bs[nb][br][bc4+3]=f2tf32f(bv.w);
        }
        __syncthreads();
    }

    const float* bvec = isq ? bq2 : bk2;
    float* fdst = isq ? g_qf : g_kf;
    #pragma unroll
    for (int mt = 0; mt < 2; mt++) {
        #pragma unroll
        for (int nt = 0; nt < 4; nt++) {
            int r = row0 + wm + mt*16 + lq;
            int cn = nt*8 + lr*2;
            float b0v = bvec[cn], b1v = bvec[cn+1];
            float ph;
            float sp, cp;
            ph = tanhf(c[mt][nt][0] + b0v) * PI_F; __sincosf(ph, &sp, &cp);
            fdst[r*64 + cn] = cp; fdst[r*64 + 32 + cn] = sp;
            ph = tanhf(c[mt][nt][1] + b1v) * PI_F; __sincosf(ph, &sp, &cp);
            fdst[r*64 + cn+1] = cp; fdst[r*64 + 32 + cn+1] = sp;
            ph = tanhf(c[mt][nt][2] + b0v) * PI_F; __sincosf(ph, &sp, &cp);
            fdst[(r+8)*64 + cn] = cp; fdst[(r+8)*64 + 32 + cn] = sp;
            ph = tanhf(c[mt][nt][3] + b1v) * PI_F; __sincosf(ph, &sp, &cp);
            fdst[(r+8)*64 + cn+1] = cp; fdst[(r+8)*64 + 32 + cn+1] = sp;
        }
    }
    // gates: each warp handles 16 rows
    for (int rr = 0; rr < 16; rr++) {
        int r = row0 + w*16 + rr;
        float p0 = 0.f, p1 = 0.f;
        #pragma unroll
        for (int i = lane; i < 64; i += 32) {
            float gv = g_g1[r*64 + i];
            p0 += gv * Wg2[i*2 + 0];
            p1 += gv * Wg2[i*2 + 1];
        }
        #pragma unroll
        for (int off = 16; off; off >>= 1) {
            p0 += __shfl_xor_sync(~0u, p0, off);
            p1 += __shfl_xor_sync(~0u, p1, off);
        }
        if (lane == 0) {
            float l0 = p0 + bg2[0], l1 = p1 + bg2[1];
            float m = fmaxf(l0, l1);
            float e0 = __expf(l0 - m), e1 = __expf(l1 - m);
            float inv = 1.f / (e0 + e1);
            g_gates[r*2 + 0] = e0 * inv;
            g_gates[r*2 + 1] = e1 * inv;
        }
    }
}

// ================= Kernel 3: per-32-row partial sums + 8-row pos snapshots ==========
__global__ __launch_bounds__(256) void k3_chunksum(const float* __restrict__ base_phases)
{
    __shared__ float kfs[8][64];
    int blk = blockIdx.x;            // (b*16+c)*4 + t
    int bc = blk >> 2, t = blk & 3;
    int b = bc >> 4, c = bc & 15;
    int d = threadIdx.x;
    int row0 = b * LL + c * CC + t * 32;
    int l0 = c * CC + t * 32;
    int s = c * 4 + t;
    float acc[64];
    #pragma unroll
    for (int f = 0; f < 64; f++) acc[f] = 0.f;
    float par = 0.f, pai = 0.f;
    for (int lt0 = 0; lt0 < 32; lt0 += 8) {
        __syncthreads();
        for (int i = d; i < 512; i += 256)
            kfs[i >> 6][i & 63] = g_kf[(row0 + lt0 + (i >> 6)) * 64 + (i & 63)];
        __syncthreads();
        #pragma unroll
        for (int j = 0; j < 8; j++) {
            int r = row0 + lt0 + j;
            float v = g_vc[r * 256 + d];
            #pragma unroll
            for (int f4 = 0; f4 < 16; f4++) {
                float4 kv = *(const float4*)&kfs[j][f4 * 4];
                acc[f4*4+0] += kv.x * v;
                acc[f4*4+1] += kv.y * v;
                acc[f4*4+2] += kv.z * v;
                acc[f4*4+3] += kv.w * v;
            }
            int l = l0 + lt0 + j;
            float ph = base_phases[l * 256 + d];
            float sp, cp; __sincosf(ph, &sp, &cp);
            float vp = g_vp[r * 256 + d];
            par += vp * cp; pai += vp * sp;
        }
        // inclusive snapshot after each 8-row group
        int snapbase = ((b * 64 + s) * 4 + (lt0 >> 3)) * 512;
        g_psnap[snapbase + d] = par;
        g_psnap[snapbase + 256 + d] = pai;
    }
    int base = blk * 64 * 256;
    #pragma unroll
    for (int f = 0; f < 64; f++) g_Spart[base + f * 256 + d] = acc[f];
}

// ================= Kernel 4: exclusive prefixes (front-batched loads) =================
__global__ __launch_bounds__(256) void k4_prefix()
{
    int tid = threadIdx.x;
    if (blockIdx.x < 128) {
        int idx = blockIdx.x * 256 + tid;       // (b, f*256+d) -> 32768 chains
        int b = idx >> 14, rd = idx & 16383;
        float v[64];
        #pragma unroll
        for (int c = 0; c < 16; c++)
            #pragma unroll
            for (int t = 0; t < 4; t++)
                v[c*4+t] = g_Spart[(((b * 16 + c) * 4) + t) * 16384 + rd];
        float run = 0.f;
        #pragma unroll
        for (int c = 0; c < 16; c++) {
            g_P[(b * 16 + c) * 16384 + rd] = run;
            run += (v[c*4] + v[c*4+1]) + (v[c*4+2] + v[c*4+3]);
        }
    } else {
        int e = (blockIdx.x - 128) * 256 + tid;
        if (e < 1024) {
            int b = e >> 9, rd = e & 511;
            float v[64];
            #pragma unroll
            for (int s = 0; s < 64; s++)
                v[s] = g_psnap[((b * 64 + s) * 4 + 3) * 512 + rd];  // 32-row sums
            float run = 0.f;
            #pragma unroll
            for (int s = 0; s < 64; s++) {
                g_pprefix[(b * 64 + s) * 512 + rd] = run;
                run += v[s];
            }
        }
    }
}

// ================= Kernel 5: intra-chunk masked scores (tf32 mma) =================
__global__ __launch_bounds__(256) void k5_mma()
{
    __shared__ float As[2][128][20];
    __shared__ float Bs[2][16][132];
    int bc = blockIdx.x; int b = bc >> 4, c = bc & 15;
    int row0 = b * LL + c * CC;
    int tid = threadIdx.x;
    int w = tid >> 5, lane = tid & 31;
    int wm = (w & 3) * 32;
    int wn = (w >> 2) * 64;
    int lq = lane >> 2, lr = lane & 3;
    int r0 = tid >> 2, c4 = (tid & 3) * 4;
    float acc[2][8][4] = {};
    float4 a0v, a1v, u0, u1;

    a0v = *(const float4*)&g_qf[(row0 + r0) * 64 + c4];
    a1v = *(const float4*)&g_qf[(row0 + r0 + 64) * 64 + c4];
    u0  = *(const float4*)&g_kf[(row0 + r0) * 64 + c4];
    u1  = *(const float4*)&g_kf[(row0 + r0 + 64) * 64 + c4];
    {
        As[0][r0][c4+0]=f2tf32f(a0v.x); As[0][r0][c4+1]=f2tf32f(a0v.y);
        As[0][r0][c4+2]=f2tf32f(a0v.z); As[0][r0][c4+3]=f2tf32f(a0v.w);
        As[0][r0+64][c4+0]=f2tf32f(a1v.x); As[0][r0+64][c4+1]=f2tf32f(a1v.y);
        As[0][r0+64][c4+2]=f2tf32f(a1v.z); As[0][r0+64][c4+3]=f2tf32f(a1v.w);
        Bs[0][c4+0][r0]=f2tf32f(u0.x); Bs[0][c4+1][r0]=f2tf32f(u0.y);
        Bs[0][c4+2][r0]=f2tf32f(u0.z); Bs[0][c4+3][r0]=f2tf32f(u0.w);
        Bs[0][c4+0][r0+64]=f2tf32f(u1.x); Bs[0][c4+1][r0+64]=f2tf32f(u1.y);
        Bs[0][c4+2][r0+64]=f2tf32f(u1.z); Bs[0][c4+3][r0+64]=f2tf32f(u1.w);
    }
    __syncthreads();

    for (int s = 0; s < 4; s++) {
        int cur = s & 1;
        if (s < 3) {
            int kn = (s + 1) * 16;
            a0v = *(const float4*)&g_qf[(row0 + r0) * 64 + kn + c4];
            a1v = *(const float4*)&g_qf[(row0 + r0 + 64) * 64 + kn + c4];
            u0  = *(const float4*)&g_kf[(row0 + r0) * 64 + kn + c4];
            u1  = *(const float4*)&g_kf[(row0 + r0 + 64) * 64 + kn + c4];
        }
        #pragma unroll
        for (int ks = 0; ks < 2; ks++) {
            unsigned a[2][4];
            #pragma unroll
            for (int mt = 0; mt < 2; mt++) {
                int rr = wm + mt*16 + lq;
                int cc = ks*8 + lr;
                a[mt][0] = __float_as_uint(As[cur][rr][cc]);
                a[mt][1] = __float_as_uint(As[cur][rr+8][cc]);
                a[mt][2] = __float_as_uint(As[cur][rr][cc+4]);
                a[mt][3] = __float_as_uint(As[cur][rr+8][cc+4]);
            }
            #pragma unroll
            for (int nt = 0; nt < 8; nt++) {
                int bn = wn + nt*8 + lq;
                unsigned b0 = __float_as_uint(Bs[cur][ks*8+lr][bn]);
                unsigned b1 = __float_as_uint(Bs[cur][ks*8+lr+4][bn]);
                #pragma unroll
                for (int mt = 0; mt < 2; mt++)
                    mma_tf32(acc[mt][nt], a[mt][0], a[mt][1], a[mt][2], a[mt][3], b0, b1);
            }
        }
        if (s < 3) {
            int nb = cur ^ 1;
            As[nb][r0][c4+0]=f2tf32f(a0v.x); As[nb][r0][c4+1]=f2tf32f(a0v.y);
            As[nb][r0][c4+2]=f2tf32f(a0v.z); As[nb][r0][c4+3]=f2tf32f(a0v.w);
            As[nb][r0+64][c4+0]=f2tf32f(a1v.x); As[nb][r0+64][c4+1]=f2tf32f(a1v.y);
            As[nb][r0+64][c4+2]=f2tf32f(a1v.z); As[nb][r0+64][c4+3]=f2tf32f(a1v.w);
            Bs[nb][c4+0][r0]=f2tf32f(u0.x); Bs[nb][c4+1][r0]=f2tf32f(u0.y);
            Bs[nb][c4+2][r0]=f2tf32f(u0.z); Bs[nb][c4+3][r0]=f2tf32f(u0.w);
            Bs[nb][c4+0][r0+64]=f2tf32f(u1.x); Bs[nb][c4+1][r0+64]=f2tf32f(u1.y);
            Bs[nb][c4+2][r0+64]=f2tf32f(u1.z); Bs[nb][c4+3][r0+64]=f2tf32f(u1.w);
        }
        __syncthreads();
    }
    int sb = bc * CC * CC;
    #pragma unroll
    for (int mt = 0; mt < 2; mt++) {
        #pragma unroll
        for (int nt = 0; nt < 8; nt++) {
            int la = wm + mt*16 + lq;
            int lb = la + 8;
            int j0 = wn + nt*8 + lr*2;
            int j1 = j0 + 1;
            *(float2*)&g_scores[sb + la*128 + j0] =
                make_float2(j0 <= la ? acc[mt][nt][0] : 0.f, j1 <= la ? acc[mt][nt][1] : 0.f);
            *(float2*)&g_scores[sb + lb*128 + j0] =
                make_float2(j0 <= lb ? acc[mt][nt][2] : 0.f, j1 <= lb ? acc[mt][nt][3] : 0.f);
        }
    }
}

// ================= Kernel 6: content output (tf32 mma): [qf | scores] @ [P ; vc] ======
__global__ __launch_bounds__(256) void k6_mma()
{
    __shared__ float As[2][128][20];
    __shared__ float Bs[2][16][68];
    int bc = blockIdx.x; int b = bc >> 4, c = bc & 15;
    int d0 = blockIdx.y * 64;
    int row0 = b * LL + c * CC;
    int tid = threadIdx.x;
    int w = tid >> 5, lane = tid & 31;
    int wm = (w & 3) * 32;
    int wn = (w >> 2) * 32;
    int lq = lane >> 2, lr = lane & 3;
    int r0 = tid >> 2, c4 = (tid & 3) * 4;
    int br = tid >> 4, bc4 = (tid & 15) * 4;
    int Pbase = bc * 64 * 256;
    int sbase = bc * CC * CC;
    float acc[2][4][4] = {};
    float4 a0v, a1v, bv;

    a0v = *(const float4*)&g_qf[(row0 + r0) * 64 + c4];
    a1v = *(const float4*)&g_qf[(row0 + r0 + 64) * 64 + c4];
    bv  = *(const float4*)&g_P[Pbase + br * 256 + d0 + bc4];
    {
        As[0][r0][c4+0]=f2tf32f(a0v.x); As[0][r0][c4+1]=f2tf32f(a0v.y);
        As[0][r0][c4+2]=f2tf32f(a0v.z); As[0][r0][c4+3]=f2tf32f(a0v.w);
        As[0][r0+64][c4+0]=f2tf32f(a1v.x); As[0][r0+64][c4+1]=f2tf32f(a1v.y);
        As[0][r0+64][c4+2]=f2tf32f(a1v.z); As[0][r0+64][c4+3]=f2tf32f(a1v.w);
        Bs[0][br][bc4+0]=f2tf32f(bv.x); Bs[0][br][bc4+1]=f2tf32f(bv.y);
        Bs[0][br][bc4+2]=f2tf32f(bv.z); Bs[0][br][bc4+3]=f2tf32f(bv.w);
    }
    __syncthreads();

    for (int s = 0; s < 12; s++) {
        int cur = s & 1;
        if (s < 11) {
            int kn = (s + 1) * 16;
            int kga = kn + c4;
            if (kga < 64) {
                a0v = *(const float4*)&g_qf[(row0 + r0) * 64 + kga];
                a1v = *(const float4*)&g_qf[(row0 + r0 + 64) * 64 + kga];
            } else {
                a0v = *(const float4*)&g_scores[sbase + r0 * 128 + kga - 64];
                a1v = *(const float4*)&g_scores[sbase + (r0 + 64) * 128 + kga - 64];
            }
            int kgb = kn + br;
            if (kgb < 64) bv = *(const float4*)&g_P[Pbase + kgb * 256 + d0 + bc4];
            else          bv = *(const float4*)&g_vc[(row0 + kgb - 64) * 256 + d0 + bc4];
        }
        #pragma unroll
        for (int ks = 0; ks < 2; ks++) {
            unsigned a[2][4];
            #pragma unroll
            for (int mt = 0; mt < 2; mt++) {
                int rr = wm + mt*16 + lq;
                int cc = ks*8 + lr;
                a[mt][0] = __float_as_uint(As[cur][rr][cc]);
                a[mt][1] = __float_as_uint(As[cur][rr+8][cc]);
                a[mt][2] = __float_as_uint(As[cur][rr][cc+4]);
                a[mt][3] = __float_as_uint(As[cur][rr+8][cc+4]);
            }
            #pragma unroll
            for (int nt = 0; nt < 4; nt++) {
                int bn = wn + nt*8 + lq;
                unsigned b0 = __float_as_uint(Bs[cur][ks*8+lr][bn]);
                unsigned b1 = __float_as_uint(Bs[cur][ks*8+lr+4][bn]);
                #pragma unroll
                for (int mt = 0; mt < 2; mt++)
                    mma_tf32(acc[mt][nt], a[mt][0], a[mt][1], a[mt][2], a[mt][3], b0, b1);
            }
        }
        if (s < 11) {
            int nb = cur ^ 1;
            As[nb][r0][c4+0]=f2tf32f(a0v.x); As[nb][r0][c4+1]=f2tf32f(a0v.y);
            As[nb][r0][c4+2]=f2tf32f(a0v.z); As[nb][r0][c4+3]=f2tf32f(a0v.w);
            As[nb][r0+64][c4+0]=f2tf32f(a1v.x); As[nb][r0+64][c4+1]=f2tf32f(a1v.y);
            As[nb][r0+64][c4+2]=f2tf32f(a1v.z); As[nb][r0+64][c4+3]=f2tf32f(a1v.w);
            Bs[nb][br][bc4+0]=f2tf32f(bv.x); Bs[nb][br][bc4+1]=f2tf32f(bv.y);
            Bs[nb][br][bc4+2]=f2tf32f(bv.z); Bs[nb][br][bc4+3]=f2tf32f(bv.w);
        }
        __syncthreads();
    }
    #pragma unroll
    for (int mt = 0; mt < 2; mt++) {
        #pragma unroll
        for (int nt = 0; nt < 4; nt++) {
            int la = wm + mt*16 + lq;
            int lb = la + 8;
            int cc = d0 + wn + nt*8 + lr*2;
            float sa = rsqrtf((float)((c*CC + la + 1) * KK));
            float sb2 = rsqrtf((float)((c*CC + lb + 1) * KK));
            *(float2*)&g_cont[(row0 + la) * 256 + cc] =
                make_float2(acc[mt][nt][0] * sa, acc[mt][nt][1] * sa);
            *(float2*)&g_cont[(row0 + lb) * 256 + cc] =
                make_float2(acc[mt][nt][2] * sb2, acc[mt][nt][3] * sb2);
        }
    }
}

// ================= Kernel 7: pos scan (8 rows/block) + gate combine + LayerNorm =========
__global__ __launch_bounds__(256) void k7_poscomb(
    const float* __restrict__ base_phases,
    const float* __restrict__ ln_g, const float* __restrict__ ln_b)
{
    __shared__ float comb[8][257];
    int blk = blockIdx.x;            // b*256 + s*4 + j
    int j = blk & 3;
    int s = (blk >> 2) & 63;
    int b = blk >> 8;
    int row0 = b * LL + s * 32 + j * 8;
    int l0 = s * 32 + j * 8;
    int d = threadIdx.x;
    float ar = g_pprefix[(b * 64 + s) * 512 + d];
    float ai = g_pprefix[(b * 64 + s) * 512 + 256 + d];
    if (j > 0) {
        int snapbase = ((b * 64 + s) * 4 + j - 1) * 512;
        ar += g_psnap[snapbase + d];
        ai += g_psnap[snapbase + 256 + d];
    }
    // front-batch all loads (MLP ~24)
    float vp[8], ph[8], cv[8];
    #pragma unroll
    for (int lt = 0; lt < 8; lt++) {
        vp[lt] = g_vp[(row0 + lt) * 256 + d];
        ph[lt] = base_phases[(l0 + lt) * 256 + d];
        cv[lt] = g_cont[(row0 + lt) * 256 + d];
    }
    #pragma unroll
    for (int lt = 0; lt < 8; lt++) {
        float sp, cp; __sincosf(ph[lt], &sp, &cp);
        ar += vp[lt] * cp; ai += vp[lt] * sp;
        float pret = (ar * cp + ai * sp) * rsqrtf((float)(l0 + lt + 1));
        float g0 = g_gates[(row0 + lt) * 2], g1v = g_gates[(row0 + lt) * 2 + 1];
        comb[lt][d] = g0 * pret + g1v * cv[lt];
    }
    __syncthreads();
    // LayerNorm: warp w handles row w
    int w = d >> 5, lane = d & 31;
    int r = row0 + w;
    float vals[8]; float s1 = 0.f, s2 = 0.f;
    #pragma unroll
    for (int k = 0; k < 8; k++) {
        float v = comb[w][lane + 32*k];
        vals[k] = v; s1 += v; s2 += v*v;
    }
    #pragma unroll
    for (int off = 16; off; off >>= 1) {
        s1 += __shfl_xor_sync(~0u, s1, off);
        s2 += __shfl_xor_sync(~0u, s2, off);
    }
    float mu = s1 * (1.f/256.f);
    float var = s2 * (1.f/256.f) - mu*mu;
    float rstd = rsqrtf(var + 1e-5f);
    #pragma unroll
    for (int k = 0; k < 8; k++) {
        int dd = lane + 32*k;
        g_norm[r*256 + dd] = (vals[k] - mu) * rstd * ln_g[dd] + ln_b[dd];
    }
}

// ================= Kernel 8: out = x + normed @ Wo + bo, 128x128 tiles ===============
__global__ __launch_bounds__(256) void k8_mma(
    const float* __restrict__ x, const float* __restrict__ Wo,
    const float* __restrict__ bo, float* __restrict__ out)
{
    __shared__ float As[2][128][20];
    __shared__ float Bs[2][16][132];
    int row0 = blockIdx.x * 128;
    int colbase = blockIdx.y * 128;
    int tid = threadIdx.x;
    int w = tid >> 5, lane = tid & 31;
    int wm = (w & 3) * 32, wn = (w >> 2) * 64;
    int lq = lane >> 2, lr = lane & 3;
    int r0 = tid >> 2, c4 = (tid & 3) * 4;
    int rB = tid >> 5, cB = (tid & 31) * 4;
    float c[2][8][4] = {};
    float4 av0, av1, bv0, bv1;

    av0 = *(const float4*)&g_norm[(row0 + r0) * 256 + c4];
    av1 = *(const float4*)&g_norm[(row0 + r0 + 64) * 256 + c4];
    bv0 = *(const float4*)&Wo[rB * 256 + colbase + cB];
    bv1 = *(const float4*)&Wo[(rB + 8) * 256 + colbase + cB];
    As[0][r0][c4+0]=f2tf32f(av0.x); As[0][r0][c4+1]=f2tf32f(av0.y);
    As[0][r0][c4+2]=f2tf32f(av0.z); As[0][r0][c4+3]=f2tf32f(av0.w);
    As[0][r0+64][c4+0]=f2tf32f(av1.x); As[0][r0+64][c4+1]=f2tf32f(av1.y);
    As[0][r0+64][c4+2]=f2tf32f(av1.z); As[0][r0+64][c4+3]=f2tf32f(av1.w);
    Bs[0][rB][cB+0]=f2tf32f(bv0.x); Bs[0][rB][cB+1]=f2tf32f(bv0.y);
    Bs[0][rB][cB+2]=f2tf32f(bv0.z); Bs[0][rB][cB+3]=f2tf32f(bv0.w);
    Bs[0][rB+8][cB+0]=f2tf32f(bv1.x); Bs[0][rB+8][cB+1]=f2tf32f(bv1.y);
    Bs[0][rB+8][cB+2]=f2tf32f(bv1.z); Bs[0][rB+8][cB+3]=f2tf32f(bv1.w);
    __syncthreads();

    for (int s = 0; s < 16; s++) {
        int cur = s & 1;
        if (s < 15) {
            int kn = (s + 1) * 16;
            av0 = *(const float4*)&g_norm[(row0 + r0) * 256 + kn + c4];
            av1 = *(const float4*)&g_norm[(row0 + r0 + 64) * 256 + kn + c4];
            bv0 = *(const float4*)&Wo[(kn + rB) * 256 + colbase + cB];
            bv1 = *(const float4*)&Wo[(kn + rB + 8) * 256 + colbase + cB];
        }
        #pragma unroll
        for (int ks = 0; ks < 2; ks++) {
            unsigned a[2][4];
            #pragma unroll
            for (int mt = 0; mt < 2; mt++) {
                int rr = wm + mt*16 + lq;
                int cc = ks*8 + lr;
                a[mt][0] = __float_as_uint(As[cur][rr][cc]);
                a[mt][1] = __float_as_uint(As[cur][rr+8][cc]);
                a[mt][2] = __float_as_uint(As[cur][rr][cc+4]);
                a[mt][3] = __float_as_uint(As[cur][rr+8][cc+4]);
            }
            #pragma unroll
            for (int nt = 0; nt < 8; nt++) {
                int bn = wn + nt*8 + lq;
                unsigned b0 = __float_as_uint(Bs[cur][ks*8+lr][bn]);
                unsigned b1 = __float_as_uint(Bs[cur][ks*8+lr+4][bn]);
                #pragma unroll
                for (int mt = 0; mt < 2; mt++)
                    mma_tf32(c[mt][nt], a[mt][0], a[mt][1], a[mt][2], a[mt][3], b0, b1);
            }
        }
        if (s < 15) {
            int nb = cur ^ 1;
            As[nb][r0][c4+0]=f2tf32f(av0.x); As[nb][r0][c4+1]=f2tf32f(av0.y);
            As[nb][r0][c4+2]=f2tf32f(av0.z); As[nb][r0][c4+3]=f2tf32f(av0.w);
            As[nb][r0+64][c4+0]=f2tf32f(av1.x); As[nb][r0+64][c4+1]=f2tf32f(av1.y);
            As[nb][r0+64][c4+2]=f2tf32f(av1.z); As[nb][r0+64][c4+3]=f2tf32f(av1.w);
            Bs[nb][rB][cB+0]=f2tf32f(bv0.x); Bs[nb][rB][cB+1]=f2tf32f(bv0.y);
            Bs[nb][rB][cB+2]=f2tf32f(bv0.z); Bs[nb][rB][cB+3]=f2tf32f(bv0.w);
            Bs[nb][rB+8][cB+0]=f2tf32f(bv1.x); Bs[nb][rB+8][cB+1]=f2tf32f(bv1.y);
            Bs[nb][rB+8][cB+2]=f2tf32f(bv1.z); Bs[nb][rB+8][cB+3]=f2tf32f(bv1.w);
        }
        __syncthreads();
    }
    #pragma unroll
    for (int mt = 0; mt < 2; mt++) {
        #pragma unroll
        for (int nt = 0; nt < 8; nt++) {
            int r = row0 + wm + mt*16 + lq;
            int cc = colbase + wn + nt*8 + lr*2;
            float b0v = bo[cc], b1v = bo[cc+1];
            float2 x0 = *(const float2*)&x[r * 256 + cc];
            float2 x1 = *(const float2*)&x[(r+8) * 256 + cc];
            *(float2*)&out[r * 256 + cc] =
                make_float2(c[mt][nt][0] + b0v + x0.x, c[mt][nt][1] + b1v + x0.y);
            *(float2*)&out[(r+8) * 256 + cc] =
                make_float2(c[mt][nt][2] + b0v + x1.x, c[mt][nt][3] + b1v + x1.y);
        }
    }
}

// ================= launcher =================
extern "C" void kernel_launch(void* const* d_in, const int* in_sizes, int n_in,
                              void* d_out, int out_size)
{
    const float* x   = (const float*)d_in[0];
    const float* bp  = (const float*)d_in[1];
    const float* Wk1 = (const float*)d_in[2];
    const float* bk1 = (const float*)d_in[3];
    const float* Wk2 = (const float*)d_in[4];
    const float* bk2 = (const float*)d_in[5];
    const float* Wq1 = (const float*)d_in[6];
    const float* bq1 = (const float*)d_in[7];
    const float* Wq2 = (const float*)d_in[8];
    const float* bq2 = (const float*)d_in[9];
    const float* Wvc = (const float*)d_in[10];
    const float* bvc = (const float*)d_in[11];
    const float* Wvp = (const float*)d_in[12];
    const float* bvp = (const float*)d_in[13];
    const float* Wg1 = (const float*)d_in[14];
    const float* bg1 = (const float*)d_in[15];
    const float* Wg2 = (const float*)d_in[16];
    const float* bg2 = (const float*)d_in[17];
    const float* lng = (const float*)d_in[18];
    const float* lnb = (const float*)d_in[19];
    const float* Wo  = (const float*)d_in[20];
    const float* bo  = (const float*)d_in[21];
    float* out = (float*)d_out;

    k1_mma<<<dim3(32, 8), 256>>>(x, Wk1, bk1, Wq1, bq1, Wvc, bvc, Wvp, bvp);
    k1g_mma<<<32, 256>>>(x, Wg1, bg1);
    k2_mma<<<32, 256>>>(Wk2, bk2, Wq2, bq2, Wg2, bg2);
    k3_chunksum<<<128, 256>>>(bp);
    k4_prefix<<<132, 256>>>();
    k5_mma<<<32, 256>>>();
    k6_mma<<<dim3(32, 4), 256>>>();
    k7_poscomb<<<512, 256>>>(bp, lng, lnb);
    k8_mma<<<dim3(32, 2), 256>>>(x, Wo, bo, out);
}

// round 6
// speedup vs baseline: 1.0735x; 1.0735x over previous
#include <cuda_runtime.h>
#include <cuda_bf16.h>
#include <math.h>

// Problem constants
#define Bb 2
#define LL 2048
#define DD 256
#define KK 32
#define FF 64          // 2*K feature dim
#define MM (Bb*LL)     // 4096 rows
#define CC 128         // chunk size
#define NC (LL/CC)     // 16 chunks per batch
#define PI_F 3.14159265358979323846f

// ---------------- scratch (device globals; no allocation allowed) ----------------
__device__ float g_hk[MM*DD];
__device__ float g_hq[MM*DD];
__device__ float g_vc[MM*DD];
__device__ float g_vp[MM*DD];
__device__ float g_g1[MM*64];
__device__ float g_kf[MM*FF];
__device__ float g_qf[MM*FF];
__device__ float g_gates[MM*2];
__device__ float g_S[Bb*NC*FF*DD];         // per-chunk content state sums (mma)
__device__ float g_P[Bb*NC*FF*DD];         // chunk-level exclusive prefix of states
__device__ float g_psnap[Bb*64*4*2*DD];    // pos accum snapshots every 8 rows (inclusive)
__device__ float g_pprefix[Bb*64*2*DD];    // exclusive prefix at 32-row granularity
__device__ float g_scores[Bb*NC*CC*CC];    // intra-chunk masked scores
__device__ float g_cont[MM*DD];
__device__ float g_norm[MM*DD];

// ---------------- tf32 helpers ----------------
__device__ __forceinline__ float f2tf32f(float f) {
    unsigned u;
    asm("cvt.rna.tf32.f32 %0, %1;" : "=r"(u) : "f"(f));
    return __uint_as_float(u);
}

__device__ __forceinline__ void mma_tf32(float c[4],
    unsigned a0, unsigned a1, unsigned a2, unsigned a3,
    unsigned b0, unsigned b1)
{
    asm volatile(
        "mma.sync.aligned.m16n8k8.row.col.f32.tf32.tf32.f32 "
        "{%0,%1,%2,%3}, {%4,%5,%6,%7}, {%8,%9}, {%0,%1,%2,%3};"
        : "+f"(c[0]), "+f"(c[1]), "+f"(c[2]), "+f"(c[3])
        : "r"(a0), "r"(a1), "r"(a2), "r"(a3), "r"(b0), "r"(b1));
}

// ================= Kernel 1: fused first-layer GEMMs (round-3 config) =================
// grid (32, 17): ct<16 -> [hk|hq|vc|vp] x 4 col-quarters; ct==16 -> g1
__global__ __launch_bounds__(256) void k1_mma(
    const float* __restrict__ x,
    const float* __restrict__ Wk1, const float* __restrict__ bk1,
    const float* __restrict__ Wq1, const float* __restrict__ bq1,
    const float* __restrict__ Wvc, const float* __restrict__ bvc,
    const float* __restrict__ Wvp, const float* __restrict__ bvp,
    const float* __restrict__ Wg1, const float* __restrict__ bg1)
{
    __shared__ float As[2][128][20];
    __shared__ float Bs[2][16][68];
    int ct = blockIdx.y;
    const float* W; const float* bias; float* outp; int Nseg; int act; int colbase;
    if (ct < 16) {
        int seg = ct >> 2;
        colbase = (ct & 3) * 64;
        Nseg = 256;
        if (seg == 0)      { W = Wk1; bias = bk1; outp = g_hk; act = 1; }
        else if (seg == 1) { W = Wq1; bias = bq1; outp = g_hq; act = 1; }
        else if (seg == 2) { W = Wvc; bias = bvc; outp = g_vc; act = 0; }
        else               { W = Wvp; bias = bvp; outp = g_vp; act = 0; }
    } else {
        W = Wg1; bias = bg1; outp = g_g1; Nseg = 64; act = 2; colbase = 0;
    }
    int row0 = blockIdx.x * 128;
    int tid = threadIdx.x;
    int w = tid >> 5, lane = tid & 31;
    int wm = (w & 3) * 32;
    int wn = (w >> 2) * 32;
    int lq = lane >> 2, lr = lane & 3;
    int r0 = tid >> 2, c4 = (tid & 3) * 4;
    int br = tid >> 4, bc4 = (tid & 15) * 4;
    float c[2][4][4] = {};
    float4 av0, av1, bv;

    av0 = *(const float4*)&x[(row0 + r0) * 256 + c4];
    av1 = *(const float4*)&x[(row0 + r0 + 64) * 256 + c4];
    bv  = *(const float4*)&W[br * Nseg + colbase + bc4];
    As[0][r0][c4+0]=f2tf32f(av0.x); As[0][r0][c4+1]=f2tf32f(av0.y);
    As[0][r0][c4+2]=f2tf32f(av0.z); As[0][r0][c4+3]=f2tf32f(av0.w);
    As[0][r0+64][c4+0]=f2tf32f(av1.x); As[0][r0+64][c4+1]=f2tf32f(av1.y);
    As[0][r0+64][c4+2]=f2tf32f(av1.z); As[0][r0+64][c4+3]=f2tf32f(av1.w);
    Bs[0][br][bc4+0]=f2tf32f(bv.x); Bs[0][br][bc4+1]=f2tf32f(bv.y);
    Bs[0][br][bc4+2]=f2tf32f(bv.z); Bs[0][br][bc4+3]=f2tf32f(bv.w);
    __syncthreads();

    for (int s = 0; s < 16; s++) {
        int cur = s & 1;
        if (s < 15) {
            int kn = (s + 1) * 16;
            av0 = *(const float4*)&x[(row0 + r0) * 256 + kn + c4];
            av1 = *(const float4*)&x[(row0 + r0 + 64) * 256 + kn + c4];
            bv  = *(const float4*)&W[(kn + br) * Nseg + colbase + bc4];
        }
        #pragma unroll
        for (int ks = 0; ks < 2; ks++) {
            unsigned a[2][4];
            #pragma unroll
            for (int mt = 0; mt < 2; mt++) {
                int rr = wm + mt*16 + lq;
                int cc = ks*8 + lr;
                a[mt][0] = __float_as_uint(As[cur][rr][cc]);
                a[mt][1] = __float_as_uint(As[cur][rr+8][cc]);
                a[mt][2] = __float_as_uint(As[cur][rr][cc+4]);
                a[mt][3] = __float_as_uint(As[cur][rr+8][cc+4]);
            }
            #pragma unroll
            for (int nt = 0; nt < 4; nt++) {
                int bn = wn + nt*8 + lq;
                unsigned b0 = __float_as_uint(Bs[cur][ks*8+lr][bn]);
                unsigned b1 = __float_as_uint(Bs[cur][ks*8+lr+4][bn]);
                #pragma unroll
                for (int mt = 0; mt < 2; mt++)
                    mma_tf32(c[mt][nt], a[mt][0], a[mt][1], a[mt][2], a[mt][3], b0, b1);
            }
        }
        if (s < 15) {
            int nb = cur ^ 1;
            As[nb][r0][c4+0]=f2tf32f(av0.x); As[nb][r0][c4+1]=f2tf32f(av0.y);
            As[nb][r0][c4+2]=f2tf32f(av0.z); As[nb][r0][c4+3]=f2tf32f(av0.w);
            As[nb][r0+64][c4+0]=f2tf32f(av1.x); As[nb][r0+64][c4+1]=f2tf32f(av1.y);
            As[nb][r0+64][c4+2]=f2tf32f(av1.z); As[nb][r0+64][c4+3]=f2tf32f(av1.w);
            Bs[nb][br][bc4+0]=f2tf32f(bv.x); Bs[nb][br][bc4+1]=f2tf32f(bv.y);
            Bs[nb][br][bc4+2]=f2tf32f(bv.z); Bs[nb][br][bc4+3]=f2tf32f(bv.w);
        }
        __syncthreads();
    }
    #pragma unroll
    for (int mt = 0; mt < 2; mt++) {
        #pragma unroll
        for (int nt = 0; nt < 4; nt++) {
            int r = row0 + wm + mt*16 + lq;
            int cc = colbase + wn + nt*8 + lr*2;
            float b0v = bias[cc], b1v = bias[cc+1];
            float v00 = c[mt][nt][0] + b0v, v01 = c[mt][nt][1] + b1v;
            float v10 = c[mt][nt][2] + b0v, v11 = c[mt][nt][3] + b1v;
            if (act == 1) { v00 = tanhf(v00); v01 = tanhf(v01); v10 = tanhf(v10); v11 = tanhf(v11); }
            else if (act == 2) { v00 = fmaxf(v00,0.f); v01 = fmaxf(v01,0.f); v10 = fmaxf(v10,0.f); v11 = fmaxf(v11,0.f); }
            *(float2*)&outp[r * Nseg + cc] = make_float2(v00, v01);
            *(float2*)&outp[(r+8) * Nseg + cc] = make_float2(v10, v11);
        }
    }
}

// ================= Kernel 2: phase features (tf32 mma) + gates =================
__global__ __launch_bounds__(256) void k2_mma(
    const float* __restrict__ Wk2, const float* __restrict__ bk2,
    const float* __restrict__ Wq2, const float* __restrict__ bq2,
    const float* __restrict__ Wg2, const float* __restrict__ bg2)
{
    __shared__ float Ak[2][128][17];
    __shared__ float Aq[2][128][17];
    __shared__ float Bs[2][16][68];
    int tid = threadIdx.x;
    int w = tid >> 5, lane = tid & 31;
    int row0 = blockIdx.x * 128;
    int wm = (w & 3) * 32;
    bool isq = (w >= 4);
    int lq = lane >> 2, lr = lane & 3;
    int r0 = tid >> 2, c4 = (tid & 3) * 4;
    int br = tid >> 4, bc4 = (tid & 15) * 4;
    float c[2][4][4] = {};
    float4 ak0, ak1, aq0, aq1, bv;

    ak0 = *(const float4*)&g_hk[(row0 + r0) * 256 + c4];
    ak1 = *(const float4*)&g_hk[(row0 + r0 + 64) * 256 + c4];
    aq0 = *(const float4*)&g_hq[(row0 + r0) * 256 + c4];
    aq1 = *(const float4*)&g_hq[(row0 + r0 + 64) * 256 + c4];
    bv  = (bc4 < 32) ? *(const float4*)&Wk2[br * 32 + bc4]
                     : *(const float4*)&Wq2[br * 32 + bc4 - 32];
    {
        Ak[0][r0][c4+0]=f2tf32f(ak0.x); Ak[0][r0][c4+1]=f2tf32f(ak0.y);
        Ak[0][r0][c4+2]=f2tf32f(ak0.z); Ak[0][r0][c4+3]=f2tf32f(ak0.w);
        Ak[0][r0+64][c4+0]=f2tf32f(ak1.x); Ak[0][r0+64][c4+1]=f2tf32f(ak1.y);
        Ak[0][r0+64][c4+2]=f2tf32f(ak1.z); Ak[0][r0+64][c4+3]=f2tf32f(ak1.w);
        Aq[0][r0][c4+0]=f2tf32f(aq0.x); Aq[0][r0][c4+1]=f2tf32f(aq0.y);
        Aq[0][r0][c4+2]=f2tf32f(aq0.z); Aq[0][r0][c4+3]=f2tf32f(aq0.w);
        Aq[0][r0+64][c4+0]=f2tf32f(aq1.x); Aq[0][r0+64][c4+1]=f2tf32f(aq1.y);
        Aq[0][r0+64][c4+2]=f2tf32f(aq1.z); Aq[0][r0+64][c4+3]=f2tf32f(aq1.w);
        Bs[0][br][bc4+0]=f2tf32f(bv.x); Bs[0][br][bc4+1]=f2tf32f(bv.y);
        Bs[0][br][bc4+2]=f2tf32f(bv.z); Bs[0][br][bc4+3]=f2tf32f(bv.w);
    }
    __syncthreads();

    for (int s = 0; s < 16; s++) {
        int cur = s & 1;
        if (s < 15) {
            int kn = (s + 1) * 16;
            ak0 = *(const float4*)&g_hk[(row0 + r0) * 256 + kn + c4];
            ak1 = *(const float4*)&g_hk[(row0 + r0 + 64) * 256 + kn + c4];
            aq0 = *(const float4*)&g_hq[(row0 + r0) * 256 + kn + c4];
            aq1 = *(const float4*)&g_hq[(row0 + r0 + 64) * 256 + kn + c4];
            bv  = (bc4 < 32) ? *(const float4*)&Wk2[(kn + br) * 32 + bc4]
                             : *(const float4*)&Wq2[(kn + br) * 32 + bc4 - 32];
        }
        const float (*A)[17] = isq ? Aq[cur] : Ak[cur];
        #pragma unroll
        for (int ks = 0; ks < 2; ks++) {
            unsigned a[2][4];
            #pragma unroll
            for (int mt = 0; mt < 2; mt++) {
                int rr = wm + mt*16 + lq;
                int cc = ks*8 + lr;
                a[mt][0] = __float_as_uint(A[rr][cc]);
                a[mt][1] = __float_as_uint(A[rr+8][cc]);
                a[mt][2] = __float_as_uint(A[rr][cc+4]);
                a[mt][3] = __float_as_uint(A[rr+8][cc+4]);
            }
            #pragma unroll
            for (int nt = 0; nt < 4; nt++) {
                int bn = (isq ? 32 : 0) + nt*8 + lq;
                unsigned b0 = __float_as_uint(Bs[cur][ks*8+lr][bn]);
                unsigned b1 = __float_as_uint(Bs[cur][ks*8+lr+4][bn]);
                #pragma unroll
                for (int mt = 0; mt < 2; mt++)
                    mma_tf32(c[mt][nt], a[mt][0], a[mt][1], a[mt][2], a[mt][3], b0, b1);
            }
        }
        if (s < 15) {
            int nb = cur ^ 1;
            Ak[nb][r0][c4+0]=f2tf32f(ak0.x); Ak[nb][r0][c4+1]=f2tf32f(ak0.y);
            Ak[nb][r0][c4+2]=f2tf32f(ak0.z); Ak[nb][r0][c4+3]=f2tf32f(ak0.w);
            Ak[nb][r0+64][c4+0]=f2tf32f(ak1.x); Ak[nb][r0+64][c4+1]=f2tf32f(ak1.y);
            Ak[nb][r0+64][c4+2]=f2tf32f(ak1.z); Ak[nb][r0+64][c4+3]=f2tf32f(ak1.w);
            Aq[nb][r0][c4+0]=f2tf32f(aq0.x); Aq[nb][r0][c4+1]=f2tf32f(aq0.y);
            Aq[nb][r0][c4+2]=f2tf32f(aq0.z); Aq[nb][r0][c4+3]=f2tf32f(aq0.w);
            Aq[nb][r0+64][c4+0]=f2tf32f(aq1.x); Aq[nb][r0+64][c4+1]=f2tf32f(aq1.y);
            Aq[nb][r0+64][c4+2]=f2tf32f(aq1.z); Aq[nb][r0+64][c4+3]=f2tf32f(aq1.w);
            Bs[nb][br][bc4+0]=f2tf32f(bv.x); Bs[nb][br][bc4+1]=f2tf32f(bv.y);
            Bs[nb][br][bc4+2]=f2tf32f(bv.z); Bs[nb][br][bc4+3]=f2tf32f(bv.w);
        }
        __syncthreads();
    }

    const float* bvec = isq ? bq2 : bk2;
    float* fdst = isq ? g_qf : g_kf;
    #pragma unroll
    for (int mt = 0; mt < 2; mt++) {
        #pragma unroll
        for (int nt = 0; nt < 4; nt++) {
            int r = row0 + wm + mt*16 + lq;
            int cn = nt*8 + lr*2;
            float b0v = bvec[cn], b1v = bvec[cn+1];
            float ph;
            float sp, cp;
            ph = tanhf(c[mt][nt][0] + b0v) * PI_F; __sincosf(ph, &sp, &cp);
            fdst[r*64 + cn] = cp; fdst[r*64 + 32 + cn] = sp;
            ph = tanhf(c[mt][nt][1] + b1v) * PI_F; __sincosf(ph, &sp, &cp);
            fdst[r*64 + cn+1] = cp; fdst[r*64 + 32 + cn+1] = sp;
            ph = tanhf(c[mt][nt][2] + b0v) * PI_F; __sincosf(ph, &sp, &cp);
            fdst[(r+8)*64 + cn] = cp; fdst[(r+8)*64 + 32 + cn] = sp;
            ph = tanhf(c[mt][nt][3] + b1v) * PI_F; __sincosf(ph, &sp, &cp);
            fdst[(r+8)*64 + cn+1] = cp; fdst[(r+8)*64 + 32 + cn+1] = sp;
        }
    }
    // gates: each warp handles 16 rows
    for (int rr = 0; rr < 16; rr++) {
        int r = row0 + w*16 + rr;
        float p0 = 0.f, p1 = 0.f;
        #pragma unroll
        for (int i = lane; i < 64; i += 32) {
            float gv = g_g1[r*64 + i];
            p0 += gv * Wg2[i*2 + 0];
            p1 += gv * Wg2[i*2 + 1];
        }
        #pragma unroll
        for (int off = 16; off; off >>= 1) {
            p0 += __shfl_xor_sync(~0u, p0, off);
            p1 += __shfl_xor_sync(~0u, p1, off);
        }
        if (lane == 0) {
            float l0 = p0 + bg2[0], l1 = p1 + bg2[1];
            float m = fmaxf(l0, l1);
            float e0 = __expf(l0 - m), e1 = __expf(l1 - m);
            float inv = 1.f / (e0 + e1);
            g_gates[r*2 + 0] = e0 * inv;
            g_gates[r*2 + 1] = e1 * inv;
        }
    }
}

// ================= Kernel 3a: content chunk states via tf32 mma =================
// S[f, d] = sum_{l<128} kf[row0+l, f] * vc[row0+l, d]; grid (32 bc, 2 d-half)
__global__ __launch_bounds__(256) void k3a_mma()
{
    __shared__ float As[2][64][17];    // A[f][l] (transposed kf)
    __shared__ float Bs[2][16][132];   // B[l][d]
    int bc = blockIdx.x;
    int b = bc >> 4, c = bc & 15;
    int d0 = blockIdx.y * 128;
    int row0 = b * LL + c * CC;
    int tid = threadIdx.x;
    int w = tid >> 5, lane = tid & 31;
    int wm = (w & 1) * 32, wn = (w >> 1) * 32;
    int lq = lane >> 2, lr = lane & 3;
    // A staging: f4 = (tid&15)*4, l = tid>>4  (coalesced reads of kf rows)
    int af4 = (tid & 15) * 4, al = tid >> 4;
    // B staging: rB = tid>>5 (and +8), cB = (tid&31)*4
    int rB = tid >> 5, cB = (tid & 31) * 4;
    float acc[2][4][4] = {};
    float4 av, bv0, bv1;

    av  = *(const float4*)&g_kf[(row0 + al) * 64 + af4];
    bv0 = *(const float4*)&g_vc[(row0 + rB) * 256 + d0 + cB];
    bv1 = *(const float4*)&g_vc[(row0 + rB + 8) * 256 + d0 + cB];
    As[0][af4+0][al]=f2tf32f(av.x); As[0][af4+1][al]=f2tf32f(av.y);
    As[0][af4+2][al]=f2tf32f(av.z); As[0][af4+3][al]=f2tf32f(av.w);
    Bs[0][rB][cB+0]=f2tf32f(bv0.x); Bs[0][rB][cB+1]=f2tf32f(bv0.y);
    Bs[0][rB][cB+2]=f2tf32f(bv0.z); Bs[0][rB][cB+3]=f2tf32f(bv0.w);
    Bs[0][rB+8][cB+0]=f2tf32f(bv1.x); Bs[0][rB+8][cB+1]=f2tf32f(bv1.y);
    Bs[0][rB+8][cB+2]=f2tf32f(bv1.z); Bs[0][rB+8][cB+3]=f2tf32f(bv1.w);
    __syncthreads();

    for (int s = 0; s < 8; s++) {
        int cur = s & 1;
        if (s < 7) {
            int kn = (s + 1) * 16;
            av  = *(const float4*)&g_kf[(row0 + kn + al) * 64 + af4];
            bv0 = *(const float4*)&g_vc[(row0 + kn + rB) * 256 + d0 + cB];
            bv1 = *(const float4*)&g_vc[(row0 + kn + rB + 8) * 256 + d0 + cB];
        }
        #pragma unroll
        for (int ks = 0; ks < 2; ks++) {
            unsigned a[2][4];
            #pragma unroll
            for (int mt = 0; mt < 2; mt++) {
                int rr = wm + mt*16 + lq;
                int cc = ks*8 + lr;
                a[mt][0] = __float_as_uint(As[cur][rr][cc]);
                a[mt][1] = __float_as_uint(As[cur][rr+8][cc]);
                a[mt][2] = __float_as_uint(As[cur][rr][cc+4]);
                a[mt][3] = __float_as_uint(As[cur][rr+8][cc+4]);
            }
            #pragma unroll
            for (int nt = 0; nt < 4; nt++) {
                int bn = wn + nt*8 + lq;
                unsigned b0 = __float_as_uint(Bs[cur][ks*8+lr][bn]);
                unsigned b1 = __float_as_uint(Bs[cur][ks*8+lr+4][bn]);
                #pragma unroll
                for (int mt = 0; mt < 2; mt++)
                    mma_tf32(acc[mt][nt], a[mt][0], a[mt][1], a[mt][2], a[mt][3], b0, b1);
            }
        }
        if (s < 7) {
            int nb = cur ^ 1;
            As[nb][af4+0][al]=f2tf32f(av.x); As[nb][af4+1][al]=f2tf32f(av.y);
            As[nb][af4+2][al]=f2tf32f(av.z); As[nb][af4+3][al]=f2tf32f(av.w);
            Bs[nb][rB][cB+0]=f2tf32f(bv0.x); Bs[nb][rB][cB+1]=f2tf32f(bv0.y);
            Bs[nb][rB][cB+2]=f2tf32f(bv0.z); Bs[nb][rB][cB+3]=f2tf32f(bv0.w);
            Bs[nb][rB+8][cB+0]=f2tf32f(bv1.x); Bs[nb][rB+8][cB+1]=f2tf32f(bv1.y);
            Bs[nb][rB+8][cB+2]=f2tf32f(bv1.z); Bs[nb][rB+8][cB+3]=f2tf32f(bv1.w);
        }
        __syncthreads();
    }
    int base = bc * 64 * 256;
    #pragma unroll
    for (int mt = 0; mt < 2; mt++) {
        #pragma unroll
        for (int nt = 0; nt < 4; nt++) {
            int f = wm + mt*16 + lq;
            int dd = d0 + wn + nt*8 + lr*2;
            *(float2*)&g_S[base + f * 256 + dd] = make_float2(acc[mt][nt][0], acc[mt][nt][1]);
            *(float2*)&g_S[base + (f+8) * 256 + dd] = make_float2(acc[mt][nt][2], acc[mt][nt][3]);
        }
    }
}

// ================= Kernel 3b: pos partial sums + 8-row snapshots =================
__global__ __launch_bounds__(256) void k3b_pos(const float* __restrict__ base_phases)
{
    int blk = blockIdx.x;            // b*64 + s
    int b = blk >> 6, s = blk & 63;
    int row0 = b * LL + s * 32;
    int l0 = s * 32;
    int d = threadIdx.x;
    float par = 0.f, pai = 0.f;
    #pragma unroll
    for (int g = 0; g < 4; g++) {
        float vp8[8], ph8[8];
        #pragma unroll
        for (int j = 0; j < 8; j++) {
            vp8[j] = g_vp[(row0 + g*8 + j) * 256 + d];
            ph8[j] = base_phases[(l0 + g*8 + j) * 256 + d];
        }
        #pragma unroll
        for (int j = 0; j < 8; j++) {
            float sp, cp; __sincosf(ph8[j], &sp, &cp);
            par += vp8[j] * cp; pai += vp8[j] * sp;
        }
        int snapbase = (blk * 4 + g) * 512;
        g_psnap[snapbase + d] = par;
        g_psnap[snapbase + 256 + d] = pai;
    }
}

// ================= Kernel 4: exclusive prefixes (front-batched loads) =================
__global__ __launch_bounds__(256) void k4_prefix()
{
    int tid = threadIdx.x;
    if (blockIdx.x < 128) {
        int idx = blockIdx.x * 256 + tid;       // (b, f*256+d) -> 32768 chains
        int b = idx >> 14, rd = idx & 16383;
        float v[16];
        #pragma unroll
        for (int c = 0; c < 16; c++)
            v[c] = g_S[(b * 16 + c) * 16384 + rd];
        float run = 0.f;
        #pragma unroll
        for (int c = 0; c < 16; c++) {
            g_P[(b * 16 + c) * 16384 + rd] = run;
            run += v[c];
        }
    } else {
        int e = (blockIdx.x - 128) * 256 + tid;
        if (e < 1024) {
            int b = e >> 9, rd = e & 511;
            float v[64];
            #pragma unroll
            for (int s = 0; s < 64; s++)
                v[s] = g_psnap[((b * 64 + s) * 4 + 3) * 512 + rd];  // 32-row sums
            float run = 0.f;
            #pragma unroll
            for (int s = 0; s < 64; s++) {
                g_pprefix[(b * 64 + s) * 512 + rd] = run;
                run += v[s];
            }
        }
    }
}

// ================= Kernel 5: intra-chunk masked scores (tf32 mma) =================
__global__ __launch_bounds__(256) void k5_mma()
{
    __shared__ float As[2][128][20];
    __shared__ float Bs[2][16][132];
    int bc = blockIdx.x; int b = bc >> 4, c = bc & 15;
    int row0 = b * LL + c * CC;
    int tid = threadIdx.x;
    int w = tid >> 5, lane = tid & 31;
    int wm = (w & 3) * 32;
    int wn = (w >> 2) * 64;
    int lq = lane >> 2, lr = lane & 3;
    int r0 = tid >> 2, c4 = (tid & 3) * 4;
    float acc[2][8][4] = {};
    float4 a0v, a1v, u0, u1;

    a0v = *(const float4*)&g_qf[(row0 + r0) * 64 + c4];
    a1v = *(const float4*)&g_qf[(row0 + r0 + 64) * 64 + c4];
    u0  = *(const float4*)&g_kf[(row0 + r0) * 64 + c4];
    u1  = *(const float4*)&g_kf[(row0 + r0 + 64) * 64 + c4];
    {
        As[0][r0][c4+0]=f2tf32f(a0v.x); As[0][r0][c4+1]=f2tf32f(a0v.y);
        As[0][r0][c4+2]=f2tf32f(a0v.z); As[0][r0][c4+3]=f2tf32f(a0v.w);
        As[0][r0+64][c4+0]=f2tf32f(a1v.x); As[0][r0+64][c4+1]=f2tf32f(a1v.y);
        As[0][r0+64][c4+2]=f2tf32f(a1v.z); As[0][r0+64][c4+3]=f2tf32f(a1v.w);
        Bs[0][c4+0][r0]=f2tf32f(u0.x); Bs[0][c4+1][r0]=f2tf32f(u0.y);
        Bs[0][c4+2][r0]=f2tf32f(u0.z); Bs[0][c4+3][r0]=f2tf32f(u0.w);
        Bs[0][c4+0][r0+64]=f2tf32f(u1.x); Bs[0][c4+1][r0+64]=f2tf32f(u1.y);
        Bs[0][c4+2][r0+64]=f2tf32f(u1.z); Bs[0][c4+3][r0+64]=f2tf32f(u1.w);
    }
    __syncthreads();

    for (int s = 0; s < 4; s++) {
        int cur = s & 1;
        if (s < 3) {
            int kn = (s + 1) * 16;
            a0v = *(const float4*)&g_qf[(row0 + r0) * 64 + kn + c4];
            a1v = *(const float4*)&g_qf[(row0 + r0 + 64) * 64 + kn + c4];
            u0  = *(const float4*)&g_kf[(row0 + r0) * 64 + kn + c4];
            u1  = *(const float4*)&g_kf[(row0 + r0 + 64) * 64 + kn + c4];
        }
        #pragma unroll
        for (int ks = 0; ks < 2; ks++) {
            unsigned a[2][4];
            #pragma unroll
            for (int mt = 0; mt < 2; mt++) {
                int rr = wm + mt*16 + lq;
                int cc = ks*8 + lr;
                a[mt][0] = __float_as_uint(As[cur][rr][cc]);
                a[mt][1] = __float_as_uint(As[cur][rr+8][cc]);
                a[mt][2] = __float_as_uint(As[cur][rr][cc+4]);
                a[mt][3] = __float_as_uint(As[cur][rr+8][cc+4]);
            }
            #pragma unroll
            for (int nt = 0; nt < 8; nt++) {
                int bn = wn + nt*8 + lq;
                unsigned b0 = __float_as_uint(Bs[cur][ks*8+lr][bn]);
                unsigned b1 = __float_as_uint(Bs[cur][ks*8+lr+4][bn]);
                #pragma unroll
                for (int mt = 0; mt < 2; mt++)
                    mma_tf32(acc[mt][nt], a[mt][0], a[mt][1], a[mt][2], a[mt][3], b0, b1);
            }
        }
        if (s < 3) {
            int nb = cur ^ 1;
            As[nb][r0][c4+0]=f2tf32f(a0v.x); As[nb][r0][c4+1]=f2tf32f(a0v.y);
            As[nb][r0][c4+2]=f2tf32f(a0v.z); As[nb][r0][c4+3]=f2tf32f(a0v.w);
            As[nb][r0+64][c4+0]=f2tf32f(a1v.x); As[nb][r0+64][c4+1]=f2tf32f(a1v.y);
            As[nb][r0+64][c4+2]=f2tf32f(a1v.z); As[nb][r0+64][c4+3]=f2tf32f(a1v.w);
            Bs[nb][c4+0][r0]=f2tf32f(u0.x); Bs[nb][c4+1][r0]=f2tf32f(u0.y);
            Bs[nb][c4+2][r0]=f2tf32f(u0.z); Bs[nb][c4+3][r0]=f2tf32f(u0.w);
            Bs[nb][c4+0][r0+64]=f2tf32f(u1.x); Bs[nb][c4+1][r0+64]=f2tf32f(u1.y);
            Bs[nb][c4+2][r0+64]=f2tf32f(u1.z); Bs[nb][c4+3][r0+64]=f2tf32f(u1.w);
        }
        __syncthreads();
    }
    int sb = bc * CC * CC;
    #pragma unroll
    for (int mt = 0; mt < 2; mt++) {
        #pragma unroll
        for (int nt = 0; nt < 8; nt++) {
            int la = wm + mt*16 + lq;
            int lb = la + 8;
            int j0 = wn + nt*8 + lr*2;
            int j1 = j0 + 1;
            *(float2*)&g_scores[sb + la*128 + j0] =
                make_float2(j0 <= la ? acc[mt][nt][0] : 0.f, j1 <= la ? acc[mt][nt][1] : 0.f);
            *(float2*)&g_scores[sb + lb*128 + j0] =
                make_float2(j0 <= lb ? acc[mt][nt][2] : 0.f, j1 <= lb ? acc[mt][nt][3] : 0.f);
        }
    }
}

// ================= Kernel 6: content output (tf32 mma): [qf | scores] @ [P ; vc] ======
__global__ __launch_bounds__(256) void k6_mma()
{
    __shared__ float As[2][128][20];
    __shared__ float Bs[2][16][68];
    int bc = blockIdx.x; int b = bc >> 4, c = bc & 15;
    int d0 = blockIdx.y * 64;
    int row0 = b * LL + c * CC;
    int tid = threadIdx.x;
    int w = tid >> 5, lane = tid & 31;
    int wm = (w & 3) * 32;
    int wn = (w >> 2) * 32;
    int lq = lane >> 2, lr = lane & 3;
    int r0 = tid >> 2, c4 = (tid & 3) * 4;
    int br = tid >> 4, bc4 = (tid & 15) * 4;
    int Pbase = bc * 64 * 256;
    int sbase = bc * CC * CC;
    float acc[2][4][4] = {};
    float4 a0v, a1v, bv;

    a0v = *(const float4*)&g_qf[(row0 + r0) * 64 + c4];
    a1v = *(const float4*)&g_qf[(row0 + r0 + 64) * 64 + c4];
    bv  = *(const float4*)&g_P[Pbase + br * 256 + d0 + bc4];
    {
        As[0][r0][c4+0]=f2tf32f(a0v.x); As[0][r0][c4+1]=f2tf32f(a0v.y);
        As[0][r0][c4+2]=f2tf32f(a0v.z); As[0][r0][c4+3]=f2tf32f(a0v.w);
        As[0][r0+64][c4+0]=f2tf32f(a1v.x); As[0][r0+64][c4+1]=f2tf32f(a1v.y);
        As[0][r0+64][c4+2]=f2tf32f(a1v.z); As[0][r0+64][c4+3]=f2tf32f(a1v.w);
        Bs[0][br][bc4+0]=f2tf32f(bv.x); Bs[0][br][bc4+1]=f2tf32f(bv.y);
        Bs[0][br][bc4+2]=f2tf32f(bv.z); Bs[0][br][bc4+3]=f2tf32f(bv.w);
    }
    __syncthreads();

    for (int s = 0; s < 12; s++) {
        int cur = s & 1;
        if (s < 11) {
            int kn = (s + 1) * 16;
            int kga = kn + c4;
            if (kga < 64) {
                a0v = *(const float4*)&g_qf[(row0 + r0) * 64 + kga];
                a1v = *(const float4*)&g_qf[(row0 + r0 + 64) * 64 + kga];
            } else {
                a0v = *(const float4*)&g_scores[sbase + r0 * 128 + kga - 64];
                a1v = *(const float4*)&g_scores[sbase + (r0 + 64) * 128 + kga - 64];
            }
            int kgb = kn + br;
            if (kgb < 64) bv = *(const float4*)&g_P[Pbase + kgb * 256 + d0 + bc4];
            else          bv = *(const float4*)&g_vc[(row0 + kgb - 64) * 256 + d0 + bc4];
        }
        #pragma unroll
        for (int ks = 0; ks < 2; ks++) {
            unsigned a[2][4];
            #pragma unroll
            for (int mt = 0; mt < 2; mt++) {
                int rr = wm + mt*16 + lq;
                int cc = ks*8 + lr;
                a[mt][0] = __float_as_uint(As[cur][rr][cc]);
                a[mt][1] = __float_as_uint(As[cur][rr+8][cc]);
                a[mt][2] = __float_as_uint(As[cur][rr][cc+4]);
                a[mt][3] = __float_as_uint(As[cur][rr+8][cc+4]);
            }
            #pragma unroll
            for (int nt = 0; nt < 4; nt++) {
                int bn = wn + nt*8 + lq;
                unsigned b0 = __float_as_uint(Bs[cur][ks*8+lr][bn]);
                unsigned b1 = __float_as_uint(Bs[cur][ks*8+lr+4][bn]);
                #pragma unroll
                for (int mt = 0; mt < 2; mt++)
                    mma_tf32(acc[mt][nt], a[mt][0], a[mt][1], a[mt][2], a[mt][3], b0, b1);
            }
        }
        if (s < 11) {
            int nb = cur ^ 1;
            As[nb][r0][c4+0]=f2tf32f(a0v.x); As[nb][r0][c4+1]=f2tf32f(a0v.y);
            As[nb][r0][c4+2]=f2tf32f(a0v.z); As[nb][r0][c4+3]=f2tf32f(a0v.w);
            As[nb][r0+64][c4+0]=f2tf32f(a1v.x); As[nb][r0+64][c4+1]=f2tf32f(a1v.y);
            As[nb][r0+64][c4+2]=f2tf32f(a1v.z); As[nb][r0+64][c4+3]=f2tf32f(a1v.w);
            Bs[nb][br][bc4+0]=f2tf32f(bv.x); Bs[nb][br][bc4+1]=f2tf32f(bv.y);
            Bs[nb][br][bc4+2]=f2tf32f(bv.z); Bs[nb][br][bc4+3]=f2tf32f(bv.w);
        }
        __syncthreads();
    }
    #pragma unroll
    for (int mt = 0; mt < 2; mt++) {
        #pragma unroll
        for (int nt = 0; nt < 4; nt++) {
            int la = wm + mt*16 + lq;
            int lb = la + 8;
            int cc = d0 + wn + nt*8 + lr*2;
            float sa = rsqrtf((float)((c*CC + la + 1) * KK));
            float sb2 = rsqrtf((float)((c*CC + lb + 1) * KK));
            *(float2*)&g_cont[(row0 + la) * 256 + cc] =
                make_float2(acc[mt][nt][0] * sa, acc[mt][nt][1] * sa);
            *(float2*)&g_cont[(row0 + lb) * 256 + cc] =
                make_float2(acc[mt][nt][2] * sb2, acc[mt][nt][3] * sb2);
        }
    }
}

// ================= Kernel 7: pos scan (8 rows/block) + gate combine + LayerNorm =========
__global__ __launch_bounds__(256) void k7_poscomb(
    const float* __restrict__ base_phases,
    const float* __restrict__ ln_g, const float* __restrict__ ln_b)
{
    __shared__ float comb[8][257];
    int blk = blockIdx.x;            // b*256 + s*4 + j
    int j = blk & 3;
    int s = (blk >> 2) & 63;
    int b = blk >> 8;
    int row0 = b * LL + s * 32 + j * 8;
    int l0 = s * 32 + j * 8;
    int d = threadIdx.x;
    float ar = g_pprefix[(b * 64 + s) * 512 + d];
    float ai = g_pprefix[(b * 64 + s) * 512 + 256 + d];
    if (j > 0) {
        int snapbase = ((b * 64 + s) * 4 + j - 1) * 512;
        ar += g_psnap[snapbase + d];
        ai += g_psnap[snapbase + 256 + d];
    }
    float vp[8], ph[8], cv[8];
    #pragma unroll
    for (int lt = 0; lt < 8; lt++) {
        vp[lt] = g_vp[(row0 + lt) * 256 + d];
        ph[lt] = base_phases[(l0 + lt) * 256 + d];
        cv[lt] = g_cont[(row0 + lt) * 256 + d];
    }
    #pragma unroll
    for (int lt = 0; lt < 8; lt++) {
        float sp, cp; __sincosf(ph[lt], &sp, &cp);
        ar += vp[lt] * cp; ai += vp[lt] * sp;
        float pret = (ar * cp + ai * sp) * rsqrtf((float)(l0 + lt + 1));
        float g0 = g_gates[(row0 + lt) * 2], g1v = g_gates[(row0 + lt) * 2 + 1];
        comb[lt][d] = g0 * pret + g1v * cv[lt];
    }
    __syncthreads();
    int w = d >> 5, lane = d & 31;
    int r = row0 + w;
    float vals[8]; float s1 = 0.f, s2 = 0.f;
    #pragma unroll
    for (int k = 0; k < 8; k++) {
        float v = comb[w][lane + 32*k];
        vals[k] = v; s1 += v; s2 += v*v;
    }
    #pragma unroll
    for (int off = 16; off; off >>= 1) {
        s1 += __shfl_xor_sync(~0u, s1, off);
        s2 += __shfl_xor_sync(~0u, s2, off);
    }
    float mu = s1 * (1.f/256.f);
    float var = s2 * (1.f/256.f) - mu*mu;
    float rstd = rsqrtf(var + 1e-5f);
    #pragma unroll
    for (int k = 0; k < 8; k++) {
        int dd = lane + 32*k;
        g_norm[r*256 + dd] = (vals[k] - mu) * rstd * ln_g[dd] + ln_b[dd];
    }
}

// ================= Kernel 8: out = x + normed @ Wo + bo (round-3 config) ==============
__global__ __launch_bounds__(256) void k8_mma(
    const float* __restrict__ x, const float* __restrict__ Wo,
    const float* __restrict__ bo, float* __restrict__ out)
{
    __shared__ float As[2][128][20];
    __shared__ float Bs[2][16][68];
    int row0 = blockIdx.x * 128;
    int colbase = blockIdx.y * 64;
    int tid = threadIdx.x;
    int w = tid >> 5, lane = tid & 31;
    int wm = (w & 3) * 32;
    int wn = (w >> 2) * 32;
    int lq = lane >> 2, lr = lane & 3;
    int r0 = tid >> 2, c4 = (tid & 3) * 4;
    int br = tid >> 4, bc4 = (tid & 15) * 4;
    float c[2][4][4] = {};
    float4 av0, av1, bv;

    av0 = *(const float4*)&g_norm[(row0 + r0) * 256 + c4];
    av1 = *(const float4*)&g_norm[(row0 + r0 + 64) * 256 + c4];
    bv  = *(const float4*)&Wo[br * 256 + colbase + bc4];
    As[0][r0][c4+0]=f2tf32f(av0.x); As[0][r0][c4+1]=f2tf32f(av0.y);
    As[0][r0][c4+2]=f2tf32f(av0.z); As[0][r0][c4+3]=f2tf32f(av0.w);
    As[0][r0+64][c4+0]=f2tf32f(av1.x); As[0][r0+64][c4+1]=f2tf32f(av1.y);
    As[0][r0+64][c4+2]=f2tf32f(av1.z); As[0][r0+64][c4+3]=f2tf32f(av1.w);
    Bs[0][br][bc4+0]=f2tf32f(bv.x); Bs[0][br][bc4+1]=f2tf32f(bv.y);
    Bs[0][br][bc4+2]=f2tf32f(bv.z); Bs[0][br][bc4+3]=f2tf32f(bv.w);
    __syncthreads();

    for (int s = 0; s < 16; s++) {
        int cur = s & 1;
        if (s < 15) {
            int kn = (s + 1) * 16;
            av0 = *(const float4*)&g_norm[(row0 + r0) * 256 + kn + c4];
            av1 = *(const float4*)&g_norm[(row0 + r0 + 64) * 256 + kn + c4];
            bv  = *(const float4*)&Wo[(kn + br) * 256 + colbase + bc4];
        }
        #pragma unroll
        for (int ks = 0; ks < 2; ks++) {
            unsigned a[2][4];
            #pragma unroll
            for (int mt = 0; mt < 2; mt++) {
                int rr = wm + mt*16 + lq;
                int cc = ks*8 + lr;
                a[mt][0] = __float_as_uint(As[cur][rr][cc]);
                a[mt][1] = __float_as_uint(As[cur][rr+8][cc]);
                a[mt][2] = __float_as_uint(As[cur][rr][cc+4]);
                a[mt][3] = __float_as_uint(As[cur][rr+8][cc+4]);
            }
            #pragma unroll
            for (int nt = 0; nt < 4; nt++) {
                int bn = wn + nt*8 + lq;
                unsigned b0 = __float_as_uint(Bs[cur][ks*8+lr][bn]);
                unsigned b1 = __float_as_uint(Bs[cur][ks*8+lr+4][bn]);
                #pragma unroll
                for (int mt = 0; mt < 2; mt++)
                    mma_tf32(c[mt][nt], a[mt][0], a[mt][1], a[mt][2], a[mt][3], b0, b1);
            }
        }
        if (s < 15) {
            int nb = cur ^ 1;
            As[nb][r0][c4+0]=f2tf32f(av0.x); As[nb][r0][c4+1]=f2tf32f(av0.y);
            As[nb][r0][c4+2]=f2tf32f(av0.z); As[nb][r0][c4+3]=f2tf32f(av0.w);
            As[nb][r0+64][c4+0]=f2tf32f(av1.x); As[nb][r0+64][c4+1]=f2tf32f(av1.y);
            As[nb][r0+64][c4+2]=f2tf32f(av1.z); As[nb][r0+64][c4+3]=f2tf32f(av1.w);
            Bs[nb][br][bc4+0]=f2tf32f(bv.x); Bs[nb][br][bc4+1]=f2tf32f(bv.y);
            Bs[nb][br][bc4+2]=f2tf32f(bv.z); Bs[nb][br][bc4+3]=f2tf32f(bv.w);
        }
        __syncthreads();
    }
    #pragma unroll
    for (int mt = 0; mt < 2; mt++) {
        #pragma unroll
        for (int nt = 0; nt < 4; nt++) {
            int r = row0 + wm + mt*16 + lq;
            int cc = colbase + wn + nt*8 + lr*2;
            float b0v = bo[cc], b1v = bo[cc+1];
            float2 x0 = *(const float2*)&x[r * 256 + cc];
            float2 x1 = *(const float2*)&x[(r+8) * 256 + cc];
            *(float2*)&out[r * 256 + cc] =
                make_float2(c[mt][nt][0] + b0v + x0.x, c[mt][nt][1] + b1v + x0.y);
            *(float2*)&out[(r+8) * 256 + cc] =
                make_float2(c[mt][nt][2] + b0v + x1.x, c[mt][nt][3] + b1v + x1.y);
        }
    }
}

// ================= launcher =================
extern "C" void kernel_launch(void* const* d_in, const int* in_sizes, int n_in,
                              void* d_out, int out_size)
{
    const float* x   = (const float*)d_in[0];
    const float* bp  = (const float*)d_in[1];
    const float* Wk1 = (const float*)d_in[2];
    const float* bk1 = (const float*)d_in[3];
    const float* Wk2 = (const float*)d_in[4];
    const float* bk2 = (const float*)d_in[5];
    const float* Wq1 = (const float*)d_in[6];
    const float* bq1 = (const float*)d_in[7];
    const float* Wq2 = (const float*)d_in[8];
    const float* bq2 = (const float*)d_in[9];
    const float* Wvc = (const float*)d_in[10];
    const float* bvc = (const float*)d_in[11];
    const float* Wvp = (const float*)d_in[12];
    const float* bvp = (const float*)d_in[13];
    const float* Wg1 = (const float*)d_in[14];
    const float* bg1 = (const float*)d_in[15];
    const float* Wg2 = (const float*)d_in[16];
    const float* bg2 = (const float*)d_in[17];
    const float* lng = (const float*)d_in[18];
    const float* lnb = (const float*)d_in[19];
    const float* Wo  = (const float*)d_in[20];
    const float* bo  = (const float*)d_in[21];
    float* out = (float*)d_out;

    k1_mma<<<dim3(32, 17), 256>>>(x, Wk1, bk1, Wq1, bq1, Wvc, bvc, Wvp, bvp, Wg1, bg1);
    k2_mma<<<32, 256>>>(Wk2, bk2, Wq2, bq2, Wg2, bg2);
    k3a_mma<<<dim3(32, 2), 256>>>();
    k3b_pos<<<128, 256>>>(bp);
    k4_prefix<<<132, 256>>>();
    k5_mma<<<32, 256>>>();
    k6_mma<<<dim3(32, 4), 256>>>();
    k7_poscomb<<<512, 256>>>(bp, lng, lnb);
    k8_mma<<<dim3(32, 4), 256>>>(x, Wo, bo, out);
}

// round 8
// speedup vs baseline: 1.1151x; 1.0388x over previous
#include <cuda_runtime.h>
#include <cuda_bf16.h>
#include <math.h>

// Problem constants
#define Bb 2
#define LL 2048
#define DD 256
#define KK 32
#define FF 64          // 2*K feature dim
#define MM (Bb*LL)     // 4096 rows
#define CC 128         // chunk size
#define NC (LL/CC)     // 16 chunks per batch
#define PI_F 3.14159265358979323846f

// ---------------- scratch (device globals; no allocation allowed) ----------------
__device__ float g_hk[MM*DD];
__device__ float g_hq[MM*DD];
__device__ float g_vc[MM*DD];
__device__ float g_vp[MM*DD];
__device__ float g_g1[MM*64];
__device__ float g_kf[MM*FF];
__device__ float g_qf[MM*FF];
__device__ float g_gates[MM*2];
__device__ float g_S[Bb*NC*FF*DD];         // per-chunk content state sums (mma)
__device__ float g_P[Bb*NC*FF*DD];         // chunk-level exclusive prefix of states
__device__ float g_psnap[Bb*64*4*2*DD];    // pos accum snapshots every 8 rows (inclusive)
__device__ float g_pprefix[Bb*64*2*DD];    // exclusive prefix at 32-row granularity
__device__ float g_scores[Bb*NC*CC*CC];    // intra-chunk masked scores
__device__ float g_cont[MM*DD];
__device__ float g_norm[MM*DD];

// mma consumes raw f32 bit patterns as tf32 (HW truncates mantissa; no cvt needed)
__device__ __forceinline__ void mma_tf32(float c[4],
    unsigned a0, unsigned a1, unsigned a2, unsigned a3,
    unsigned b0, unsigned b1)
{
    asm volatile(
        "mma.sync.aligned.m16n8k8.row.col.f32.tf32.tf32.f32 "
        "{%0,%1,%2,%3}, {%4,%5,%6,%7}, {%8,%9}, {%0,%1,%2,%3};"
        : "+f"(c[0]), "+f"(c[1]), "+f"(c[2]), "+f"(c[3])
        : "r"(a0), "r"(a1), "r"(a2), "r"(a3), "r"(b0), "r"(b1));
}

// ================= Kernel 1: fused first-layer GEMMs =================
// grid (32, 17): ct<16 -> [hk|hq|vc|vp] x 4 col-quarters; ct==16 -> g1
__global__ __launch_bounds__(256) void k1_mma(
    const float* __restrict__ x,
    const float* __restrict__ Wk1, const float* __restrict__ bk1,
    const float* __restrict__ Wq1, const float* __restrict__ bq1,
    const float* __restrict__ Wvc, const float* __restrict__ bvc,
    const float* __restrict__ Wvp, const float* __restrict__ bvp,
    const float* __restrict__ Wg1, const float* __restrict__ bg1)
{
    __shared__ float As[2][128][20];
    __shared__ float Bs[2][16][68];
    int ct = blockIdx.y;
    const float* W; const float* bias; float* outp; int Nseg; int act; int colbase;
    if (ct < 16) {
        int seg = ct >> 2;
        colbase = (ct & 3) * 64;
        Nseg = 256;
        if (seg == 0)      { W = Wk1; bias = bk1; outp = g_hk; act = 1; }
        else if (seg == 1) { W = Wq1; bias = bq1; outp = g_hq; act = 1; }
        else if (seg == 2) { W = Wvc; bias = bvc; outp = g_vc; act = 0; }
        else               { W = Wvp; bias = bvp; outp = g_vp; act = 0; }
    } else {
        W = Wg1; bias = bg1; outp = g_g1; Nseg = 64; act = 2; colbase = 0;
    }
    int row0 = blockIdx.x * 128;
    int tid = threadIdx.x;
    int w = tid >> 5, lane = tid & 31;
    int wm = (w & 3) * 32;
    int wn = (w >> 2) * 32;
    int lq = lane >> 2, lr = lane & 3;
    int r0 = tid >> 2, c4 = (tid & 3) * 4;
    int br = tid >> 4, bc4 = (tid & 15) * 4;
    float c[2][4][4] = {};
    float4 av0, av1, bv;

    av0 = *(const float4*)&x[(row0 + r0) * 256 + c4];
    av1 = *(const float4*)&x[(row0 + r0 + 64) * 256 + c4];
    bv  = *(const float4*)&W[br * Nseg + colbase + bc4];
    *(float4*)&As[0][r0][c4] = av0;
    *(float4*)&As[0][r0+64][c4] = av1;
    *(float4*)&Bs[0][br][bc4] = bv;
    __syncthreads();

    for (int s = 0; s < 16; s++) {
        int cur = s & 1;
        if (s < 15) {
            int kn = (s + 1) * 16;
            av0 = *(const float4*)&x[(row0 + r0) * 256 + kn + c4];
            av1 = *(const float4*)&x[(row0 + r0 + 64) * 256 + kn + c4];
            bv  = *(const float4*)&W[(kn + br) * Nseg + colbase + bc4];
        }
        #pragma unroll
        for (int ks = 0; ks < 2; ks++) {
            unsigned a[2][4];
            #pragma unroll
            for (int mt = 0; mt < 2; mt++) {
                int rr = wm + mt*16 + lq;
                int cc = ks*8 + lr;
                a[mt][0] = __float_as_uint(As[cur][rr][cc]);
                a[mt][1] = __float_as_uint(As[cur][rr+8][cc]);
                a[mt][2] = __float_as_uint(As[cur][rr][cc+4]);
                a[mt][3] = __float_as_uint(As[cur][rr+8][cc+4]);
            }
            #pragma unroll
            for (int nt = 0; nt < 4; nt++) {
                int bn = wn + nt*8 + lq;
                unsigned b0 = __float_as_uint(Bs[cur][ks*8+lr][bn]);
                unsigned b1 = __float_as_uint(Bs[cur][ks*8+lr+4][bn]);
                #pragma unroll
                for (int mt = 0; mt < 2; mt++)
                    mma_tf32(c[mt][nt], a[mt][0], a[mt][1], a[mt][2], a[mt][3], b0, b1);
            }
        }
        if (s < 15) {
            int nb = cur ^ 1;
            *(float4*)&As[nb][r0][c4] = av0;
            *(float4*)&As[nb][r0+64][c4] = av1;
            *(float4*)&Bs[nb][br][bc4] = bv;
        }
        __syncthreads();
    }
    #pragma unroll
    for (int mt = 0; mt < 2; mt++) {
        #pragma unroll
        for (int nt = 0; nt < 4; nt++) {
            int r = row0 + wm + mt*16 + lq;
            int cc = colbase + wn + nt*8 + lr*2;
            float b0v = bias[cc], b1v = bias[cc+1];
            float v00 = c[mt][nt][0] + b0v, v01 = c[mt][nt][1] + b1v;
            float v10 = c[mt][nt][2] + b0v, v11 = c[mt][nt][3] + b1v;
            if (act == 1) { v00 = tanhf(v00); v01 = tanhf(v01); v10 = tanhf(v10); v11 = tanhf(v11); }
            else if (act == 2) { v00 = fmaxf(v00,0.f); v01 = fmaxf(v01,0.f); v10 = fmaxf(v10,0.f); v11 = fmaxf(v11,0.f); }
            *(float2*)&outp[r * Nseg + cc] = make_float2(v00, v01);
            *(float2*)&outp[(r+8) * Nseg + cc] = make_float2(v10, v11);
        }
    }
}

// ================= Kernel 2: phase features (tf32 mma) + gates =================
// A arrays use stride 18 (8B-aligned rows, float2 stores) to fit 48KB smem.
__global__ __launch_bounds__(256) void k2_mma(
    const float* __restrict__ Wk2, const float* __restrict__ bk2,
    const float* __restrict__ Wq2, const float* __restrict__ bq2,
    const float* __restrict__ Wg2, const float* __restrict__ bg2)
{
    __shared__ float Ak[2][128][18];
    __shared__ float Aq[2][128][18];
    __shared__ float Bs[2][16][68];
    int tid = threadIdx.x;
    int w = tid >> 5, lane = tid & 31;
    int row0 = blockIdx.x * 128;
    int wm = (w & 3) * 32;
    bool isq = (w >= 4);
    int lq = lane >> 2, lr = lane & 3;
    int r0 = tid >> 2, c4 = (tid & 3) * 4;
    int br = tid >> 4, bc4 = (tid & 15) * 4;
    float c[2][4][4] = {};
    float4 ak0, ak1, aq0, aq1, bv;

    ak0 = *(const float4*)&g_hk[(row0 + r0) * 256 + c4];
    ak1 = *(const float4*)&g_hk[(row0 + r0 + 64) * 256 + c4];
    aq0 = *(const float4*)&g_hq[(row0 + r0) * 256 + c4];
    aq1 = *(const float4*)&g_hq[(row0 + r0 + 64) * 256 + c4];
    bv  = (bc4 < 32) ? *(const float4*)&Wk2[br * 32 + bc4]
                     : *(const float4*)&Wq2[br * 32 + bc4 - 32];
    *(float2*)&Ak[0][r0][c4]      = make_float2(ak0.x, ak0.y);
    *(float2*)&Ak[0][r0][c4+2]    = make_float2(ak0.z, ak0.w);
    *(float2*)&Ak[0][r0+64][c4]   = make_float2(ak1.x, ak1.y);
    *(float2*)&Ak[0][r0+64][c4+2] = make_float2(ak1.z, ak1.w);
    *(float2*)&Aq[0][r0][c4]      = make_float2(aq0.x, aq0.y);
    *(float2*)&Aq[0][r0][c4+2]    = make_float2(aq0.z, aq0.w);
    *(float2*)&Aq[0][r0+64][c4]   = make_float2(aq1.x, aq1.y);
    *(float2*)&Aq[0][r0+64][c4+2] = make_float2(aq1.z, aq1.w);
    *(float4*)&Bs[0][br][bc4] = bv;
    __syncthreads();

    for (int s = 0; s < 16; s++) {
        int cur = s & 1;
        if (s < 15) {
            int kn = (s + 1) * 16;
            ak0 = *(const float4*)&g_hk[(row0 + r0) * 256 + kn + c4];
            ak1 = *(const float4*)&g_hk[(row0 + r0 + 64) * 256 + kn + c4];
            aq0 = *(const float4*)&g_hq[(row0 + r0) * 256 + kn + c4];
            aq1 = *(const float4*)&g_hq[(row0 + r0 + 64) * 256 + kn + c4];
            bv  = (bc4 < 32) ? *(const float4*)&Wk2[(kn + br) * 32 + bc4]
                             : *(const float4*)&Wq2[(kn + br) * 32 + bc4 - 32];
        }
        const float (*A)[18] = isq ? Aq[cur] : Ak[cur];
        #pragma unroll
        for (int ks = 0; ks < 2; ks++) {
            unsigned a[2][4];
            #pragma unroll
            for (int mt = 0; mt < 2; mt++) {
                int rr = wm + mt*16 + lq;
                int cc = ks*8 + lr;
                a[mt][0] = __float_as_uint(A[rr][cc]);
                a[mt][1] = __float_as_uint(A[rr+8][cc]);
                a[mt][2] = __float_as_uint(A[rr][cc+4]);
                a[mt][3] = __float_as_uint(A[rr+8][cc+4]);
            }
            #pragma unroll
            for (int nt = 0; nt < 4; nt++) {
                int bn = (isq ? 32 : 0) + nt*8 + lq;
                unsigned b0 = __float_as_uint(Bs[cur][ks*8+lr][bn]);
                unsigned b1 = __float_as_uint(Bs[cur][ks*8+lr+4][bn]);
                #pragma unroll
                for (int mt = 0; mt < 2; mt++)
                    mma_tf32(c[mt][nt], a[mt][0], a[mt][1], a[mt][2], a[mt][3], b0, b1);
            }
        }
        if (s < 15) {
            int nb = cur ^ 1;
            *(float2*)&Ak[nb][r0][c4]      = make_float2(ak0.x, ak0.y);
            *(float2*)&Ak[nb][r0][c4+2]    = make_float2(ak0.z, ak0.w);
            *(float2*)&Ak[nb][r0+64][c4]   = make_float2(ak1.x, ak1.y);
            *(float2*)&Ak[nb][r0+64][c4+2] = make_float2(ak1.z, ak1.w);
            *(float2*)&Aq[nb][r0][c4]      = make_float2(aq0.x, aq0.y);
            *(float2*)&Aq[nb][r0][c4+2]    = make_float2(aq0.z, aq0.w);
            *(float2*)&Aq[nb][r0+64][c4]   = make_float2(aq1.x, aq1.y);
            *(float2*)&Aq[nb][r0+64][c4+2] = make_float2(aq1.z, aq1.w);
            *(float4*)&Bs[nb][br][bc4] = bv;
        }
        __syncthreads();
    }

    const float* bvec = isq ? bq2 : bk2;
    float* fdst = isq ? g_qf : g_kf;
    #pragma unroll
    for (int mt = 0; mt < 2; mt++) {
        #pragma unroll
        for (int nt = 0; nt < 4; nt++) {
            int r = row0 + wm + mt*16 + lq;
            int cn = nt*8 + lr*2;
            float b0v = bvec[cn], b1v = bvec[cn+1];
            float ph;
            float sp, cp;
            ph = tanhf(c[mt][nt][0] + b0v) * PI_F; __sincosf(ph, &sp, &cp);
            fdst[r*64 + cn] = cp; fdst[r*64 + 32 + cn] = sp;
            ph = tanhf(c[mt][nt][1] + b1v) * PI_F; __sincosf(ph, &sp, &cp);
            fdst[r*64 + cn+1] = cp; fdst[r*64 + 32 + cn+1] = sp;
            ph = tanhf(c[mt][nt][2] + b0v) * PI_F; __sincosf(ph, &sp, &cp);
            fdst[(r+8)*64 + cn] = cp; fdst[(r+8)*64 + 32 + cn] = sp;
            ph = tanhf(c[mt][nt][3] + b1v) * PI_F; __sincosf(ph, &sp, &cp);
            fdst[(r+8)*64 + cn+1] = cp; fdst[(r+8)*64 + 32 + cn+1] = sp;
        }
    }
    // gates: each warp handles 16 rows
    for (int rr = 0; rr < 16; rr++) {
        int r = row0 + w*16 + rr;
        float p0 = 0.f, p1 = 0.f;
        #pragma unroll
        for (int i = lane; i < 64; i += 32) {
            float gv = g_g1[r*64 + i];
            p0 += gv * Wg2[i*2 + 0];
            p1 += gv * Wg2[i*2 + 1];
        }
        #pragma unroll
        for (int off = 16; off; off >>= 1) {
            p0 += __shfl_xor_sync(~0u, p0, off);
            p1 += __shfl_xor_sync(~0u, p1, off);
        }
        if (lane == 0) {
            float l0 = p0 + bg2[0], l1 = p1 + bg2[1];
            float m = fmaxf(l0, l1);
            float e0 = __expf(l0 - m), e1 = __expf(l1 - m);
            float inv = 1.f / (e0 + e1);
            g_gates[r*2 + 0] = e0 * inv;
            g_gates[r*2 + 1] = e1 * inv;
        }
    }
}

// ================= Kernel 3a: content chunk states via tf32 mma =================
// S[f, d] = sum_{l<128} kf[row0+l, f] * vc[row0+l, d]; grid (32 bc, 2 d-half)
// kf staged row-major [l][f]; A fragment reads swapped (A[f][l] = Kl[l][f]).
__global__ __launch_bounds__(256) void k3a_mma()
{
    __shared__ float Kl[2][16][68];    // [l-chunk 16][f 64]
    __shared__ float Bs[2][16][132];   // [l][d]
    int bc = blockIdx.x;
    int b = bc >> 4, c = bc & 15;
    int d0 = blockIdx.y * 128;
    int row0 = b * LL + c * CC;
    int tid = threadIdx.x;
    int w = tid >> 5, lane = tid & 31;
    int wm = (w & 1) * 32, wn = (w >> 1) * 32;
    int lq = lane >> 2, lr = lane & 3;
    int af4 = (tid & 15) * 4, al = tid >> 4;
    int rB = tid >> 5, cB = (tid & 31) * 4;
    float acc[2][4][4] = {};
    float4 av, bv0, bv1;

    av  = *(const float4*)&g_kf[(row0 + al) * 64 + af4];
    bv0 = *(const float4*)&g_vc[(row0 + rB) * 256 + d0 + cB];
    bv1 = *(const float4*)&g_vc[(row0 + rB + 8) * 256 + d0 + cB];
    *(float4*)&Kl[0][al][af4] = av;
    *(float4*)&Bs[0][rB][cB] = bv0;
    *(float4*)&Bs[0][rB+8][cB] = bv1;
    __syncthreads();

    for (int s = 0; s < 8; s++) {
        int cur = s & 1;
        if (s < 7) {
            int kn = (s + 1) * 16;
            av  = *(const float4*)&g_kf[(row0 + kn + al) * 64 + af4];
            bv0 = *(const float4*)&g_vc[(row0 + kn + rB) * 256 + d0 + cB];
            bv1 = *(const float4*)&g_vc[(row0 + kn + rB + 8) * 256 + d0 + cB];
        }
        #pragma unroll
        for (int ks = 0; ks < 2; ks++) {
            unsigned a[2][4];
            #pragma unroll
            for (int mt = 0; mt < 2; mt++) {
                int rr = wm + mt*16 + lq;      // f index (output row)
                int cc = ks*8 + lr;            // l index (k)
                a[mt][0] = __float_as_uint(Kl[cur][cc][rr]);
                a[mt][1] = __float_as_uint(Kl[cur][cc][rr+8]);
                a[mt][2] = __float_as_uint(Kl[cur][cc+4][rr]);
                a[mt][3] = __float_as_uint(Kl[cur][cc+4][rr+8]);
            }
            #pragma unroll
            for (int nt = 0; nt < 4; nt++) {
                int bn = wn + nt*8 + lq;
                unsigned b0 = __float_as_uint(Bs[cur][ks*8+lr][bn]);
                unsigned b1 = __float_as_uint(Bs[cur][ks*8+lr+4][bn]);
                #pragma unroll
                for (int mt = 0; mt < 2; mt++)
                    mma_tf32(acc[mt][nt], a[mt][0], a[mt][1], a[mt][2], a[mt][3], b0, b1);
            }
        }
        if (s < 7) {
            int nb = cur ^ 1;
            *(float4*)&Kl[nb][al][af4] = av;
            *(float4*)&Bs[nb][rB][cB] = bv0;
            *(float4*)&Bs[nb][rB+8][cB] = bv1;
        }
        __syncthreads();
    }
    int base = bc * 64 * 256;
    #pragma unroll
    for (int mt = 0; mt < 2; mt++) {
        #pragma unroll
        for (int nt = 0; nt < 4; nt++) {
            int f = wm + mt*16 + lq;
            int dd = d0 + wn + nt*8 + lr*2;
            *(float2*)&g_S[base + f * 256 + dd] = make_float2(acc[mt][nt][0], acc[mt][nt][1]);
            *(float2*)&g_S[base + (f+8) * 256 + dd] = make_float2(acc[mt][nt][2], acc[mt][nt][3]);
        }
    }
}

// ================= Kernel 3b: pos partial sums + 8-row snapshots =================
__global__ __launch_bounds__(256) void k3b_pos(const float* __restrict__ base_phases)
{
    int blk = blockIdx.x;            // b*64 + s
    int b = blk >> 6, s = blk & 63;
    int row0 = b * LL + s * 32;
    int l0 = s * 32;
    int d = threadIdx.x;
    float par = 0.f, pai = 0.f;
    #pragma unroll
    for (int g = 0; g < 4; g++) {
        float vp8[8], ph8[8];
        #pragma unroll
        for (int j = 0; j < 8; j++) {
            vp8[j] = g_vp[(row0 + g*8 + j) * 256 + d];
            ph8[j] = base_phases[(l0 + g*8 + j) * 256 + d];
        }
        #pragma unroll
        for (int j = 0; j < 8; j++) {
            float sp, cp; __sincosf(ph8[j], &sp, &cp);
            par += vp8[j] * cp; pai += vp8[j] * sp;
        }
        int snapbase = (blk * 4 + g) * 512;
        g_psnap[snapbase + d] = par;
        g_psnap[snapbase + 256 + d] = pai;
    }
}

// ================= Kernel 4: exclusive prefixes (front-batched loads) =================
__global__ __launch_bounds__(256) void k4_prefix()
{
    int tid = threadIdx.x;
    if (blockIdx.x < 128) {
        int idx = blockIdx.x * 256 + tid;       // (b, f*256+d) -> 32768 chains
        int b = idx >> 14, rd = idx & 16383;
        float v[16];
        #pragma unroll
        for (int c = 0; c < 16; c++)
            v[c] = g_S[(b * 16 + c) * 16384 + rd];
        float run = 0.f;
        #pragma unroll
        for (int c = 0; c < 16; c++) {
            g_P[(b * 16 + c) * 16384 + rd] = run;
            run += v[c];
        }
    } else {
        int e = (blockIdx.x - 128) * 256 + tid;
        if (e < 1024) {
            int b = e >> 9, rd = e & 511;
            float v[64];
            #pragma unroll
            for (int s = 0; s < 64; s++)
                v[s] = g_psnap[((b * 64 + s) * 4 + 3) * 512 + rd];  // 32-row sums
            float run = 0.f;
            #pragma unroll
            for (int s = 0; s < 64; s++) {
                g_pprefix[(b * 64 + s) * 512 + rd] = run;
                run += v[s];
            }
        }
    }
}

// ================= Kernel 5: intra-chunk masked scores (tf32 mma) =================
// kf staged row-major; B fragment reads swapped (B[f][j] = Ks[j][f]).
__global__ __launch_bounds__(256) void k5_mma()
{
    __shared__ float As[2][128][20];
    __shared__ float Ks[2][128][20];
    int bc = blockIdx.x; int b = bc >> 4, c = bc & 15;
    int row0 = b * LL + c * CC;
    int tid = threadIdx.x;
    int w = tid >> 5, lane = tid & 31;
    int wm = (w & 3) * 32;
    int wn = (w >> 2) * 64;
    int lq = lane >> 2, lr = lane & 3;
    int r0 = tid >> 2, c4 = (tid & 3) * 4;
    float acc[2][8][4] = {};
    float4 a0v, a1v, u0, u1;

    a0v = *(const float4*)&g_qf[(row0 + r0) * 64 + c4];
    a1v = *(const float4*)&g_qf[(row0 + r0 + 64) * 64 + c4];
    u0  = *(const float4*)&g_kf[(row0 + r0) * 64 + c4];
    u1  = *(const float4*)&g_kf[(row0 + r0 + 64) * 64 + c4];
    *(float4*)&As[0][r0][c4] = a0v;
    *(float4*)&As[0][r0+64][c4] = a1v;
    *(float4*)&Ks[0][r0][c4] = u0;
    *(float4*)&Ks[0][r0+64][c4] = u1;
    __syncthreads();

    for (int s = 0; s < 4; s++) {
        int cur = s & 1;
        if (s < 3) {
            int kn = (s + 1) * 16;
            a0v = *(const float4*)&g_qf[(row0 + r0) * 64 + kn + c4];
            a1v = *(const float4*)&g_qf[(row0 + r0 + 64) * 64 + kn + c4];
            u0  = *(const float4*)&g_kf[(row0 + r0) * 64 + kn + c4];
            u1  = *(const float4*)&g_kf[(row0 + r0 + 64) * 64 + kn + c4];
        }
        #pragma unroll
        for (int ks = 0; ks < 2; ks++) {
            unsigned a[2][4];
            #pragma unroll
            for (int mt = 0; mt < 2; mt++) {
                int rr = wm + mt*16 + lq;
                int cc = ks*8 + lr;
                a[mt][0] = __float_as_uint(As[cur][rr][cc]);
                a[mt][1] = __float_as_uint(As[cur][rr+8][cc]);
                a[mt][2] = __float_as_uint(As[cur][rr][cc+4]);
                a[mt][3] = __float_as_uint(As[cur][rr+8][cc+4]);
            }
            #pragma unroll
            for (int nt = 0; nt < 8; nt++) {
                int bn = wn + nt*8 + lq;     // j (column of scores)
                unsigned b0 = __float_as_uint(Ks[cur][bn][ks*8+lr]);
                unsigned b1 = __float_as_uint(Ks[cur][bn][ks*8+lr+4]);
                #pragma unroll
                for (int mt = 0; mt < 2; mt++)
                    mma_tf32(acc[mt][nt], a[mt][0], a[mt][1], a[mt][2], a[mt][3], b0, b1);
            }
        }
        if (s < 3) {
            int nb = cur ^ 1;
            *(float4*)&As[nb][r0][c4] = a0v;
            *(float4*)&As[nb][r0+64][c4] = a1v;
            *(float4*)&Ks[nb][r0][c4] = u0;
            *(float4*)&Ks[nb][r0+64][c4] = u1;
        }
        __syncthreads();
    }
    int sb = bc * CC * CC;
    #pragma unroll
    for (int mt = 0; mt < 2; mt++) {
        #pragma unroll
        for (int nt = 0; nt < 8; nt++) {
            int la = wm + mt*16 + lq;
            int lb = la + 8;
            int j0 = wn + nt*8 + lr*2;
            int j1 = j0 + 1;
            *(float2*)&g_scores[sb + la*128 + j0] =
                make_float2(j0 <= la ? acc[mt][nt][0] : 0.f, j1 <= la ? acc[mt][nt][1] : 0.f);
            *(float2*)&g_scores[sb + lb*128 + j0] =
                make_float2(j0 <= lb ? acc[mt][nt][2] : 0.f, j1 <= lb ? acc[mt][nt][3] : 0.f);
        }
    }
}

// ================= Kernel 6: content output (tf32 mma): [qf | scores] @ [P ; vc] ======
__global__ __launch_bounds__(256) void k6_mma()
{
    __shared__ float As[2][128][20];
    __shared__ float Bs[2][16][68];
    int bc = blockIdx.x; int b = bc >> 4, c = bc & 15;
    int d0 = blockIdx.y * 64;
    int row0 = b * LL + c * CC;
    int tid = threadIdx.x;
    int w = tid >> 5, lane = tid & 31;
    int wm = (w & 3) * 32;
    int wn = (w >> 2) * 32;
    int lq = lane >> 2, lr = lane & 3;
    int r0 = tid >> 2, c4 = (tid & 3) * 4;
    int br = tid >> 4, bc4 = (tid & 15) * 4;
    int Pbase = bc * 64 * 256;
    int sbase = bc * CC * CC;
    float acc[2][4][4] = {};
    float4 a0v, a1v, bv;

    a0v = *(const float4*)&g_qf[(row0 + r0) * 64 + c4];
    a1v = *(const float4*)&g_qf[(row0 + r0 + 64) * 64 + c4];
    bv  = *(const float4*)&g_P[Pbase + br * 256 + d0 + bc4];
    *(float4*)&As[0][r0][c4] = a0v;
    *(float4*)&As[0][r0+64][c4] = a1v;
    *(float4*)&Bs[0][br][bc4] = bv;
    __syncthreads();

    for (int s = 0; s < 12; s++) {
        int cur = s & 1;
        if (s < 11) {
            int kn = (s + 1) * 16;
            int kga = kn + c4;
            if (kga < 64) {
                a0v = *(const float4*)&g_qf[(row0 + r0) * 64 + kga];
                a1v = *(const float4*)&g_qf[(row0 + r0 + 64) * 64 + kga];
            } else {
                a0v = *(const float4*)&g_scores[sbase + r0 * 128 + kga - 64];
                a1v = *(const float4*)&g_scores[sbase + (r0 + 64) * 128 + kga - 64];
            }
            int kgb = kn + br;
            if (kgb < 64) bv = *(const float4*)&g_P[Pbase + kgb * 256 + d0 + bc4];
            else          bv = *(const float4*)&g_vc[(row0 + kgb - 64) * 256 + d0 + bc4];
        }
        #pragma unroll
        for (int ks = 0; ks < 2; ks++) {
            unsigned a[2][4];
            #pragma unroll
            for (int mt = 0; mt < 2; mt++) {
                int rr = wm + mt*16 + lq;
                int cc = ks*8 + lr;
                a[mt][0] = __float_as_uint(As[cur][rr][cc]);
                a[mt][1] = __float_as_uint(As[cur][rr+8][cc]);
                a[mt][2] = __float_as_uint(As[cur][rr][cc+4]);
                a[mt][3] = __float_as_uint(As[cur][rr+8][cc+4]);
            }
            #pragma unroll
            for (int nt = 0; nt < 4; nt++) {
                int bn = wn + nt*8 + lq;
                unsigned b0 = __float_as_uint(Bs[cur][ks*8+lr][bn]);
                unsigned b1 = __float_as_uint(Bs[cur][ks*8+lr+4][bn]);
                #pragma unroll
                for (int mt = 0; mt < 2; mt++)
                    mma_tf32(acc[mt][nt], a[mt][0], a[mt][1], a[mt][2], a[mt][3], b0, b1);
            }
        }
        if (s < 11) {
            int nb = cur ^ 1;
            *(float4*)&As[nb][r0][c4] = a0v;
            *(float4*)&As[nb][r0+64][c4] = a1v;
            *(float4*)&Bs[nb][br][bc4] = bv;
        }
        __syncthreads();
    }
    #pragma unroll
    for (int mt = 0; mt < 2; mt++) {
        #pragma unroll
        for (int nt = 0; nt < 4; nt++) {
            int la = wm + mt*16 + lq;
            int lb = la + 8;
            int cc = d0 + wn + nt*8 + lr*2;
            float sa = rsqrtf((float)((c*CC + la + 1) * KK));
            float sb2 = rsqrtf((float)((c*CC + lb + 1) * KK));
            *(float2*)&g_cont[(row0 + la) * 256 + cc] =
                make_float2(acc[mt][nt][0] * sa, acc[mt][nt][1] * sa);
            *(float2*)&g_cont[(row0 + lb) * 256 + cc] =
                make_float2(acc[mt][nt][2] * sb2, acc[mt][nt][3] * sb2);
        }
    }
}

// ================= Kernel 7: pos scan (8 rows/block) + gate combine + LayerNorm =========
__global__ __launch_bounds__(256) void k7_poscomb(
    const float* __restrict__ base_phases,
    const float* __restrict__ ln_g, const float* __restrict__ ln_b)
{
    __shared__ float comb[8][257];
    int blk = blockIdx.x;            // b*256 + s*4 + j
    int j = blk & 3;
    int s = (blk >> 2) & 63;
    int b = blk >> 8;
    int row0 = b * LL + s * 32 + j * 8;
    int l0 = s * 32 + j * 8;
    int d = threadIdx.x;
    float ar = g_pprefix[(b * 64 + s) * 512 + d];
    float ai = g_pprefix[(b * 64 + s) * 512 + 256 + d];
    if (j > 0) {
        int snapbase = ((b * 64 + s) * 4 + j - 1) * 512;
        ar += g_psnap[snapbase + d];
        ai += g_psnap[snapbase + 256 + d];
    }
    float vp[8], ph[8], cv[8];
    #pragma unroll
    for (int lt = 0; lt < 8; lt++) {
        vp[lt] = g_vp[(row0 + lt) * 256 + d];
        ph[lt] = base_phases[(l0 + lt) * 256 + d];
        cv[lt] = g_cont[(row0 + lt) * 256 + d];
    }
    #pragma unroll
    for (int lt = 0; lt < 8; lt++) {
        float sp, cp; __sincosf(ph[lt], &sp, &cp);
        ar += vp[lt] * cp; ai += vp[lt] * sp;
        float pret = (ar * cp + ai * sp) * rsqrtf((float)(l0 + lt + 1));
        float g0 = g_gates[(row0 + lt) * 2], g1v = g_gates[(row0 + lt) * 2 + 1];
        comb[lt][d] = g0 * pret + g1v * cv[lt];
    }
    __syncthreads();
    int w = d >> 5, lane = d & 31;
    int r = row0 + w;
    float vals[8]; float s1 = 0.f, s2 = 0.f;
    #pragma unroll
    for (int k = 0; k < 8; k++) {
        float v = comb[w][lane + 32*k];
        vals[k] = v; s1 += v; s2 += v*v;
    }
    #pragma unroll
    for (int off = 16; off; off >>= 1) {
        s1 += __shfl_xor_sync(~0u, s1, off);
        s2 += __shfl_xor_sync(~0u, s2, off);
    }
    float mu = s1 * (1.f/256.f);
    float var = s2 * (1.f/256.f) - mu*mu;
    float rstd = rsqrtf(var + 1e-5f);
    #pragma unroll
    for (int k = 0; k < 8; k++) {
        int dd = lane + 32*k;
        g_norm[r*256 + dd] = (vals[k] - mu) * rstd * ln_g[dd] + ln_b[dd];
    }
}

// ================= Kernel 8: out = x + normed @ Wo + bo =================
__global__ __launch_bounds__(256) void k8_mma(
    const float* __restrict__ x, const float* __restrict__ Wo,
    const float* __restrict__ bo, float* __restrict__ out)
{
    __shared__ float As[2][128][20];
    __shared__ float Bs[2][16][68];
    int row0 = blockIdx.x * 128;
    int colbase = blockIdx.y * 64;
    int tid = threadIdx.x;
    int w = tid >> 5, lane = tid & 31;
    int wm = (w & 3) * 32;
    int wn = (w >> 2) * 32;
    int lq = lane >> 2, lr = lane & 3;
    int r0 = tid >> 2, c4 = (tid & 3) * 4;
    int br = tid >> 4, bc4 = (tid & 15) * 4;
    float c[2][4][4] = {};
    float4 av0, av1, bv;

    av0 = *(const float4*)&g_norm[(row0 + r0) * 256 + c4];
    av1 = *(const float4*)&g_norm[(row0 + r0 + 64) * 256 + c4];
    bv  = *(const float4*)&Wo[br * 256 + colbase + bc4];
    *(float4*)&As[0][r0][c4] = av0;
    *(float4*)&As[0][r0+64][c4] = av1;
    *(float4*)&Bs[0][br][bc4] = bv;
    __syncthreads();

    for (int s = 0; s < 16; s++) {
        int cur = s & 1;
        if (s < 15) {
            int kn = (s + 1) * 16;
            av0 = *(const float4*)&g_norm[(row0 + r0) * 256 + kn + c4];
            av1 = *(const float4*)&g_norm[(row0 + r0 + 64) * 256 + kn + c4];
            bv  = *(const float4*)&Wo[(kn + br) * 256 + colbase + bc4];
        }
        #pragma unroll
        for (int ks = 0; ks < 2; ks++) {
            unsigned a[2][4];
            #pragma unroll
            for (int mt = 0; mt < 2; mt++) {
                int rr = wm + mt*16 + lq;
                int cc = ks*8 + lr;
                a[mt][0] = __float_as_uint(As[cur][rr][cc]);
                a[mt][1] = __float_as_uint(As[cur][rr+8][cc]);
                a[mt][2] = __float_as_uint(As[cur][rr][cc+4]);
                a[mt][3] = __float_as_uint(As[cur][rr+8][cc+4]);
            }
            #pragma unroll
            for (int nt = 0; nt < 4; nt++) {
                int bn = wn + nt*8 + lq;
                unsigned b0 = __float_as_uint(Bs[cur][ks*8+lr][bn]);
                unsigned b1 = __float_as_uint(Bs[cur][ks*8+lr+4][bn]);
                #pragma unroll
                for (int mt = 0; mt < 2; mt++)
                    mma_tf32(c[mt][nt], a[mt][0], a[mt][1], a[mt][2], a[mt][3], b0, b1);
            }
        }
        if (s < 15) {
            int nb = cur ^ 1;
            *(float4*)&As[nb][r0][c4] = av0;
            *(float4*)&As[nb][r0+64][c4] = av1;
            *(float4*)&Bs[nb][br][bc4] = bv;
        }
        __syncthreads();
    }
    #pragma unroll
    for (int mt = 0; mt < 2; mt++) {
        #pragma unroll
        for (int nt = 0; nt < 4; nt++) {
            int r = row0 + wm + mt*16 + lq;
            int cc = colbase + wn + nt*8 + lr*2;
            float b0v = bo[cc], b1v = bo[cc+1];
            float2 x0 = *(const float2*)&x[r * 256 + cc];
            float2 x1 = *(const float2*)&x[(r+8) * 256 + cc];
            *(float2*)&out[r * 256 + cc] =
                make_float2(c[mt][nt][0] + b0v + x0.x, c[mt][nt][1] + b1v + x0.y);
            *(float2*)&out[(r+8) * 256 + cc] =
                make_float2(c[mt][nt][2] + b0v + x1.x, c[mt][nt][3] + b1v + x1.y);
        }
    }
}

// ================= launcher =================
extern "C" void kernel_launch(void* const* d_in, const int* in_sizes, int n_in,
                              void* d_out, int out_size)
{
    const float* x   = (const float*)d_in[0];
    const float* bp  = (const float*)d_in[1];
    const float* Wk1 = (const float*)d_in[2];
    const float* bk1 = (const float*)d_in[3];
    const float* Wk2 = (const float*)d_in[4];
    const float* bk2 = (const float*)d_in[5];
    const float* Wq1 = (const float*)d_in[6];
    const float* bq1 = (const float*)d_in[7];
    const float* Wq2 = (const float*)d_in[8];
    const float* bq2 = (const float*)d_in[9];
    const float* Wvc = (const float*)d_in[10];
    const float* bvc = (const float*)d_in[11];
    const float* Wvp = (const float*)d_in[12];
    const float* bvp = (const float*)d_in[13];
    const float* Wg1 = (const float*)d_in[14];
    const float* bg1 = (const float*)d_in[15];
    const float* Wg2 = (const float*)d_in[16];
    const float* bg2 = (const float*)d_in[17];
    const float* lng = (const float*)d_in[18];
    const float* lnb = (const float*)d_in[19];
    const float* Wo  = (const float*)d_in[20];
    const float* bo  = (const float*)d_in[21];
    float* out = (float*)d_out;

    k1_mma<<<dim3(32, 17), 256>>>(x, Wk1, bk1, Wq1, bq1, Wvc, bvc, Wvp, bvp, Wg1, bg1);
    k2_mma<<<32, 256>>>(Wk2, bk2, Wq2, bq2, Wg2, bg2);
    k3a_mma<<<dim3(32, 2), 256>>>();
    k3b_pos<<<128, 256>>>(bp);
    k4_prefix<<<132, 256>>>();
    k5_mma<<<32, 256>>>();
    k6_mma<<<dim3(32, 4), 256>>>();
    k7_poscomb<<<512, 256>>>(bp, lng, lnb);
    k8_mma<<<dim3(32, 4), 256>>>(x, Wo, bo, out);
}

// round 9
// speedup vs baseline: 1.2080x; 1.0833x over previous
#include <cuda_runtime.h>
#include <cuda_bf16.h>
#include <math.h>

// Problem constants
#define Bb 2
#define LL 2048
#define DD 256
#define KK 32
#define FF 64          // 2*K feature dim
#define MM (Bb*LL)     // 4096 rows
#define CC 128         // chunk size
#define NC (LL/CC)     // 16 chunks per batch
#define PI_F 3.14159265358979323846f

// ---------------- scratch (device globals; no allocation allowed) ----------------
__device__ float g_hk[MM*DD];
__device__ float g_hq[MM*DD];
__device__ float g_vc[MM*DD];
__device__ float g_vp[MM*DD];
__device__ float g_g1[MM*64];
__device__ float g_kf[MM*FF];
__device__ float g_qf[MM*FF];
__device__ float g_gates[MM*2];
__device__ float g_S[Bb*NC*FF*DD];         // per-chunk content state sums (mma)
__device__ float g_P[Bb*NC*FF*DD];         // chunk-level exclusive prefix of states
__device__ float g_psnap[Bb*64*4*2*DD];    // pos accum snapshots every 8 rows (inclusive)
__device__ float g_pprefix[Bb*64*2*DD];    // exclusive prefix at 32-row granularity
__device__ float g_scores[Bb*NC*CC*CC];    // intra-chunk masked scores
__device__ float g_cont[MM*DD];
__device__ float g_norm[MM*DD];

// mma consumes raw f32 bit patterns as tf32 (HW truncates mantissa; no cvt needed)
__device__ __forceinline__ void mma_tf32(float c[4],
    unsigned a0, unsigned a1, unsigned a2, unsigned a3,
    unsigned b0, unsigned b1)
{
    asm volatile(
        "mma.sync.aligned.m16n8k8.row.col.f32.tf32.tf32.f32 "
        "{%0,%1,%2,%3}, {%4,%5,%6,%7}, {%8,%9}, {%0,%1,%2,%3};"
        : "+f"(c[0]), "+f"(c[1]), "+f"(c[2]), "+f"(c[3])
        : "r"(a0), "r"(a1), "r"(a2), "r"(a3), "r"(b0), "r"(b1));
}

// ================= Kernel 1: fused first-layer GEMMs =================
// grid (32, 17): ct<16 -> [hk|hq|vc|vp] x 4 col-quarters; ct==16 -> g1
__global__ __launch_bounds__(256) void k1_mma(
    const float* __restrict__ x,
    const float* __restrict__ Wk1, const float* __restrict__ bk1,
    const float* __restrict__ Wq1, const float* __restrict__ bq1,
    const float* __restrict__ Wvc, const float* __restrict__ bvc,
    const float* __restrict__ Wvp, const float* __restrict__ bvp,
    const float* __restrict__ Wg1, const float* __restrict__ bg1)
{
    __shared__ float As[2][128][20];
    __shared__ float Bs[2][16][68];
    int ct = blockIdx.y;
    const float* W; const float* bias; float* outp; int Nseg; int act; int colbase;
    if (ct < 16) {
        int seg = ct >> 2;
        colbase = (ct & 3) * 64;
        Nseg = 256;
        if (seg == 0)      { W = Wk1; bias = bk1; outp = g_hk; act = 1; }
        else if (seg == 1) { W = Wq1; bias = bq1; outp = g_hq; act = 1; }
        else if (seg == 2) { W = Wvc; bias = bvc; outp = g_vc; act = 0; }
        else               { W = Wvp; bias = bvp; outp = g_vp; act = 0; }
    } else {
        W = Wg1; bias = bg1; outp = g_g1; Nseg = 64; act = 2; colbase = 0;
    }
    int row0 = blockIdx.x * 128;
    int tid = threadIdx.x;
    int w = tid >> 5, lane = tid & 31;
    int wm = (w & 3) * 32;
    int wn = (w >> 2) * 32;
    int lq = lane >> 2, lr = lane & 3;
    int r0 = tid >> 2, c4 = (tid & 3) * 4;
    int br = tid >> 4, bc4 = (tid & 15) * 4;
    float c[2][4][4] = {};
    float4 av0, av1, bv;

    av0 = *(const float4*)&x[(row0 + r0) * 256 + c4];
    av1 = *(const float4*)&x[(row0 + r0 + 64) * 256 + c4];
    bv  = *(const float4*)&W[br * Nseg + colbase + bc4];
    *(float4*)&As[0][r0][c4] = av0;
    *(float4*)&As[0][r0+64][c4] = av1;
    *(float4*)&Bs[0][br][bc4] = bv;
    __syncthreads();

    for (int s = 0; s < 16; s++) {
        int cur = s & 1;
        if (s < 15) {
            int kn = (s + 1) * 16;
            av0 = *(const float4*)&x[(row0 + r0) * 256 + kn + c4];
            av1 = *(const float4*)&x[(row0 + r0 + 64) * 256 + kn + c4];
            bv  = *(const float4*)&W[(kn + br) * Nseg + colbase + bc4];
        }
        #pragma unroll
        for (int ks = 0; ks < 2; ks++) {
            unsigned a[2][4];
            #pragma unroll
            for (int mt = 0; mt < 2; mt++) {
                int rr = wm + mt*16 + lq;
                int cc = ks*8 + lr;
                a[mt][0] = __float_as_uint(As[cur][rr][cc]);
                a[mt][1] = __float_as_uint(As[cur][rr+8][cc]);
                a[mt][2] = __float_as_uint(As[cur][rr][cc+4]);
                a[mt][3] = __float_as_uint(As[cur][rr+8][cc+4]);
            }
            #pragma unroll
            for (int nt = 0; nt < 4; nt++) {
                int bn = wn + nt*8 + lq;
                unsigned b0 = __float_as_uint(Bs[cur][ks*8+lr][bn]);
                unsigned b1 = __float_as_uint(Bs[cur][ks*8+lr+4][bn]);
                #pragma unroll
                for (int mt = 0; mt < 2; mt++)
                    mma_tf32(c[mt][nt], a[mt][0], a[mt][1], a[mt][2], a[mt][3], b0, b1);
            }
        }
        if (s < 15) {
            int nb = cur ^ 1;
            *(float4*)&As[nb][r0][c4] = av0;
            *(float4*)&As[nb][r0+64][c4] = av1;
            *(float4*)&Bs[nb][br][bc4] = bv;
        }
        __syncthreads();
    }
    #pragma unroll
    for (int mt = 0; mt < 2; mt++) {
        #pragma unroll
        for (int nt = 0; nt < 4; nt++) {
            int r = row0 + wm + mt*16 + lq;
            int cc = colbase + wn + nt*8 + lr*2;
            float b0v = bias[cc], b1v = bias[cc+1];
            float v00 = c[mt][nt][0] + b0v, v01 = c[mt][nt][1] + b1v;
            float v10 = c[mt][nt][2] + b0v, v11 = c[mt][nt][3] + b1v;
            if (act == 1) { v00 = tanhf(v00); v01 = tanhf(v01); v10 = tanhf(v10); v11 = tanhf(v11); }
            else if (act == 2) { v00 = fmaxf(v00,0.f); v01 = fmaxf(v01,0.f); v10 = fmaxf(v10,0.f); v11 = fmaxf(v11,0.f); }
            *(float2*)&outp[r * Nseg + cc] = make_float2(v00, v01);
            *(float2*)&outp[(r+8) * Nseg + cc] = make_float2(v10, v11);
        }
    }
}

// ================= Kernel 2+3b merged: phase features + gates || pos partial sums =======
// blocks [0,32): k2 work; blocks [32,160): k3b work. Both depend only on k1.
__global__ __launch_bounds__(256) void k23b_mma(
    const float* __restrict__ Wk2, const float* __restrict__ bk2,
    const float* __restrict__ Wq2, const float* __restrict__ bq2,
    const float* __restrict__ Wg2, const float* __restrict__ bg2,
    const float* __restrict__ base_phases)
{
    __shared__ float Ak[2][128][18];
    __shared__ float Aq[2][128][18];
    __shared__ float Bs[2][16][68];
    int tid = threadIdx.x;

    if (blockIdx.x >= 32) {
        // ---- k3b: pos partial sums + 8-row snapshots ----
        int blk = blockIdx.x - 32;   // b*64 + s
        int row0 = (blk >> 6) * LL + (blk & 63) * 32;
        int l0 = (blk & 63) * 32;
        int d = tid;
        float par = 0.f, pai = 0.f;
        #pragma unroll
        for (int g = 0; g < 4; g++) {
            float vp8[8], ph8[8];
            #pragma unroll
            for (int j = 0; j < 8; j++) {
                vp8[j] = g_vp[(row0 + g*8 + j) * 256 + d];
                ph8[j] = base_phases[(l0 + g*8 + j) * 256 + d];
            }
            #pragma unroll
            for (int j = 0; j < 8; j++) {
                float sp, cp; __sincosf(ph8[j], &sp, &cp);
                par += vp8[j] * cp; pai += vp8[j] * sp;
            }
            int snapbase = (blk * 4 + g) * 512;
            g_psnap[snapbase + d] = par;
            g_psnap[snapbase + 256 + d] = pai;
        }
        return;
    }

    // ---- k2: phase features (tf32 mma) + gates ----
    int w = tid >> 5, lane = tid & 31;
    int row0 = blockIdx.x * 128;
    int wm = (w & 3) * 32;
    bool isq = (w >= 4);
    int lq = lane >> 2, lr = lane & 3;
    int r0 = tid >> 2, c4 = (tid & 3) * 4;
    int br = tid >> 4, bc4 = (tid & 15) * 4;
    float c[2][4][4] = {};
    float4 ak0, ak1, aq0, aq1, bv;

    ak0 = *(const float4*)&g_hk[(row0 + r0) * 256 + c4];
    ak1 = *(const float4*)&g_hk[(row0 + r0 + 64) * 256 + c4];
    aq0 = *(const float4*)&g_hq[(row0 + r0) * 256 + c4];
    aq1 = *(const float4*)&g_hq[(row0 + r0 + 64) * 256 + c4];
    bv  = (bc4 < 32) ? *(const float4*)&Wk2[br * 32 + bc4]
                     : *(const float4*)&Wq2[br * 32 + bc4 - 32];
    *(float2*)&Ak[0][r0][c4]      = make_float2(ak0.x, ak0.y);
    *(float2*)&Ak[0][r0][c4+2]    = make_float2(ak0.z, ak0.w);
    *(float2*)&Ak[0][r0+64][c4]   = make_float2(ak1.x, ak1.y);
    *(float2*)&Ak[0][r0+64][c4+2] = make_float2(ak1.z, ak1.w);
    *(float2*)&Aq[0][r0][c4]      = make_float2(aq0.x, aq0.y);
    *(float2*)&Aq[0][r0][c4+2]    = make_float2(aq0.z, aq0.w);
    *(float2*)&Aq[0][r0+64][c4]   = make_float2(aq1.x, aq1.y);
    *(float2*)&Aq[0][r0+64][c4+2] = make_float2(aq1.z, aq1.w);
    *(float4*)&Bs[0][br][bc4] = bv;
    __syncthreads();

    for (int s = 0; s < 16; s++) {
        int cur = s & 1;
        if (s < 15) {
            int kn = (s + 1) * 16;
            ak0 = *(const float4*)&g_hk[(row0 + r0) * 256 + kn + c4];
            ak1 = *(const float4*)&g_hk[(row0 + r0 + 64) * 256 + kn + c4];
            aq0 = *(const float4*)&g_hq[(row0 + r0) * 256 + kn + c4];
            aq1 = *(const float4*)&g_hq[(row0 + r0 + 64) * 256 + kn + c4];
            bv  = (bc4 < 32) ? *(const float4*)&Wk2[(kn + br) * 32 + bc4]
                             : *(const float4*)&Wq2[(kn + br) * 32 + bc4 - 32];
        }
        const float (*A)[18] = isq ? Aq[cur] : Ak[cur];
        #pragma unroll
        for (int ks = 0; ks < 2; ks++) {
            unsigned a[2][4];
            #pragma unroll
            for (int mt = 0; mt < 2; mt++) {
                int rr = wm + mt*16 + lq;
                int cc = ks*8 + lr;
                a[mt][0] = __float_as_uint(A[rr][cc]);
                a[mt][1] = __float_as_uint(A[rr+8][cc]);
                a[mt][2] = __float_as_uint(A[rr][cc+4]);
                a[mt][3] = __float_as_uint(A[rr+8][cc+4]);
            }
            #pragma unroll
            for (int nt = 0; nt < 4; nt++) {
                int bn = (isq ? 32 : 0) + nt*8 + lq;
                unsigned b0 = __float_as_uint(Bs[cur][ks*8+lr][bn]);
                unsigned b1 = __float_as_uint(Bs[cur][ks*8+lr+4][bn]);
                #pragma unroll
                for (int mt = 0; mt < 2; mt++)
                    mma_tf32(c[mt][nt], a[mt][0], a[mt][1], a[mt][2], a[mt][3], b0, b1);
            }
        }
        if (s < 15) {
            int nb = cur ^ 1;
            *(float2*)&Ak[nb][r0][c4]      = make_float2(ak0.x, ak0.y);
            *(float2*)&Ak[nb][r0][c4+2]    = make_float2(ak0.z, ak0.w);
            *(float2*)&Ak[nb][r0+64][c4]   = make_float2(ak1.x, ak1.y);
            *(float2*)&Ak[nb][r0+64][c4+2] = make_float2(ak1.z, ak1.w);
            *(float2*)&Aq[nb][r0][c4]      = make_float2(aq0.x, aq0.y);
            *(float2*)&Aq[nb][r0][c4+2]    = make_float2(aq0.z, aq0.w);
            *(float2*)&Aq[nb][r0+64][c4]   = make_float2(aq1.x, aq1.y);
            *(float2*)&Aq[nb][r0+64][c4+2] = make_float2(aq1.z, aq1.w);
            *(float4*)&Bs[nb][br][bc4] = bv;
        }
        __syncthreads();
    }

    const float* bvec = isq ? bq2 : bk2;
    float* fdst = isq ? g_qf : g_kf;
    #pragma unroll
    for (int mt = 0; mt < 2; mt++) {
        #pragma unroll
        for (int nt = 0; nt < 4; nt++) {
            int r = row0 + wm + mt*16 + lq;
            int cn = nt*8 + lr*2;
            float b0v = bvec[cn], b1v = bvec[cn+1];
            float ph;
            float sp, cp;
            ph = tanhf(c[mt][nt][0] + b0v) * PI_F; __sincosf(ph, &sp, &cp);
            fdst[r*64 + cn] = cp; fdst[r*64 + 32 + cn] = sp;
            ph = tanhf(c[mt][nt][1] + b1v) * PI_F; __sincosf(ph, &sp, &cp);
            fdst[r*64 + cn+1] = cp; fdst[r*64 + 32 + cn+1] = sp;
            ph = tanhf(c[mt][nt][2] + b0v) * PI_F; __sincosf(ph, &sp, &cp);
            fdst[(r+8)*64 + cn] = cp; fdst[(r+8)*64 + 32 + cn] = sp;
            ph = tanhf(c[mt][nt][3] + b1v) * PI_F; __sincosf(ph, &sp, &cp);
            fdst[(r+8)*64 + cn+1] = cp; fdst[(r+8)*64 + 32 + cn+1] = sp;
        }
    }
    // gates: each warp handles 16 rows
    for (int rr = 0; rr < 16; rr++) {
        int r = row0 + w*16 + rr;
        float p0 = 0.f, p1 = 0.f;
        #pragma unroll
        for (int i = lane; i < 64; i += 32) {
            float gv = g_g1[r*64 + i];
            p0 += gv * Wg2[i*2 + 0];
            p1 += gv * Wg2[i*2 + 1];
        }
        #pragma unroll
        for (int off = 16; off; off >>= 1) {
            p0 += __shfl_xor_sync(~0u, p0, off);
            p1 += __shfl_xor_sync(~0u, p1, off);
        }
        if (lane == 0) {
            float l0 = p0 + bg2[0], l1 = p1 + bg2[1];
            float m = fmaxf(l0, l1);
            float e0 = __expf(l0 - m), e1 = __expf(l1 - m);
            float inv = 1.f / (e0 + e1);
            g_gates[r*2 + 0] = e0 * inv;
            g_gates[r*2 + 1] = e1 * inv;
        }
    }
}

// ================= Kernel 3a+5 merged: chunk states || masked scores =================
// blocks [0,64): k3a (bc = x&31, d0 = (x>>5)*128); blocks [64,96): k5 (bc = x-64).
// Shared memory is a union: k3a needs 6400 floats, k5 needs 10240 floats.
__global__ __launch_bounds__(256) void k3a5_mma()
{
    __shared__ float sraw[10240];
    int tid = threadIdx.x;
    int w = tid >> 5, lane = tid & 31;
    int lq = lane >> 2, lr = lane & 3;

    if (blockIdx.x < 64) {
        // ---- k3a: S[f, d] = sum_l kf[l,f] * vc[l,d] ----
        float (*Kl)[16][68]  = (float(*)[16][68])sraw;          // 2176 floats
        float (*Bs)[16][132] = (float(*)[16][132])(sraw + 2176); // 4224 floats
        int bc = blockIdx.x & 31;
        int b = bc >> 4, c = bc & 15;
        int d0 = (blockIdx.x >> 5) * 128;
        int row0 = b * LL + c * CC;
        int wm = (w & 1) * 32, wn = (w >> 1) * 32;
        int af4 = (tid & 15) * 4, al = tid >> 4;
        int rB = tid >> 5, cB = (tid & 31) * 4;
        float acc[2][4][4] = {};
        float4 av, bv0, bv1;

        av  = *(const float4*)&g_kf[(row0 + al) * 64 + af4];
        bv0 = *(const float4*)&g_vc[(row0 + rB) * 256 + d0 + cB];
        bv1 = *(const float4*)&g_vc[(row0 + rB + 8) * 256 + d0 + cB];
        *(float4*)&Kl[0][al][af4] = av;
        *(float4*)&Bs[0][rB][cB] = bv0;
        *(float4*)&Bs[0][rB+8][cB] = bv1;
        __syncthreads();

        for (int s = 0; s < 8; s++) {
            int cur = s & 1;
            if (s < 7) {
                int kn = (s + 1) * 16;
                av  = *(const float4*)&g_kf[(row0 + kn + al) * 64 + af4];
                bv0 = *(const float4*)&g_vc[(row0 + kn + rB) * 256 + d0 + cB];
                bv1 = *(const float4*)&g_vc[(row0 + kn + rB + 8) * 256 + d0 + cB];
            }
            #pragma unroll
            for (int ks = 0; ks < 2; ks++) {
                unsigned a[2][4];
                #pragma unroll
                for (int mt = 0; mt < 2; mt++) {
                    int rr = wm + mt*16 + lq;
                    int cc = ks*8 + lr;
                    a[mt][0] = __float_as_uint(Kl[cur][cc][rr]);
                    a[mt][1] = __float_as_uint(Kl[cur][cc][rr+8]);
                    a[mt][2] = __float_as_uint(Kl[cur][cc+4][rr]);
                    a[mt][3] = __float_as_uint(Kl[cur][cc+4][rr+8]);
                }
                #pragma unroll
                for (int nt = 0; nt < 4; nt++) {
                    int bn = wn + nt*8 + lq;
                    unsigned b0 = __float_as_uint(Bs[cur][ks*8+lr][bn]);
                    unsigned b1 = __float_as_uint(Bs[cur][ks*8+lr+4][bn]);
                    #pragma unroll
                    for (int mt = 0; mt < 2; mt++)
                        mma_tf32(acc[mt][nt], a[mt][0], a[mt][1], a[mt][2], a[mt][3], b0, b1);
                }
            }
            if (s < 7) {
                int nb = cur ^ 1;
                *(float4*)&Kl[nb][al][af4] = av;
                *(float4*)&Bs[nb][rB][cB] = bv0;
                *(float4*)&Bs[nb][rB+8][cB] = bv1;
            }
            __syncthreads();
        }
        int base = bc * 64 * 256;
        #pragma unroll
        for (int mt = 0; mt < 2; mt++) {
            #pragma unroll
            for (int nt = 0; nt < 4; nt++) {
                int f = wm + mt*16 + lq;
                int dd = d0 + wn + nt*8 + lr*2;
                *(float2*)&g_S[base + f * 256 + dd] = make_float2(acc[mt][nt][0], acc[mt][nt][1]);
                *(float2*)&g_S[base + (f+8) * 256 + dd] = make_float2(acc[mt][nt][2], acc[mt][nt][3]);
            }
        }
        return;
    }

    // ---- k5: intra-chunk masked scores ----
    {
        float (*As)[128][20] = (float(*)[128][20])sraw;           // 5120 floats
        float (*Ks)[128][20] = (float(*)[128][20])(sraw + 5120);  // 5120 floats
        int bc = blockIdx.x - 64;
        int b = bc >> 4, c = bc & 15;
        int row0 = b * LL + c * CC;
        int wm = (w & 3) * 32;
        int wn = (w >> 2) * 64;
        int r0 = tid >> 2, c4 = (tid & 3) * 4;
        float acc[2][8][4] = {};
        float4 a0v, a1v, u0, u1;

        a0v = *(const float4*)&g_qf[(row0 + r0) * 64 + c4];
        a1v = *(const float4*)&g_qf[(row0 + r0 + 64) * 64 + c4];
        u0  = *(const float4*)&g_kf[(row0 + r0) * 64 + c4];
        u1  = *(const float4*)&g_kf[(row0 + r0 + 64) * 64 + c4];
        *(float4*)&As[0][r0][c4] = a0v;
        *(float4*)&As[0][r0+64][c4] = a1v;
        *(float4*)&Ks[0][r0][c4] = u0;
        *(float4*)&Ks[0][r0+64][c4] = u1;
        __syncthreads();

        for (int s = 0; s < 4; s++) {
            int cur = s & 1;
            if (s < 3) {
                int kn = (s + 1) * 16;
                a0v = *(const float4*)&g_qf[(row0 + r0) * 64 + kn + c4];
                a1v = *(const float4*)&g_qf[(row0 + r0 + 64) * 64 + kn + c4];
                u0  = *(const float4*)&g_kf[(row0 + r0) * 64 + kn + c4];
                u1  = *(const float4*)&g_kf[(row0 + r0 + 64) * 64 + kn + c4];
            }
            #pragma unroll
            for (int ks = 0; ks < 2; ks++) {
                unsigned a[2][4];
                #pragma unroll
                for (int mt = 0; mt < 2; mt++) {
                    int rr = wm + mt*16 + lq;
                    int cc = ks*8 + lr;
                    a[mt][0] = __float_as_uint(As[cur][rr][cc]);
                    a[mt][1] = __float_as_uint(As[cur][rr+8][cc]);
                    a[mt][2] = __float_as_uint(As[cur][rr][cc+4]);
                    a[mt][3] = __float_as_uint(As[cur][rr+8][cc+4]);
                }
                #pragma unroll
                for (int nt = 0; nt < 8; nt++) {
                    int bn = wn + nt*8 + lq;
                    unsigned b0 = __float_as_uint(Ks[cur][bn][ks*8+lr]);
                    unsigned b1 = __float_as_uint(Ks[cur][bn][ks*8+lr+4]);
                    #pragma unroll
                    for (int mt = 0; mt < 2; mt++)
                        mma_tf32(acc[mt][nt], a[mt][0], a[mt][1], a[mt][2], a[mt][3], b0, b1);
                }
            }
            if (s < 3) {
                int nb = cur ^ 1;
                *(float4*)&As[nb][r0][c4] = a0v;
                *(float4*)&As[nb][r0+64][c4] = a1v;
                *(float4*)&Ks[nb][r0][c4] = u0;
                *(float4*)&Ks[nb][r0+64][c4] = u1;
            }
            __syncthreads();
        }
        int sb = bc * CC * CC;
        #pragma unroll
        for (int mt = 0; mt < 2; mt++) {
            #pragma unroll
            for (int nt = 0; nt < 8; nt++) {
                int la = wm + mt*16 + lq;
                int lb = la + 8;
                int j0 = wn + nt*8 + lr*2;
                int j1 = j0 + 1;
                *(float2*)&g_scores[sb + la*128 + j0] =
                    make_float2(j0 <= la ? acc[mt][nt][0] : 0.f, j1 <= la ? acc[mt][nt][1] : 0.f);
                *(float2*)&g_scores[sb + lb*128 + j0] =
                    make_float2(j0 <= lb ? acc[mt][nt][2] : 0.f, j1 <= lb ? acc[mt][nt][3] : 0.f);
            }
        }
    }
}

// ================= Kernel 4: exclusive prefixes (front-batched loads) =================
__global__ __launch_bounds__(256) void k4_prefix()
{
    int tid = threadIdx.x;
    if (blockIdx.x < 128) {
        int idx = blockIdx.x * 256 + tid;       // (b, f*256+d) -> 32768 chains
        int b = idx >> 14, rd = idx & 16383;
        float v[16];
        #pragma unroll
        for (int c = 0; c < 16; c++)
            v[c] = g_S[(b * 16 + c) * 16384 + rd];
        float run = 0.f;
        #pragma unroll
        for (int c = 0; c < 16; c++) {
            g_P[(b * 16 + c) * 16384 + rd] = run;
            run += v[c];
        }
    } else {
        int e = (blockIdx.x - 128) * 256 + tid;
        if (e < 1024) {
            int b = e >> 9, rd = e & 511;
            float v[64];
            #pragma unroll
            for (int s = 0; s < 64; s++)
                v[s] = g_psnap[((b * 64 + s) * 4 + 3) * 512 + rd];  // 32-row sums
            float run = 0.f;
            #pragma unroll
            for (int s = 0; s < 64; s++) {
                g_pprefix[(b * 64 + s) * 512 + rd] = run;
                run += v[s];
            }
        }
    }
}

// ================= Kernel 6: content output (tf32 mma): [qf | scores] @ [P ; vc] ======
__global__ __launch_bounds__(256) void k6_mma()
{
    __shared__ float As[2][128][20];
    __shared__ float Bs[2][16][68];
    int bc = blockIdx.x; int b = bc >> 4, c = bc & 15;
    int d0 = blockIdx.y * 64;
    int row0 = b * LL + c * CC;
    int tid = threadIdx.x;
    int w = tid >> 5, lane = tid & 31;
    int wm = (w & 3) * 32;
    int wn = (w >> 2) * 32;
    int lq = lane >> 2, lr = lane & 3;
    int r0 = tid >> 2, c4 = (tid & 3) * 4;
    int br = tid >> 4, bc4 = (tid & 15) * 4;
    int Pbase = bc * 64 * 256;
    int sbase = bc * CC * CC;
    float acc[2][4][4] = {};
    float4 a0v, a1v, bv;

    a0v = *(const float4*)&g_qf[(row0 + r0) * 64 + c4];
    a1v = *(const float4*)&g_qf[(row0 + r0 + 64) * 64 + c4];
    bv  = *(const float4*)&g_P[Pbase + br * 256 + d0 + bc4];
    *(float4*)&As[0][r0][c4] = a0v;
    *(float4*)&As[0][r0+64][c4] = a1v;
    *(float4*)&Bs[0][br][bc4] = bv;
    __syncthreads();

    for (int s = 0; s < 12; s++) {
        int cur = s & 1;
        if (s < 11) {
            int kn = (s + 1) * 16;
            int kga = kn + c4;
            if (kga < 64) {
                a0v = *(const float4*)&g_qf[(row0 + r0) * 64 + kga];
                a1v = *(const float4*)&g_qf[(row0 + r0 + 64) * 64 + kga];
            } else {
                a0v = *(const float4*)&g_scores[sbase + r0 * 128 + kga - 64];
                a1v = *(const float4*)&g_scores[sbase + (r0 + 64) * 128 + kga - 64];
            }
            int kgb = kn + br;
            if (kgb < 64) bv = *(const float4*)&g_P[Pbase + kgb * 256 + d0 + bc4];
            else          bv = *(const float4*)&g_vc[(row0 + kgb - 64) * 256 + d0 + bc4];
        }
        #pragma unroll
        for (int ks = 0; ks < 2; ks++) {
            unsigned a[2][4];
            #pragma unroll
            for (int mt = 0; mt < 2; mt++) {
                int rr = wm + mt*16 + lq;
                int cc = ks*8 + lr;
                a[mt][0] = __float_as_uint(As[cur][rr][cc]);
                a[mt][1] = __float_as_uint(As[cur][rr+8][cc]);
                a[mt][2] = __float_as_uint(As[cur][rr][cc+4]);
                a[mt][3] = __float_as_uint(As[cur][rr+8][cc+4]);
            }
            #pragma unroll
            for (int nt = 0; nt < 4; nt++) {
                int bn = wn + nt*8 + lq;
                unsigned b0 = __float_as_uint(Bs[cur][ks*8+lr][bn]);
                unsigned b1 = __float_as_uint(Bs[cur][ks*8+lr+4][bn]);
                #pragma unroll
                for (int mt = 0; mt < 2; mt++)
                    mma_tf32(acc[mt][nt], a[mt][0], a[mt][1], a[mt][2], a[mt][3], b0, b1);
            }
        }
        if (s < 11) {
            int nb = cur ^ 1;
            *(float4*)&As[nb][r0][c4] = a0v;
            *(float4*)&As[nb][r0+64][c4] = a1v;
            *(float4*)&Bs[nb][br][bc4] = bv;
        }
        __syncthreads();
    }
    #pragma unroll
    for (int mt = 0; mt < 2; mt++) {
        #pragma unroll
        for (int nt = 0; nt < 4; nt++) {
            int la = wm + mt*16 + lq;
            int lb = la + 8;
            int cc = d0 + wn + nt*8 + lr*2;
            float sa = rsqrtf((float)((c*CC + la + 1) * KK));
            float sb2 = rsqrtf((float)((c*CC + lb + 1) * KK));
            *(float2*)&g_cont[(row0 + la) * 256 + cc] =
                make_float2(acc[mt][nt][0] * sa, acc[mt][nt][1] * sa);
            *(float2*)&g_cont[(row0 + lb) * 256 + cc] =
                make_float2(acc[mt][nt][2] * sb2, acc[mt][nt][3] * sb2);
        }
    }
}

// ================= Kernel 7: pos scan (8 rows/block) + gate combine + LayerNorm =========
__global__ __launch_bounds__(256) void k7_poscomb(
    const float* __restrict__ base_phases,
    const float* __restrict__ ln_g, const float* __restrict__ ln_b)
{
    __shared__ float comb[8][257];
    int blk = blockIdx.x;            // b*256 + s*4 + j
    int j = blk & 3;
    int s = (blk >> 2) & 63;
    int b = blk >> 8;
    int row0 = b * LL + s * 32 + j * 8;
    int l0 = s * 32 + j * 8;
    int d = threadIdx.x;
    float ar = g_pprefix[(b * 64 + s) * 512 + d];
    float ai = g_pprefix[(b * 64 + s) * 512 + 256 + d];
    if (j > 0) {
        int snapbase = ((b * 64 + s) * 4 + j - 1) * 512;
        ar += g_psnap[snapbase + d];
        ai += g_psnap[snapbase + 256 + d];
    }
    float vp[8], ph[8], cv[8];
    #pragma unroll
    for (int lt = 0; lt < 8; lt++) {
        vp[lt] = g_vp[(row0 + lt) * 256 + d];
        ph[lt] = base_phases[(l0 + lt) * 256 + d];
        cv[lt] = g_cont[(row0 + lt) * 256 + d];
    }
    #pragma unroll
    for (int lt = 0; lt < 8; lt++) {
        float sp, cp; __sincosf(ph[lt], &sp, &cp);
        ar += vp[lt] * cp; ai += vp[lt] * sp;
        float pret = (ar * cp + ai * sp) * rsqrtf((float)(l0 + lt + 1));
        float g0 = g_gates[(row0 + lt) * 2], g1v = g_gates[(row0 + lt) * 2 + 1];
        comb[lt][d] = g0 * pret + g1v * cv[lt];
    }
    __syncthreads();
    int w = d >> 5, lane = d & 31;
    int r = row0 + w;
    float vals[8]; float s1 = 0.f, s2 = 0.f;
    #pragma unroll
    for (int k = 0; k < 8; k++) {
        float v = comb[w][lane + 32*k];
        vals[k] = v; s1 += v; s2 += v*v;
    }
    #pragma unroll
    for (int off = 16; off; off >>= 1) {
        s1 += __shfl_xor_sync(~0u, s1, off);
        s2 += __shfl_xor_sync(~0u, s2, off);
    }
    float mu = s1 * (1.f/256.f);
    float var = s2 * (1.f/256.f) - mu*mu;
    float rstd = rsqrtf(var + 1e-5f);
    #pragma unroll
    for (int k = 0; k < 8; k++) {
        int dd = lane + 32*k;
        g_norm[r*256 + dd] = (vals[k] - mu) * rstd * ln_g[dd] + ln_b[dd];
    }
}

// ================= Kernel 8: out = x + normed @ Wo + bo =================
__global__ __launch_bounds__(256) void k8_mma(
    const float* __restrict__ x, const float* __restrict__ Wo,
    const float* __restrict__ bo, float* __restrict__ out)
{
    __shared__ float As[2][128][20];
    __shared__ float Bs[2][16][68];
    int row0 = blockIdx.x * 128;
    int colbase = blockIdx.y * 64;
    int tid = threadIdx.x;
    int w = tid >> 5, lane = tid & 31;
    int wm = (w & 3) * 32;
    int wn = (w >> 2) * 32;
    int lq = lane >> 2, lr = lane & 3;
    int r0 = tid >> 2, c4 = (tid & 3) * 4;
    int br = tid >> 4, bc4 = (tid & 15) * 4;
    float c[2][4][4] = {};
    float4 av0, av1, bv;

    av0 = *(const float4*)&g_norm[(row0 + r0) * 256 + c4];
    av1 = *(const float4*)&g_norm[(row0 + r0 + 64) * 256 + c4];
    bv  = *(const float4*)&Wo[br * 256 + colbase + bc4];
    *(float4*)&As[0][r0][c4] = av0;
    *(float4*)&As[0][r0+64][c4] = av1;
    *(float4*)&Bs[0][br][bc4] = bv;
    __syncthreads();

    for (int s = 0; s < 16; s++) {
        int cur = s & 1;
        if (s < 15) {
            int kn = (s + 1) * 16;
            av0 = *(const float4*)&g_norm[(row0 + r0) * 256 + kn + c4];
            av1 = *(const float4*)&g_norm[(row0 + r0 + 64) * 256 + kn + c4];
            bv  = *(const float4*)&Wo[(kn + br) * 256 + colbase + bc4];
        }
        #pragma unroll
        for (int ks = 0; ks < 2; ks++) {
            unsigned a[2][4];
            #pragma unroll
            for (int mt = 0; mt < 2; mt++) {
                int rr = wm + mt*16 + lq;
                int cc = ks*8 + lr;
                a[mt][0] = __float_as_uint(As[cur][rr][cc]);
                a[mt][1] = __float_as_uint(As[cur][rr+8][cc]);
                a[mt][2] = __float_as_uint(As[cur][rr][cc+4]);
                a[mt][3] = __float_as_uint(As[cur][rr+8][cc+4]);
            }
            #pragma unroll
            for (int nt = 0; nt < 4; nt++) {
                int bn = wn + nt*8 + lq;
                unsigned b0 = __float_as_uint(Bs[cur][ks*8+lr][bn]);
                unsigned b1 = __float_as_uint(Bs[cur][ks*8+lr+4][bn]);
                #pragma unroll
                for (int mt = 0; mt < 2; mt++)
                    mma_tf32(c[mt][nt], a[mt][0], a[mt][1], a[mt][2], a[mt][3], b0, b1);
            }
        }
        if (s < 15) {
            int nb = cur ^ 1;
            *(float4*)&As[nb][r0][c4] = av0;
            *(float4*)&As[nb][r0+64][c4] = av1;
            *(float4*)&Bs[nb][br][bc4] = bv;
        }
        __syncthreads();
    }
    #pragma unroll
    for (int mt = 0; mt < 2; mt++) {
        #pragma unroll
        for (int nt = 0; nt < 4; nt++) {
            int r = row0 + wm + mt*16 + lq;
            int cc = colbase + wn + nt*8 + lr*2;
            float b0v = bo[cc], b1v = bo[cc+1];
            float2 x0 = *(const float2*)&x[r * 256 + cc];
            float2 x1 = *(const float2*)&x[(r+8) * 256 + cc];
            *(float2*)&out[r * 256 + cc] =
                make_float2(c[mt][nt][0] + b0v + x0.x, c[mt][nt][1] + b1v + x0.y);
            *(float2*)&out[(r+8) * 256 + cc] =
                make_float2(c[mt][nt][2] + b0v + x1.x, c[mt][nt][3] + b1v + x1.y);
        }
    }
}

// ================= launcher =================
extern "C" void kernel_launch(void* const* d_in, const int* in_sizes, int n_in,
                              void* d_out, int out_size)
{
    const float* x   = (const float*)d_in[0];
    const float* bp  = (const float*)d_in[1];
    const float* Wk1 = (const float*)d_in[2];
    const float* bk1 = (const float*)d_in[3];
    const float* Wk2 = (const float*)d_in[4];
    const float* bk2 = (const float*)d_in[5];
    const float* Wq1 = (const float*)d_in[6];
    const float* bq1 = (const float*)d_in[7];
    const float* Wq2 = (const float*)d_in[8];
    const float* bq2 = (const float*)d_in[9];
    const float* Wvc = (const float*)d_in[10];
    const float* bvc = (const float*)d_in[11];
    const float* Wvp = (const float*)d_in[12];
    const float* bvp = (const float*)d_in[13];
    const float* Wg1 = (const float*)d_in[14];
    const float* bg1 = (const float*)d_in[15];
    const float* Wg2 = (const float*)d_in[16];
    const float* bg2 = (const float*)d_in[17];
    const float* lng = (const float*)d_in[18];
    const float* lnb = (const float*)d_in[19];
    const float* Wo  = (const float*)d_in[20];
    const float* bo  = (const float*)d_in[21];
    float* out = (float*)d_out;

    k1_mma<<<dim3(32, 17), 256>>>(x, Wk1, bk1, Wq1, bq1, Wvc, bvc, Wvp, bvp, Wg1, bg1);
    k23b_mma<<<160, 256>>>(Wk2, bk2, Wq2, bq2, Wg2, bg2, bp);
    k3a5_mma<<<96, 256>>>();
    k4_prefix<<<132, 256>>>();
    k6_mma<<<dim3(32, 4), 256>>>();
    k7_poscomb<<<512, 256>>>(bp, lng, lnb);
    k8_mma<<<dim3(32, 4), 256>>>(x, Wo, bo, out);
}

// round 11
// speedup vs baseline: 1.3030x; 1.0787x over previous
#include <cuda_runtime.h>
#include <cuda_bf16.h>
#include <math.h>

// Problem constants
#define Bb 2
#define LL 2048
#define DD 256
#define KK 32
#define FF 64          // 2*K feature dim
#define MM (Bb*LL)     // 4096 rows
#define CC 128         // chunk size
#define NC (LL/CC)     // 16 chunks per batch
#define PI_F 3.14159265358979323846f

// ---------------- scratch (device globals; no allocation allowed) ----------------
__device__ float g_hk[MM*DD];
__device__ float g_hq[MM*DD];
__device__ float g_vc[MM*DD];
__device__ float g_vp[MM*DD];
__device__ float g_g1[MM*64];
__device__ float g_kf[MM*FF];
__device__ float g_qf[MM*FF];
__device__ float g_gates[MM*2];
__device__ float g_S[Bb*NC*FF*DD];         // per-chunk content state sums (mma)
__device__ float g_P[Bb*NC*FF*DD];         // chunk-level exclusive prefix of states
__device__ float g_psnap[Bb*64*4*2*DD];    // pos accum snapshots every 8 rows (inclusive)
__device__ float g_pprefix[Bb*64*2*DD];    // exclusive prefix at 32-row granularity
__device__ float g_scores[Bb*NC*CC*CC];    // intra-chunk masked scores
__device__ float g_cont[MM*DD];
__device__ float g_norm[MM*DD];

// mma consumes raw f32 bit patterns as tf32 (HW truncates mantissa; no cvt needed)
__device__ __forceinline__ void mma_tf32(float c[4],
    unsigned a0, unsigned a1, unsigned a2, unsigned a3,
    unsigned b0, unsigned b1)
{
    asm volatile(
        "mma.sync.aligned.m16n8k8.row.col.f32.tf32.tf32.f32 "
        "{%0,%1,%2,%3}, {%4,%5,%6,%7}, {%8,%9}, {%0,%1,%2,%3};"
        : "+f"(c[0]), "+f"(c[1]), "+f"(c[2]), "+f"(c[3])
        : "r"(a0), "r"(a1), "r"(a2), "r"(a3), "r"(b0), "r"(b1));
}

// ---------------- cp.async helpers ----------------
__device__ __forceinline__ void cp_async16(void* smem_dst, const void* gsrc) {
    unsigned saddr = (unsigned)__cvta_generic_to_shared(smem_dst);
    asm volatile("cp.async.cg.shared.global [%0], [%1], 16;" :: "r"(saddr), "l"(gsrc));
}
__device__ __forceinline__ void cp_commit() {
    asm volatile("cp.async.commit_group;");
}
__device__ __forceinline__ void cp_wait1() {
    asm volatile("cp.async.wait_group 1;");
}
__device__ __forceinline__ void cp_wait0() {
    asm volatile("cp.async.wait_group 0;");
}

// ================= Kernel 1: fused first-layer GEMMs (3-stage cp.async) =============
// grid (32, 17): ct<16 -> [hk|hq|vc|vp] x 4 col-quarters; ct==16 -> g1
__global__ __launch_bounds__(256) void k1_mma(
    const float* __restrict__ x,
    const float* __restrict__ Wk1, const float* __restrict__ bk1,
    const float* __restrict__ Wq1, const float* __restrict__ bq1,
    const float* __restrict__ Wvc, const float* __restrict__ bvc,
    const float* __restrict__ Wvp, const float* __restrict__ bvp,
    const float* __restrict__ Wg1, const float* __restrict__ bg1)
{
    __shared__ float As[3][128][20];
    __shared__ float Bs[3][16][68];
    int ct = blockIdx.y;
    const float* W; const float* bias; float* outp; int Nseg; int act; int colbase;
    if (ct < 16) {
        int seg = ct >> 2;
        colbase = (ct & 3) * 64;
        Nseg = 256;
        if (seg == 0)      { W = Wk1; bias = bk1; outp = g_hk; act = 1; }
        else if (seg == 1) { W = Wq1; bias = bq1; outp = g_hq; act = 1; }
        else if (seg == 2) { W = Wvc; bias = bvc; outp = g_vc; act = 0; }
        else               { W = Wvp; bias = bvp; outp = g_vp; act = 0; }
    } else {
        W = Wg1; bias = bg1; outp = g_g1; Nseg = 64; act = 2; colbase = 0;
    }
    int row0 = blockIdx.x * 128;
    int tid = threadIdx.x;
    int w = tid >> 5, lane = tid & 31;
    int wm = (w & 3) * 32;
    int wn = (w >> 2) * 32;
    int lq = lane >> 2, lr = lane & 3;
    int r0 = tid >> 2, c4 = (tid & 3) * 4;
    int br = tid >> 4, bc4 = (tid & 15) * 4;
    float c[2][4][4] = {};

    // prefetch stages 0,1
    #pragma unroll
    for (int p = 0; p < 2; p++) {
        int k0 = p * 16;
        cp_async16(&As[p][r0][c4],    &x[(row0 + r0) * 256 + k0 + c4]);
        cp_async16(&As[p][r0+64][c4], &x[(row0 + r0 + 64) * 256 + k0 + c4]);
        cp_async16(&Bs[p][br][bc4],   &W[(k0 + br) * Nseg + colbase + bc4]);
        cp_commit();
    }

    for (int s = 0; s < 16; s++) {
        if (s < 15) cp_wait1(); else cp_wait0();
        __syncthreads();
        int cur = s % 3;
        #pragma unroll
        for (int ks = 0; ks < 2; ks++) {
            unsigned a[2][4];
            #pragma unroll
            for (int mt = 0; mt < 2; mt++) {
                int rr = wm + mt*16 + lq;
                int cc = ks*8 + lr;
                a[mt][0] = __float_as_uint(As[cur][rr][cc]);
                a[mt][1] = __float_as_uint(As[cur][rr+8][cc]);
                a[mt][2] = __float_as_uint(As[cur][rr][cc+4]);
                a[mt][3] = __float_as_uint(As[cur][rr+8][cc+4]);
            }
            #pragma unroll
            for (int nt = 0; nt < 4; nt++) {
                int bn = wn + nt*8 + lq;
                unsigned b0 = __float_as_uint(Bs[cur][ks*8+lr][bn]);
                unsigned b1 = __float_as_uint(Bs[cur][ks*8+lr+4][bn]);
                #pragma unroll
                for (int mt = 0; mt < 2; mt++)
                    mma_tf32(c[mt][nt], a[mt][0], a[mt][1], a[mt][2], a[mt][3], b0, b1);
            }
        }
        if (s < 14) {
            int st = (s + 2) % 3;
            int k0 = (s + 2) * 16;
            cp_async16(&As[st][r0][c4],    &x[(row0 + r0) * 256 + k0 + c4]);
            cp_async16(&As[st][r0+64][c4], &x[(row0 + r0 + 64) * 256 + k0 + c4]);
            cp_async16(&Bs[st][br][bc4],   &W[(k0 + br) * Nseg + colbase + bc4]);
            cp_commit();
        }
    }
    #pragma unroll
    for (int mt = 0; mt < 2; mt++) {
        #pragma unroll
        for (int nt = 0; nt < 4; nt++) {
            int r = row0 + wm + mt*16 + lq;
            int cc = colbase + wn + nt*8 + lr*2;
            float b0v = bias[cc], b1v = bias[cc+1];
            float v00 = c[mt][nt][0] + b0v, v01 = c[mt][nt][1] + b1v;
            float v10 = c[mt][nt][2] + b0v, v11 = c[mt][nt][3] + b1v;
            if (act == 1) { v00 = tanhf(v00); v01 = tanhf(v01); v10 = tanhf(v10); v11 = tanhf(v11); }
            else if (act == 2) { v00 = fmaxf(v00,0.f); v01 = fmaxf(v01,0.f); v10 = fmaxf(v10,0.f); v11 = fmaxf(v11,0.f); }
            *(float2*)&outp[r * Nseg + cc] = make_float2(v00, v01);
            *(float2*)&outp[(r+8) * Nseg + cc] = make_float2(v10, v11);
        }
    }
}

// ================= Kernel 2+3b merged: phase features + gates || pos partial sums =======
__global__ __launch_bounds__(256) void k23b_mma(
    const float* __restrict__ Wk2, const float* __restrict__ bk2,
    const float* __restrict__ Wq2, const float* __restrict__ bq2,
    const float* __restrict__ Wg2, const float* __restrict__ bg2,
    const float* __restrict__ base_phases)
{
    __shared__ float Ak[2][128][18];
    __shared__ float Aq[2][128][18];
    __shared__ float Bs[2][16][68];
    int tid = threadIdx.x;

    if (blockIdx.x >= 32) {
        int blk = blockIdx.x - 32;   // b*64 + s
        int row0 = (blk >> 6) * LL + (blk & 63) * 32;
        int l0 = (blk & 63) * 32;
        int d = tid;
        float par = 0.f, pai = 0.f;
        #pragma unroll
        for (int g = 0; g < 4; g++) {
            float vp8[8], ph8[8];
            #pragma unroll
            for (int j = 0; j < 8; j++) {
                vp8[j] = g_vp[(row0 + g*8 + j) * 256 + d];
                ph8[j] = base_phases[(l0 + g*8 + j) * 256 + d];
            }
            #pragma unroll
            for (int j = 0; j < 8; j++) {
                float sp, cp; __sincosf(ph8[j], &sp, &cp);
                par += vp8[j] * cp; pai += vp8[j] * sp;
            }
            int snapbase = (blk * 4 + g) * 512;
            g_psnap[snapbase + d] = par;
            g_psnap[snapbase + 256 + d] = pai;
        }
        return;
    }

    int w = tid >> 5, lane = tid & 31;
    int row0 = blockIdx.x * 128;
    int wm = (w & 3) * 32;
    bool isq = (w >= 4);
    int lq = lane >> 2, lr = lane & 3;
    int r0 = tid >> 2, c4 = (tid & 3) * 4;
    int br = tid >> 4, bc4 = (tid & 15) * 4;
    float c[2][4][4] = {};
    float4 ak0, ak1, aq0, aq1, bv;

    ak0 = *(const float4*)&g_hk[(row0 + r0) * 256 + c4];
    ak1 = *(const float4*)&g_hk[(row0 + r0 + 64) * 256 + c4];
    aq0 = *(const float4*)&g_hq[(row0 + r0) * 256 + c4];
    aq1 = *(const float4*)&g_hq[(row0 + r0 + 64) * 256 + c4];
    bv  = (bc4 < 32) ? *(const float4*)&Wk2[br * 32 + bc4]
                     : *(const float4*)&Wq2[br * 32 + bc4 - 32];
    *(float2*)&Ak[0][r0][c4]      = make_float2(ak0.x, ak0.y);
    *(float2*)&Ak[0][r0][c4+2]    = make_float2(ak0.z, ak0.w);
    *(float2*)&Ak[0][r0+64][c4]   = make_float2(ak1.x, ak1.y);
    *(float2*)&Ak[0][r0+64][c4+2] = make_float2(ak1.z, ak1.w);
    *(float2*)&Aq[0][r0][c4]      = make_float2(aq0.x, aq0.y);
    *(float2*)&Aq[0][r0][c4+2]    = make_float2(aq0.z, aq0.w);
    *(float2*)&Aq[0][r0+64][c4]   = make_float2(aq1.x, aq1.y);
    *(float2*)&Aq[0][r0+64][c4+2] = make_float2(aq1.z, aq1.w);
    *(float4*)&Bs[0][br][bc4] = bv;
    __syncthreads();

    for (int s = 0; s < 16; s++) {
        int cur = s & 1;
        if (s < 15) {
            int kn = (s + 1) * 16;
            ak0 = *(const float4*)&g_hk[(row0 + r0) * 256 + kn + c4];
            ak1 = *(const float4*)&g_hk[(row0 + r0 + 64) * 256 + kn + c4];
            aq0 = *(const float4*)&g_hq[(row0 + r0) * 256 + kn + c4];
            aq1 = *(const float4*)&g_hq[(row0 + r0 + 64) * 256 + kn + c4];
            bv  = (bc4 < 32) ? *(const float4*)&Wk2[(kn + br) * 32 + bc4]
                             : *(const float4*)&Wq2[(kn + br) * 32 + bc4 - 32];
        }
        const float (*A)[18] = isq ? Aq[cur] : Ak[cur];
        #pragma unroll
        for (int ks = 0; ks < 2; ks++) {
            unsigned a[2][4];
            #pragma unroll
            for (int mt = 0; mt < 2; mt++) {
                int rr = wm + mt*16 + lq;
                int cc = ks*8 + lr;
                a[mt][0] = __float_as_uint(A[rr][cc]);
                a[mt][1] = __float_as_uint(A[rr+8][cc]);
                a[mt][2] = __float_as_uint(A[rr][cc+4]);
                a[mt][3] = __float_as_uint(A[rr+8][cc+4]);
            }
            #pragma unroll
            for (int nt = 0; nt < 4; nt++) {
                int bn = (isq ? 32 : 0) + nt*8 + lq;
                unsigned b0 = __float_as_uint(Bs[cur][ks*8+lr][bn]);
                unsigned b1 = __float_as_uint(Bs[cur][ks*8+lr+4][bn]);
                #pragma unroll
                for (int mt = 0; mt < 2; mt++)
                    mma_tf32(c[mt][nt], a[mt][0], a[mt][1], a[mt][2], a[mt][3], b0, b1);
            }
        }
        if (s < 15) {
            int nb = cur ^ 1;
            *(float2*)&Ak[nb][r0][c4]      = make_float2(ak0.x, ak0.y);
            *(float2*)&Ak[nb][r0][c4+2]    = make_float2(ak0.z, ak0.w);
            *(float2*)&Ak[nb][r0+64][c4]   = make_float2(ak1.x, ak1.y);
            *(float2*)&Ak[nb][r0+64][c4+2] = make_float2(ak1.z, ak1.w);
            *(float2*)&Aq[nb][r0][c4]      = make_float2(aq0.x, aq0.y);
            *(float2*)&Aq[nb][r0][c4+2]    = make_float2(aq0.z, aq0.w);
            *(float2*)&Aq[nb][r0+64][c4]   = make_float2(aq1.x, aq1.y);
            *(float2*)&Aq[nb][r0+64][c4+2] = make_float2(aq1.z, aq1.w);
            *(float4*)&Bs[nb][br][bc4] = bv;
        }
        __syncthreads();
    }

    const float* bvec = isq ? bq2 : bk2;
    float* fdst = isq ? g_qf : g_kf;
    #pragma unroll
    for (int mt = 0; mt < 2; mt++) {
        #pragma unroll
        for (int nt = 0; nt < 4; nt++) {
            int r = row0 + wm + mt*16 + lq;
            int cn = nt*8 + lr*2;
            float b0v = bvec[cn], b1v = bvec[cn+1];
            float ph;
            float sp, cp;
            ph = tanhf(c[mt][nt][0] + b0v) * PI_F; __sincosf(ph, &sp, &cp);
            fdst[r*64 + cn] = cp; fdst[r*64 + 32 + cn] = sp;
            ph = tanhf(c[mt][nt][1] + b1v) * PI_F; __sincosf(ph, &sp, &cp);
            fdst[r*64 + cn+1] = cp; fdst[r*64 + 32 + cn+1] = sp;
            ph = tanhf(c[mt][nt][2] + b0v) * PI_F; __sincosf(ph, &sp, &cp);
            fdst[(r+8)*64 + cn] = cp; fdst[(r+8)*64 + 32 + cn] = sp;
            ph = tanhf(c[mt][nt][3] + b1v) * PI_F; __sincosf(ph, &sp, &cp);
            fdst[(r+8)*64 + cn+1] = cp; fdst[(r+8)*64 + 32 + cn+1] = sp;
        }
    }
    for (int rr = 0; rr < 16; rr++) {
        int r = row0 + w*16 + rr;
        float p0 = 0.f, p1 = 0.f;
        #pragma unroll
        for (int i = lane; i < 64; i += 32) {
            float gv = g_g1[r*64 + i];
            p0 += gv * Wg2[i*2 + 0];
            p1 += gv * Wg2[i*2 + 1];
        }
        #pragma unroll
        for (int off = 16; off; off >>= 1) {
            p0 += __shfl_xor_sync(~0u, p0, off);
            p1 += __shfl_xor_sync(~0u, p1, off);
        }
        if (lane == 0) {
            float l0 = p0 + bg2[0], l1 = p1 + bg2[1];
            float m = fmaxf(l0, l1);
            float e0 = __expf(l0 - m), e1 = __expf(l1 - m);
            float inv = 1.f / (e0 + e1);
            g_gates[r*2 + 0] = e0 * inv;
            g_gates[r*2 + 1] = e1 * inv;
        }
    }
}

// ================= Kernel 3a+5 merged: chunk states || masked scores =================
__global__ __launch_bounds__(256) void k3a5_mma()
{
    __shared__ float sraw[10240];
    int tid = threadIdx.x;
    int w = tid >> 5, lane = tid & 31;
    int lq = lane >> 2, lr = lane & 3;

    if (blockIdx.x < 64) {
        float (*Kl)[16][68]  = (float(*)[16][68])sraw;
        float (*Bs)[16][132] = (float(*)[16][132])(sraw + 2176);
        int bc = blockIdx.x & 31;
        int b = bc >> 4, c = bc & 15;
        int d0 = (blockIdx.x >> 5) * 128;
        int row0 = b * LL + c * CC;
        int wm = (w & 1) * 32, wn = (w >> 1) * 32;
        int af4 = (tid & 15) * 4, al = tid >> 4;
        int rB = tid >> 5, cB = (tid & 31) * 4;
        float acc[2][4][4] = {};
        float4 av, bv0, bv1;

        av  = *(const float4*)&g_kf[(row0 + al) * 64 + af4];
        bv0 = *(const float4*)&g_vc[(row0 + rB) * 256 + d0 + cB];
        bv1 = *(const float4*)&g_vc[(row0 + rB + 8) * 256 + d0 + cB];
        *(float4*)&Kl[0][al][af4] = av;
        *(float4*)&Bs[0][rB][cB] = bv0;
        *(float4*)&Bs[0][rB+8][cB] = bv1;
        __syncthreads();

        for (int s = 0; s < 8; s++) {
            int cur = s & 1;
            if (s < 7) {
                int kn = (s + 1) * 16;
                av  = *(const float4*)&g_kf[(row0 + kn + al) * 64 + af4];
                bv0 = *(const float4*)&g_vc[(row0 + kn + rB) * 256 + d0 + cB];
                bv1 = *(const float4*)&g_vc[(row0 + kn + rB + 8) * 256 + d0 + cB];
            }
            #pragma unroll
            for (int ks = 0; ks < 2; ks++) {
                unsigned a[2][4];
                #pragma unroll
                for (int mt = 0; mt < 2; mt++) {
                    int rr = wm + mt*16 + lq;
                    int cc = ks*8 + lr;
                    a[mt][0] = __float_as_uint(Kl[cur][cc][rr]);
                    a[mt][1] = __float_as_uint(Kl[cur][cc][rr+8]);
                    a[mt][2] = __float_as_uint(Kl[cur][cc+4][rr]);
                    a[mt][3] = __float_as_uint(Kl[cur][cc+4][rr+8]);
                }
                #pragma unroll
                for (int nt = 0; nt < 4; nt++) {
                    int bn = wn + nt*8 + lq;
                    unsigned b0 = __float_as_uint(Bs[cur][ks*8+lr][bn]);
                    unsigned b1 = __float_as_uint(Bs[cur][ks*8+lr+4][bn]);
                    #pragma unroll
                    for (int mt = 0; mt < 2; mt++)
                        mma_tf32(acc[mt][nt], a[mt][0], a[mt][1], a[mt][2], a[mt][3], b0, b1);
                }
            }
            if (s < 7) {
                int nb = cur ^ 1;
                *(float4*)&Kl[nb][al][af4] = av;
                *(float4*)&Bs[nb][rB][cB] = bv0;
                *(float4*)&Bs[nb][rB+8][cB] = bv1;
            }
            __syncthreads();
        }
        int base = bc * 64 * 256;
        #pragma unroll
        for (int mt = 0; mt < 2; mt++) {
            #pragma unroll
            for (int nt = 0; nt < 4; nt++) {
                int f = wm + mt*16 + lq;
                int dd = d0 + wn + nt*8 + lr*2;
                *(float2*)&g_S[base + f * 256 + dd] = make_float2(acc[mt][nt][0], acc[mt][nt][1]);
                *(float2*)&g_S[base + (f+8) * 256 + dd] = make_float2(acc[mt][nt][2], acc[mt][nt][3]);
            }
        }
        return;
    }

    {
        float (*As)[128][20] = (float(*)[128][20])sraw;
        float (*Ks)[128][20] = (float(*)[128][20])(sraw + 5120);
        int bc = blockIdx.x - 64;
        int b = bc >> 4, c = bc & 15;
        int row0 = b * LL + c * CC;
        int wm = (w & 3) * 32;
        int wn = (w >> 2) * 64;
        int r0 = tid >> 2, c4 = (tid & 3) * 4;
        float acc[2][8][4] = {};
        float4 a0v, a1v, u0, u1;

        a0v = *(const float4*)&g_qf[(row0 + r0) * 64 + c4];
        a1v = *(const float4*)&g_qf[(row0 + r0 + 64) * 64 + c4];
        u0  = *(const float4*)&g_kf[(row0 + r0) * 64 + c4];
        u1  = *(const float4*)&g_kf[(row0 + r0 + 64) * 64 + c4];
        *(float4*)&As[0][r0][c4] = a0v;
        *(float4*)&As[0][r0+64][c4] = a1v;
        *(float4*)&Ks[0][r0][c4] = u0;
        *(float4*)&Ks[0][r0+64][c4] = u1;
        __syncthreads();

        for (int s = 0; s < 4; s++) {
            int cur = s & 1;
            if (s < 3) {
                int kn = (s + 1) * 16;
                a0v = *(const float4*)&g_qf[(row0 + r0) * 64 + kn + c4];
                a1v = *(const float4*)&g_qf[(row0 + r0 + 64) * 64 + kn + c4];
                u0  = *(const float4*)&g_kf[(row0 + r0) * 64 + kn + c4];
                u1  = *(const float4*)&g_kf[(row0 + r0 + 64) * 64 + kn + c4];
            }
            #pragma unroll
            for (int ks = 0; ks < 2; ks++) {
                unsigned a[2][4];
                #pragma unroll
                for (int mt = 0; mt < 2; mt++) {
                    int rr = wm + mt*16 + lq;
                    int cc = ks*8 + lr;
                    a[mt][0] = __float_as_uint(As[cur][rr][cc]);
                    a[mt][1] = __float_as_uint(As[cur][rr+8][cc]);
                    a[mt][2] = __float_as_uint(As[cur][rr][cc+4]);
                    a[mt][3] = __float_as_uint(As[cur][rr+8][cc+4]);
                }
                #pragma unroll
                for (int nt = 0; nt < 8; nt++) {
                    int bn = wn + nt*8 + lq;
                    unsigned b0 = __float_as_uint(Ks[cur][bn][ks*8+lr]);
                    unsigned b1 = __float_as_uint(Ks[cur][bn][ks*8+lr+4]);
                    #pragma unroll
                    for (int mt = 0; mt < 2; mt++)
                        mma_tf32(acc[mt][nt], a[mt][0], a[mt][1], a[mt][2], a[mt][3], b0, b1);
                }
            }
            if (s < 3) {
                int nb = cur ^ 1;
                *(float4*)&As[nb][r0][c4] = a0v;
                *(float4*)&As[nb][r0+64][c4] = a1v;
                *(float4*)&Ks[nb][r0][c4] = u0;
                *(float4*)&Ks[nb][r0+64][c4] = u1;
            }
            __syncthreads();
        }
        int sb = bc * CC * CC;
        #pragma unroll
        for (int mt = 0; mt < 2; mt++) {
            #pragma unroll
            for (int nt = 0; nt < 8; nt++) {
                int la = wm + mt*16 + lq;
                int lb = la + 8;
                int j0 = wn + nt*8 + lr*2;
                int j1 = j0 + 1;
                *(float2*)&g_scores[sb + la*128 + j0] =
                    make_float2(j0 <= la ? acc[mt][nt][0] : 0.f, j1 <= la ? acc[mt][nt][1] : 0.f);
                *(float2*)&g_scores[sb + lb*128 + j0] =
                    make_float2(j0 <= lb ? acc[mt][nt][2] : 0.f, j1 <= lb ? acc[mt][nt][3] : 0.f);
            }
        }
    }
}

// ================= Kernel 4: exclusive prefixes (front-batched loads) =================
__global__ __launch_bounds__(256) void k4_prefix()
{
    int tid = threadIdx.x;
    if (blockIdx.x < 128) {
        int idx = blockIdx.x * 256 + tid;
        int b = idx >> 14, rd = idx & 16383;
        float v[16];
        #pragma unroll
        for (int c = 0; c < 16; c++)
            v[c] = g_S[(b * 16 + c) * 16384 + rd];
        float run = 0.f;
        #pragma unroll
        for (int c = 0; c < 16; c++) {
            g_P[(b * 16 + c) * 16384 + rd] = run;
            run += v[c];
        }
    } else {
        int e = (blockIdx.x - 128) * 256 + tid;
        if (e < 1024) {
            int b = e >> 9, rd = e & 511;
            float v[64];
            #pragma unroll
            for (int s = 0; s < 64; s++)
                v[s] = g_psnap[((b * 64 + s) * 4 + 3) * 512 + rd];
            float run = 0.f;
            #pragma unroll
            for (int s = 0; s < 64; s++) {
                g_pprefix[(b * 64 + s) * 512 + rd] = run;
                run += v[s];
            }
        }
    }
}

// ================= Kernel 6: content output (3-stage cp.async) =================
__global__ __launch_bounds__(256) void k6_mma()
{
    __shared__ float As[3][128][20];
    __shared__ float Bs[3][16][68];
    int bc = blockIdx.x; int b = bc >> 4, c = bc & 15;
    int d0 = blockIdx.y * 64;
    int row0 = b * LL + c * CC;
    int tid = threadIdx.x;
    int w = tid >> 5, lane = tid & 31;
    int wm = (w & 3) * 32;
    int wn = (w >> 2) * 32;
    int lq = lane >> 2, lr = lane & 3;
    int r0 = tid >> 2, c4 = (tid & 3) * 4;
    int br = tid >> 4, bc4 = (tid & 15) * 4;
    int Pbase = bc * 64 * 256;
    int sbase = bc * CC * CC;
    float acc[2][4][4] = {};

    #pragma unroll
    for (int p = 0; p < 2; p++) {
        int k0 = p * 16;
        int kga = k0 + c4;
        const float *sa0, *sa1;
        if (kga < 64) {
            sa0 = &g_qf[(row0 + r0) * 64 + kga];
            sa1 = &g_qf[(row0 + r0 + 64) * 64 + kga];
        } else {
            sa0 = &g_scores[sbase + r0 * 128 + kga - 64];
            sa1 = &g_scores[sbase + (r0 + 64) * 128 + kga - 64];
        }
        int kgb = k0 + br;
        const float* sbp = (kgb < 64) ? &g_P[Pbase + kgb * 256 + d0 + bc4]
                                      : &g_vc[(row0 + kgb - 64) * 256 + d0 + bc4];
        cp_async16(&As[p][r0][c4], sa0);
        cp_async16(&As[p][r0+64][c4], sa1);
        cp_async16(&Bs[p][br][bc4], sbp);
        cp_commit();
    }

    for (int s = 0; s < 12; s++) {
        if (s < 11) cp_wait1(); else cp_wait0();
        __syncthreads();
        int cur = s % 3;
        #pragma unroll
        for (int ks = 0; ks < 2; ks++) {
            unsigned a[2][4];
            #pragma unroll
            for (int mt = 0; mt < 2; mt++) {
                int rr = wm + mt*16 + lq;
                int cc = ks*8 + lr;
                a[mt][0] = __float_as_uint(As[cur][rr][cc]);
                a[mt][1] = __float_as_uint(As[cur][rr+8][cc]);
                a[mt][2] = __float_as_uint(As[cur][rr][cc+4]);
                a[mt][3] = __float_as_uint(As[cur][rr+8][cc+4]);
            }
            #pragma unroll
            for (int nt = 0; nt < 4; nt++) {
                int bn = wn + nt*8 + lq;
                unsigned b0 = __float_as_uint(Bs[cur][ks*8+lr][bn]);
                unsigned b1 = __float_as_uint(Bs[cur][ks*8+lr+4][bn]);
                #pragma unroll
                for (int mt = 0; mt < 2; mt++)
                    mma_tf32(acc[mt][nt], a[mt][0], a[mt][1], a[mt][2], a[mt][3], b0, b1);
            }
        }
        if (s < 10) {
            int st = (s + 2) % 3;
            int k0 = (s + 2) * 16;
            int kga = k0 + c4;
            const float *sa0, *sa1;
            if (kga < 64) {
                sa0 = &g_qf[(row0 + r0) * 64 + kga];
                sa1 = &g_qf[(row0 + r0 + 64) * 64 + kga];
            } else {
                sa0 = &g_scores[sbase + r0 * 128 + kga - 64];
                sa1 = &g_scores[sbase + (r0 + 64) * 128 + kga - 64];
            }
            int kgb = k0 + br;
            const float* sbp = (kgb < 64) ? &g_P[Pbase + kgb * 256 + d0 + bc4]
                                          : &g_vc[(row0 + kgb - 64) * 256 + d0 + bc4];
            cp_async16(&As[st][r0][c4], sa0);
            cp_async16(&As[st][r0+64][c4], sa1);
            cp_async16(&Bs[st][br][bc4], sbp);
            cp_commit();
        }
    }
    #pragma unroll
    for (int mt = 0; mt < 2; mt++) {
        #pragma unroll
        for (int nt = 0; nt < 4; nt++) {
            int la = wm + mt*16 + lq;
            int lb = la + 8;
            int cc = d0 + wn + nt*8 + lr*2;
            float sa = rsqrtf((float)((c*CC + la + 1) * KK));
            float sb2 = rsqrtf((float)((c*CC + lb + 1) * KK));
            *(float2*)&g_cont[(row0 + la) * 256 + cc] =
                make_float2(acc[mt][nt][0] * sa, acc[mt][nt][1] * sa);
            *(float2*)&g_cont[(row0 + lb) * 256 + cc] =
                make_float2(acc[mt][nt][2] * sb2, acc[mt][nt][3] * sb2);
        }
    }
}

// ================= Kernel 7: pos scan (8 rows/block) + gate combine + LayerNorm =========
__global__ __launch_bounds__(256) void k7_poscomb(
    const float* __restrict__ base_phases,
    const float* __restrict__ ln_g, const float* __restrict__ ln_b)
{
    __shared__ float comb[8][257];
    int blk = blockIdx.x;
    int j = blk & 3;
    int s = (blk >> 2) & 63;
    int b = blk >> 8;
    int row0 = b * LL + s * 32 + j * 8;
    int l0 = s * 32 + j * 8;
    int d = threadIdx.x;
    float ar = g_pprefix[(b * 64 + s) * 512 + d];
    float ai = g_pprefix[(b * 64 + s) * 512 + 256 + d];
    if (j > 0) {
        int snapbase = ((b * 64 + s) * 4 + j - 1) * 512;
        ar += g_psnap[snapbase + d];
        ai += g_psnap[snapbase + 256 + d];
    }
    float vp[8], ph[8], cv[8];
    #pragma unroll
    for (int lt = 0; lt < 8; lt++) {
        vp[lt] = g_vp[(row0 + lt) * 256 + d];
        ph[lt] = base_phases[(l0 + lt) * 256 + d];
        cv[lt] = g_cont[(row0 + lt) * 256 + d];
    }
    #pragma unroll
    for (int lt = 0; lt < 8; lt++) {
        float sp, cp; __sincosf(ph[lt], &sp, &cp);
        ar += vp[lt] * cp; ai += vp[lt] * sp;
        float pret = (ar * cp + ai * sp) * rsqrtf((float)(l0 + lt + 1));
        float g0 = g_gates[(row0 + lt) * 2], g1v = g_gates[(row0 + lt) * 2 + 1];
        comb[lt][d] = g0 * pret + g1v * cv[lt];
    }
    __syncthreads();
    int w = d >> 5, lane = d & 31;
    int r = row0 + w;
    float vals[8]; float s1 = 0.f, s2 = 0.f;
    #pragma unroll
    for (int k = 0; k < 8; k++) {
        float v = comb[w][lane + 32*k];
        vals[k] = v; s1 += v; s2 += v*v;
    }
    #pragma unroll
    for (int off = 16; off; off >>= 1) {
        s1 += __shfl_xor_sync(~0u, s1, off);
        s2 += __shfl_xor_sync(~0u, s2, off);
    }
    float mu = s1 * (1.f/256.f);
    float var = s2 * (1.f/256.f) - mu*mu;
    float rstd = rsqrtf(var + 1e-5f);
    #pragma unroll
    for (int k = 0; k < 8; k++) {
        int dd = lane + 32*k;
        g_norm[r*256 + dd] = (vals[k] - mu) * rstd * ln_g[dd] + ln_b[dd];
    }
}

// ================= Kernel 8: out = x + normed @ Wo + bo (3-stage cp.async) ============
__global__ __launch_bounds__(256) void k8_mma(
    const float* __restrict__ x, const float* __restrict__ Wo,
    const float* __restrict__ bo, float* __restrict__ out)
{
    __shared__ float As[3][128][20];
    __shared__ float Bs[3][16][68];
    int row0 = blockIdx.x * 128;
    int colbase = blockIdx.y * 64;
    int tid = threadIdx.x;
    int w = tid >> 5, lane = tid & 31;
    int wm = (w & 3) * 32;
    int wn = (w >> 2) * 32;
    int lq = lane >> 2, lr = lane & 3;
    int r0 = tid >> 2, c4 = (tid & 3) * 4;
    int br = tid >> 4, bc4 = (tid & 15) * 4;
    float c[2][4][4] = {};

    #pragma unroll
    for (int p = 0; p < 2; p++) {
        int k0 = p * 16;
        cp_async16(&As[p][r0][c4],    &g_norm[(row0 + r0) * 256 + k0 + c4]);
        cp_async16(&As[p][r0+64][c4], &g_norm[(row0 + r0 + 64) * 256 + k0 + c4]);
        cp_async16(&Bs[p][br][bc4],   &Wo[(k0 + br) * 256 + colbase + bc4]);
        cp_commit();
    }

    for (int s = 0; s < 16; s++) {
        if (s < 15) cp_wait1(); else cp_wait0();
        __syncthreads();
        int cur = s % 3;
        #pragma unroll
        for (int ks = 0; ks < 2; ks++) {
            unsigned a[2][4];
            #pragma unroll
            for (int mt = 0; mt < 2; mt++) {
                int rr = wm + mt*16 + lq;
                int cc = ks*8 + lr;
                a[mt][0] = __float_as_uint(As[cur][rr][cc]);
                a[mt][1] = __float_as_uint(As[cur][rr+8][cc]);
                a[mt][2] = __float_as_uint(As[cur][rr][cc+4]);
                a[mt][3] = __float_as_uint(As[cur][rr+8][cc+4]);
            }
            #pragma unroll
            for (int nt = 0; nt < 4; nt++) {
                int bn = wn + nt*8 + lq;
                unsigned b0 = __float_as_uint(Bs[cur][ks*8+lr][bn]);
                unsigned b1 = __float_as_uint(Bs[cur][ks*8+lr+4][bn]);
                #pragma unroll
                for (int mt = 0; mt < 2; mt++)
                    mma_tf32(c[mt][nt], a[mt][0], a[mt][1], a[mt][2], a[mt][3], b0, b1);
            }
        }
        if (s < 14) {
            int st = (s + 2) % 3;
            int k0 = (s + 2) * 16;
            cp_async16(&As[st][r0][c4],    &g_norm[(row0 + r0) * 256 + k0 + c4]);
            cp_async16(&As[st][r0+64][c4], &g_norm[(row0 + r0 + 64) * 256 + k0 + c4]);
            cp_async16(&Bs[st][br][bc4],   &Wo[(k0 + br) * 256 + colbase + bc4]);
            cp_commit();
        }
    }
    #pragma unroll
    for (int mt = 0; mt < 2; mt++) {
        #pragma unroll
        for (int nt = 0; nt < 4; nt++) {
            int r = row0 + wm + mt*16 + lq;
            int cc = colbase + wn + nt*8 + lr*2;
            float b0v = bo[cc], b1v = bo[cc+1];
            float2 x0 = *(const float2*)&x[r * 256 + cc];
            float2 x1 = *(const float2*)&x[(r+8) * 256 + cc];
            *(float2*)&out[r * 256 + cc] =
                make_float2(c[mt][nt][0] + b0v + x0.x, c[mt][nt][1] + b1v + x0.y);
            *(float2*)&out[(r+8) * 256 + cc] =
                make_float2(c[mt][nt][2] + b0v + x1.x, c[mt][nt][3] + b1v + x1.y);
        }
    }
}

// ================= launcher =================
extern "C" void kernel_launch(void* const* d_in, const int* in_sizes, int n_in,
                              void* d_out, int out_size)
{
    const float* x   = (const float*)d_in[0];
    const float* bp  = (const float*)d_in[1];
    const float* Wk1 = (const float*)d_in[2];
    const float* bk1 = (const float*)d_in[3];
    const float* Wk2 = (const float*)d_in[4];
    const float* bk2 = (const float*)d_in[5];
    const float* Wq1 = (const float*)d_in[6];
    const float* bq1 = (const float*)d_in[7];
    const float* Wq2 = (const float*)d_in[8];
    const float* bq2 = (const float*)d_in[9];
    const float* Wvc = (const float*)d_in[10];
    const float* bvc = (const float*)d_in[11];
    const float* Wvp = (const float*)d_in[12];
    const float* bvp = (const float*)d_in[13];
    const float* Wg1 = (const float*)d_in[14];
    const float* bg1 = (const float*)d_in[15];
    const float* Wg2 = (const float*)d_in[16];
    const float* bg2 = (const float*)d_in[17];
    const float* lng = (const float*)d_in[18];
    const float* lnb = (const float*)d_in[19];
    const float* Wo  = (const float*)d_in[20];
    const float* bo  = (const float*)d_in[21];
    float* out = (float*)d_out;

    k1_mma<<<dim3(32, 17), 256>>>(x, Wk1, bk1, Wq1, bq1, Wvc, bvc, Wvp, bvp, Wg1, bg1);
    k23b_mma<<<160, 256>>>(Wk2, bk2, Wq2, bq2, Wg2, bg2, bp);
    k3a5_mma<<<96, 256>>>();
    k4_prefix<<<132, 256>>>();
    k6_mma<<<dim3(32, 4), 256>>>();
    k7_poscomb<<<512, 256>>>(bp, lng, lnb);
    k8_mma<<<dim3(32, 4), 256>>>(x, Wo, bo, out);
}

// round 12
// speedup vs baseline: 1.4479x; 1.1112x over previous
#include <cuda_runtime.h>
#include <cuda_bf16.h>
#include <math.h>

// Problem constants
#define Bb 2
#define LL 2048
#define DD 256
#define KK 32
#define FF 64          // 2*K feature dim
#define MM (Bb*LL)     // 4096 rows
#define CC 128         // chunk size
#define NC (LL/CC)     // 16 chunks per batch
#define PI_F 3.14159265358979323846f

// ---------------- scratch (device globals; no allocation allowed) ----------------
__device__ float g_hk[MM*DD];
__device__ float g_hq[MM*DD];
__device__ float g_vc[MM*DD];
__device__ float g_vp[MM*DD];
__device__ float g_g1[MM*64];
__device__ float g_kf[MM*FF];
__device__ float g_qf[MM*FF];
__device__ float g_gates[MM*2];
__device__ float g_S[Bb*NC*FF*DD];         // per-chunk content state sums (mma)
__device__ float g_P[Bb*NC*FF*DD];         // chunk-level exclusive prefix of states
__device__ float g_psnap[Bb*64*4*2*DD];    // pos accum snapshots every 8 rows (inclusive)
__device__ float g_pprefix[Bb*64*2*DD];    // exclusive prefix at 32-row granularity
__device__ float g_scores[Bb*NC*CC*CC];    // intra-chunk masked scores
__device__ float g_cont[MM*DD];
__device__ float g_norm[MM*DD];

// mma consumes raw f32 bit patterns as tf32 (HW truncates mantissa; no cvt needed)
__device__ __forceinline__ void mma_tf32(float c[4],
    unsigned a0, unsigned a1, unsigned a2, unsigned a3,
    unsigned b0, unsigned b1)
{
    asm volatile(
        "mma.sync.aligned.m16n8k8.row.col.f32.tf32.tf32.f32 "
        "{%0,%1,%2,%3}, {%4,%5,%6,%7}, {%8,%9}, {%0,%1,%2,%3};"
        : "+f"(c[0]), "+f"(c[1]), "+f"(c[2]), "+f"(c[3])
        : "r"(a0), "r"(a1), "r"(a2), "r"(a3), "r"(b0), "r"(b1));
}

// ---------------- cp.async helpers ----------------
__device__ __forceinline__ void cp_async16(void* smem_dst, const void* gsrc) {
    unsigned saddr = (unsigned)__cvta_generic_to_shared(smem_dst);
    asm volatile("cp.async.cg.shared.global [%0], [%1], 16;" :: "r"(saddr), "l"(gsrc));
}
__device__ __forceinline__ void cp_commit() {
    asm volatile("cp.async.commit_group;");
}
__device__ __forceinline__ void cp_wait1() {
    asm volatile("cp.async.wait_group 1;");
}
__device__ __forceinline__ void cp_wait0() {
    asm volatile("cp.async.wait_group 0;");
}

// ================= Kernel 1: fused first-layer GEMMs (3-stage cp.async) =============
// grid (32, 17): ct<16 -> [hk|hq|vc|vp] x 4 col-quarters; ct==16 -> g1
__global__ __launch_bounds__(256) void k1_mma(
    const float* __restrict__ x,
    const float* __restrict__ Wk1, const float* __restrict__ bk1,
    const float* __restrict__ Wq1, const float* __restrict__ bq1,
    const float* __restrict__ Wvc, const float* __restrict__ bvc,
    const float* __restrict__ Wvp, const float* __restrict__ bvp,
    const float* __restrict__ Wg1, const float* __restrict__ bg1)
{
    __shared__ __align__(16) float As[3][128][20];
    __shared__ __align__(16) float Bs[3][16][68];
    int ct = blockIdx.y;
    const float* W; const float* bias; float* outp; int Nseg; int act; int colbase;
    if (ct < 16) {
        int seg = ct >> 2;
        colbase = (ct & 3) * 64;
        Nseg = 256;
        if (seg == 0)      { W = Wk1; bias = bk1; outp = g_hk; act = 1; }
        else if (seg == 1) { W = Wq1; bias = bq1; outp = g_hq; act = 1; }
        else if (seg == 2) { W = Wvc; bias = bvc; outp = g_vc; act = 0; }
        else               { W = Wvp; bias = bvp; outp = g_vp; act = 0; }
    } else {
        W = Wg1; bias = bg1; outp = g_g1; Nseg = 64; act = 2; colbase = 0;
    }
    int row0 = blockIdx.x * 128;
    int tid = threadIdx.x;
    int w = tid >> 5, lane = tid & 31;
    int wm = (w & 3) * 32;
    int wn = (w >> 2) * 32;
    int lq = lane >> 2, lr = lane & 3;
    int r0 = tid >> 2, c4 = (tid & 3) * 4;
    int br = tid >> 4, bc4 = (tid & 15) * 4;
    float c[2][4][4] = {};

    #pragma unroll
    for (int p = 0; p < 2; p++) {
        int k0 = p * 16;
        cp_async16(&As[p][r0][c4],    &x[(row0 + r0) * 256 + k0 + c4]);
        cp_async16(&As[p][r0+64][c4], &x[(row0 + r0 + 64) * 256 + k0 + c4]);
        cp_async16(&Bs[p][br][bc4],   &W[(k0 + br) * Nseg + colbase + bc4]);
        cp_commit();
    }

    for (int s = 0; s < 16; s++) {
        if (s < 15) cp_wait1(); else cp_wait0();
        __syncthreads();
        int cur = s % 3;
        #pragma unroll
        for (int ks = 0; ks < 2; ks++) {
            unsigned a[2][4];
            #pragma unroll
            for (int mt = 0; mt < 2; mt++) {
                int rr = wm + mt*16 + lq;
                int cc = ks*8 + lr;
                a[mt][0] = __float_as_uint(As[cur][rr][cc]);
                a[mt][1] = __float_as_uint(As[cur][rr+8][cc]);
                a[mt][2] = __float_as_uint(As[cur][rr][cc+4]);
                a[mt][3] = __float_as_uint(As[cur][rr+8][cc+4]);
            }
            #pragma unroll
            for (int nt = 0; nt < 4; nt++) {
                int bn = wn + nt*8 + lq;
                unsigned b0 = __float_as_uint(Bs[cur][ks*8+lr][bn]);
                unsigned b1 = __float_as_uint(Bs[cur][ks*8+lr+4][bn]);
                #pragma unroll
                for (int mt = 0; mt < 2; mt++)
                    mma_tf32(c[mt][nt], a[mt][0], a[mt][1], a[mt][2], a[mt][3], b0, b1);
            }
        }
        if (s < 14) {
            int st = (s + 2) % 3;
            int k0 = (s + 2) * 16;
            cp_async16(&As[st][r0][c4],    &x[(row0 + r0) * 256 + k0 + c4]);
            cp_async16(&As[st][r0+64][c4], &x[(row0 + r0 + 64) * 256 + k0 + c4]);
            cp_async16(&Bs[st][br][bc4],   &W[(k0 + br) * Nseg + colbase + bc4]);
            cp_commit();
        }
    }
    #pragma unroll
    for (int mt = 0; mt < 2; mt++) {
        #pragma unroll
        for (int nt = 0; nt < 4; nt++) {
            int r = row0 + wm + mt*16 + lq;
            int cc = colbase + wn + nt*8 + lr*2;
            float b0v = bias[cc], b1v = bias[cc+1];
            float v00 = c[mt][nt][0] + b0v, v01 = c[mt][nt][1] + b1v;
            float v10 = c[mt][nt][2] + b0v, v11 = c[mt][nt][3] + b1v;
            if (act == 1) { v00 = tanhf(v00); v01 = tanhf(v01); v10 = tanhf(v10); v11 = tanhf(v11); }
            else if (act == 2) { v00 = fmaxf(v00,0.f); v01 = fmaxf(v01,0.f); v10 = fmaxf(v10,0.f); v11 = fmaxf(v11,0.f); }
            *(float2*)&outp[r * Nseg + cc] = make_float2(v00, v01);
            *(float2*)&outp[(r+8) * Nseg + cc] = make_float2(v10, v11);
        }
    }
}

// ===== Kernel 2+3b merged: split phase GEMMs (3-stage cp.async) || pos front-batch ====
// blocks [0,32): k-path GEMM + gates; [32,64): q-path GEMM; [64,192): pos partials.
__global__ __launch_bounds__(256) void k23b_mma(
    const float* __restrict__ Wk2, const float* __restrict__ bk2,
    const float* __restrict__ Wq2, const float* __restrict__ bq2,
    const float* __restrict__ Wg2, const float* __restrict__ bg2,
    const float* __restrict__ base_phases)
{
    __shared__ __align__(16) float As[3][128][20];
    __shared__ __align__(16) float Bs[3][16][36];
    int tid = threadIdx.x;
    int bx = blockIdx.x;

    if (bx >= 64) {
        // ---- pos partial sums, fully front-batched (MLP 64) ----
        int blk = bx - 64;   // b*64 + s
        int row0 = (blk >> 6) * LL + (blk & 63) * 32;
        int l0 = (blk & 63) * 32;
        int d = tid;
        float vp[32], ph[32];
        #pragma unroll
        for (int j = 0; j < 32; j++) {
            vp[j] = g_vp[(row0 + j) * 256 + d];
            ph[j] = base_phases[(l0 + j) * 256 + d];
        }
        float par = 0.f, pai = 0.f;
        #pragma unroll
        for (int g = 0; g < 4; g++) {
            #pragma unroll
            for (int j = 0; j < 8; j++) {
                int idx = g*8 + j;
                float sp, cp; __sincosf(ph[idx], &sp, &cp);
                par += vp[idx] * cp; pai += vp[idx] * sp;
            }
            int snapbase = (blk * 4 + g) * 512;
            g_psnap[snapbase + d] = par;
            g_psnap[snapbase + 256 + d] = pai;
        }
        return;
    }

    // ---- phase-feature GEMM: one path per block ----
    bool isq = (bx >= 32);
    int row0 = (bx & 31) * 128;
    const float* H  = isq ? g_hq : g_hk;
    const float* W2 = isq ? Wq2 : Wk2;
    const float* bvec = isq ? bq2 : bk2;
    float* fdst = isq ? g_qf : g_kf;

    int w = tid >> 5, lane = tid & 31;
    int wm = (w & 3) * 32;
    int wn = (w >> 2) * 16;
    int lq = lane >> 2, lr = lane & 3;
    int r0 = tid >> 2, c4 = (tid & 3) * 4;
    int brB = tid >> 3, bc4B = (tid & 7) * 4;   // valid for tid < 128
    float c[2][2][4] = {};

    #pragma unroll
    for (int p = 0; p < 2; p++) {
        int k0 = p * 16;
        cp_async16(&As[p][r0][c4],    &H[(row0 + r0) * 256 + k0 + c4]);
        cp_async16(&As[p][r0+64][c4], &H[(row0 + r0 + 64) * 256 + k0 + c4]);
        if (tid < 128)
            cp_async16(&Bs[p][brB][bc4B], &W2[(k0 + brB) * 32 + bc4B]);
        cp_commit();
    }

    for (int s = 0; s < 16; s++) {
        if (s < 15) cp_wait1(); else cp_wait0();
        __syncthreads();
        int cur = s % 3;
        #pragma unroll
        for (int ks = 0; ks < 2; ks++) {
            unsigned a[2][4];
            #pragma unroll
            for (int mt = 0; mt < 2; mt++) {
                int rr = wm + mt*16 + lq;
                int cc = ks*8 + lr;
                a[mt][0] = __float_as_uint(As[cur][rr][cc]);
                a[mt][1] = __float_as_uint(As[cur][rr+8][cc]);
                a[mt][2] = __float_as_uint(As[cur][rr][cc+4]);
                a[mt][3] = __float_as_uint(As[cur][rr+8][cc+4]);
            }
            #pragma unroll
            for (int nt = 0; nt < 2; nt++) {
                int bn = wn + nt*8 + lq;
                unsigned b0 = __float_as_uint(Bs[cur][ks*8+lr][bn]);
                unsigned b1 = __float_as_uint(Bs[cur][ks*8+lr+4][bn]);
                #pragma unroll
                for (int mt = 0; mt < 2; mt++)
                    mma_tf32(c[mt][nt], a[mt][0], a[mt][1], a[mt][2], a[mt][3], b0, b1);
            }
        }
        if (s < 14) {
            int st = (s + 2) % 3;
            int k0 = (s + 2) * 16;
            cp_async16(&As[st][r0][c4],    &H[(row0 + r0) * 256 + k0 + c4]);
            cp_async16(&As[st][r0+64][c4], &H[(row0 + r0 + 64) * 256 + k0 + c4]);
            if (tid < 128)
                cp_async16(&Bs[st][brB][bc4B], &W2[(k0 + brB) * 32 + bc4B]);
            cp_commit();
        }
    }

    #pragma unroll
    for (int mt = 0; mt < 2; mt++) {
        #pragma unroll
        for (int nt = 0; nt < 2; nt++) {
            int r = row0 + wm + mt*16 + lq;
            int cn = wn + nt*8 + lr*2;
            float b0v = bvec[cn], b1v = bvec[cn+1];
            float ph;
            float sp, cp;
            ph = tanhf(c[mt][nt][0] + b0v) * PI_F; __sincosf(ph, &sp, &cp);
            fdst[r*64 + cn] = cp; fdst[r*64 + 32 + cn] = sp;
            ph = tanhf(c[mt][nt][1] + b1v) * PI_F; __sincosf(ph, &sp, &cp);
            fdst[r*64 + cn+1] = cp; fdst[r*64 + 32 + cn+1] = sp;
            ph = tanhf(c[mt][nt][2] + b0v) * PI_F; __sincosf(ph, &sp, &cp);
            fdst[(r+8)*64 + cn] = cp; fdst[(r+8)*64 + 32 + cn] = sp;
            ph = tanhf(c[mt][nt][3] + b1v) * PI_F; __sincosf(ph, &sp, &cp);
            fdst[(r+8)*64 + cn+1] = cp; fdst[(r+8)*64 + 32 + cn+1] = sp;
        }
    }
    // gates only in the k-path blocks
    if (!isq) {
        for (int rr = 0; rr < 16; rr++) {
            int r = row0 + w*16 + rr;
            float p0 = 0.f, p1 = 0.f;
            #pragma unroll
            for (int i = lane; i < 64; i += 32) {
                float gv = g_g1[r*64 + i];
                p0 += gv * Wg2[i*2 + 0];
                p1 += gv * Wg2[i*2 + 1];
            }
            #pragma unroll
            for (int off = 16; off; off >>= 1) {
                p0 += __shfl_xor_sync(~0u, p0, off);
                p1 += __shfl_xor_sync(~0u, p1, off);
            }
            if (lane == 0) {
                float l0 = p0 + bg2[0], l1 = p1 + bg2[1];
                float m = fmaxf(l0, l1);
                float e0 = __expf(l0 - m), e1 = __expf(l1 - m);
                float inv = 1.f / (e0 + e1);
                g_gates[r*2 + 0] = e0 * inv;
                g_gates[r*2 + 1] = e1 * inv;
            }
        }
    }
}

// ================= Kernel 3a+5 merged: chunk states || masked scores =================
__global__ __launch_bounds__(256) void k3a5_mma()
{
    __shared__ float sraw[10240];
    int tid = threadIdx.x;
    int w = tid >> 5, lane = tid & 31;
    int lq = lane >> 2, lr = lane & 3;

    if (blockIdx.x < 64) {
        float (*Kl)[16][68]  = (float(*)[16][68])sraw;
        float (*Bs)[16][132] = (float(*)[16][132])(sraw + 2176);
        int bc = blockIdx.x & 31;
        int b = bc >> 4, c = bc & 15;
        int d0 = (blockIdx.x >> 5) * 128;
        int row0 = b * LL + c * CC;
        int wm = (w & 1) * 32, wn = (w >> 1) * 32;
        int af4 = (tid & 15) * 4, al = tid >> 4;
        int rB = tid >> 5, cB = (tid & 31) * 4;
        float acc[2][4][4] = {};
        float4 av, bv0, bv1;

        av  = *(const float4*)&g_kf[(row0 + al) * 64 + af4];
        bv0 = *(const float4*)&g_vc[(row0 + rB) * 256 + d0 + cB];
        bv1 = *(const float4*)&g_vc[(row0 + rB + 8) * 256 + d0 + cB];
        *(float4*)&Kl[0][al][af4] = av;
        *(float4*)&Bs[0][rB][cB] = bv0;
        *(float4*)&Bs[0][rB+8][cB] = bv1;
        __syncthreads();

        for (int s = 0; s < 8; s++) {
            int cur = s & 1;
            if (s < 7) {
                int kn = (s + 1) * 16;
                av  = *(const float4*)&g_kf[(row0 + kn + al) * 64 + af4];
                bv0 = *(const float4*)&g_vc[(row0 + kn + rB) * 256 + d0 + cB];
                bv1 = *(const float4*)&g_vc[(row0 + kn + rB + 8) * 256 + d0 + cB];
            }
            #pragma unroll
            for (int ks = 0; ks < 2; ks++) {
                unsigned a[2][4];
                #pragma unroll
                for (int mt = 0; mt < 2; mt++) {
                    int rr = wm + mt*16 + lq;
                    int cc = ks*8 + lr;
                    a[mt][0] = __float_as_uint(Kl[cur][cc][rr]);
                    a[mt][1] = __float_as_uint(Kl[cur][cc][rr+8]);
                    a[mt][2] = __float_as_uint(Kl[cur][cc+4][rr]);
                    a[mt][3] = __float_as_uint(Kl[cur][cc+4][rr+8]);
                }
                #pragma unroll
                for (int nt = 0; nt < 4; nt++) {
                    int bn = wn + nt*8 + lq;
                    unsigned b0 = __float_as_uint(Bs[cur][ks*8+lr][bn]);
                    unsigned b1 = __float_as_uint(Bs[cur][ks*8+lr+4][bn]);
                    #pragma unroll
                    for (int mt = 0; mt < 2; mt++)
                        mma_tf32(acc[mt][nt], a[mt][0], a[mt][1], a[mt][2], a[mt][3], b0, b1);
                }
            }
            if (s < 7) {
                int nb = cur ^ 1;
                *(float4*)&Kl[nb][al][af4] = av;
                *(float4*)&Bs[nb][rB][cB] = bv0;
                *(float4*)&Bs[nb][rB+8][cB] = bv1;
            }
            __syncthreads();
        }
        int base = bc * 64 * 256;
        #pragma unroll
        for (int mt = 0; mt < 2; mt++) {
            #pragma unroll
            for (int nt = 0; nt < 4; nt++) {
                int f = wm + mt*16 + lq;
                int dd = d0 + wn + nt*8 + lr*2;
                *(float2*)&g_S[base + f * 256 + dd] = make_float2(acc[mt][nt][0], acc[mt][nt][1]);
                *(float2*)&g_S[base + (f+8) * 256 + dd] = make_float2(acc[mt][nt][2], acc[mt][nt][3]);
            }
        }
        return;
    }

    {
        float (*As)[128][20] = (float(*)[128][20])sraw;
        float (*Ks)[128][20] = (float(*)[128][20])(sraw + 5120);
        int bc = blockIdx.x - 64;
        int b = bc >> 4, c = bc & 15;
        int row0 = b * LL + c * CC;
        int wm = (w & 3) * 32;
        int wn = (w >> 2) * 64;
        int r0 = tid >> 2, c4 = (tid & 3) * 4;
        float acc[2][8][4] = {};
        float4 a0v, a1v, u0, u1;

        a0v = *(const float4*)&g_qf[(row0 + r0) * 64 + c4];
        a1v = *(const float4*)&g_qf[(row0 + r0 + 64) * 64 + c4];
        u0  = *(const float4*)&g_kf[(row0 + r0) * 64 + c4];
        u1  = *(const float4*)&g_kf[(row0 + r0 + 64) * 64 + c4];
        *(float4*)&As[0][r0][c4] = a0v;
        *(float4*)&As[0][r0+64][c4] = a1v;
        *(float4*)&Ks[0][r0][c4] = u0;
        *(float4*)&Ks[0][r0+64][c4] = u1;
        __syncthreads();

        for (int s = 0; s < 4; s++) {
            int cur = s & 1;
            if (s < 3) {
                int kn = (s + 1) * 16;
                a0v = *(const float4*)&g_qf[(row0 + r0) * 64 + kn + c4];
                a1v = *(const float4*)&g_qf[(row0 + r0 + 64) * 64 + kn + c4];
                u0  = *(const float4*)&g_kf[(row0 + r0) * 64 + kn + c4];
                u1  = *(const float4*)&g_kf[(row0 + r0 + 64) * 64 + kn + c4];
            }
            #pragma unroll
            for (int ks = 0; ks < 2; ks++) {
                unsigned a[2][4];
                #pragma unroll
                for (int mt = 0; mt < 2; mt++) {
                    int rr = wm + mt*16 + lq;
                    int cc = ks*8 + lr;
                    a[mt][0] = __float_as_uint(As[cur][rr][cc]);
                    a[mt][1] = __float_as_uint(As[cur][rr+8][cc]);
                    a[mt][2] = __float_as_uint(As[cur][rr][cc+4]);
                    a[mt][3] = __float_as_uint(As[cur][rr+8][cc+4]);
                }
                #pragma unroll
                for (int nt = 0; nt < 8; nt++) {
                    int bn = wn + nt*8 + lq;
                    unsigned b0 = __float_as_uint(Ks[cur][bn][ks*8+lr]);
                    unsigned b1 = __float_as_uint(Ks[cur][bn][ks*8+lr+4]);
                    #pragma unroll
                    for (int mt = 0; mt < 2; mt++)
                        mma_tf32(acc[mt][nt], a[mt][0], a[mt][1], a[mt][2], a[mt][3], b0, b1);
                }
            }
            if (s < 3) {
                int nb = cur ^ 1;
                *(float4*)&As[nb][r0][c4] = a0v;
                *(float4*)&As[nb][r0+64][c4] = a1v;
                *(float4*)&Ks[nb][r0][c4] = u0;
                *(float4*)&Ks[nb][r0+64][c4] = u1;
            }
            __syncthreads();
        }
        int sb = bc * CC * CC;
        #pragma unroll
        for (int mt = 0; mt < 2; mt++) {
            #pragma unroll
            for (int nt = 0; nt < 8; nt++) {
                int la = wm + mt*16 + lq;
                int lb = la + 8;
                int j0 = wn + nt*8 + lr*2;
                int j1 = j0 + 1;
                *(float2*)&g_scores[sb + la*128 + j0] =
                    make_float2(j0 <= la ? acc[mt][nt][0] : 0.f, j1 <= la ? acc[mt][nt][1] : 0.f);
                *(float2*)&g_scores[sb + lb*128 + j0] =
                    make_float2(j0 <= lb ? acc[mt][nt][2] : 0.f, j1 <= lb ? acc[mt][nt][3] : 0.f);
            }
        }
    }
}

// ================= Kernel 4: exclusive prefixes (front-batched loads) =================
__global__ __launch_bounds__(256) void k4_prefix()
{
    int tid = threadIdx.x;
    if (blockIdx.x < 128) {
        int idx = blockIdx.x * 256 + tid;
        int b = idx >> 14, rd = idx & 16383;
        float v[16];
        #pragma unroll
        for (int c = 0; c < 16; c++)
            v[c] = g_S[(b * 16 + c) * 16384 + rd];
        float run = 0.f;
        #pragma unroll
        for (int c = 0; c < 16; c++) {
            g_P[(b * 16 + c) * 16384 + rd] = run;
            run += v[c];
        }
    } else {
        int e = (blockIdx.x - 128) * 256 + tid;
        if (e < 1024) {
            int b = e >> 9, rd = e & 511;
            float v[64];
            #pragma unroll
            for (int s = 0; s < 64; s++)
                v[s] = g_psnap[((b * 64 + s) * 4 + 3) * 512 + rd];
            float run = 0.f;
            #pragma unroll
            for (int s = 0; s < 64; s++) {
                g_pprefix[(b * 64 + s) * 512 + rd] = run;
                run += v[s];
            }
        }
    }
}

// ================= Kernel 6: content output (3-stage cp.async) =================
__global__ __launch_bounds__(256) void k6_mma()
{
    __shared__ __align__(16) float As[3][128][20];
    __shared__ __align__(16) float Bs[3][16][68];
    int bc = blockIdx.x; int b = bc >> 4, c = bc & 15;
    int d0 = blockIdx.y * 64;
    int row0 = b * LL + c * CC;
    int tid = threadIdx.x;
    int w = tid >> 5, lane = tid & 31;
    int wm = (w & 3) * 32;
    int wn = (w >> 2) * 32;
    int lq = lane >> 2, lr = lane & 3;
    int r0 = tid >> 2, c4 = (tid & 3) * 4;
    int br = tid >> 4, bc4 = (tid & 15) * 4;
    int Pbase = bc * 64 * 256;
    int sbase = bc * CC * CC;
    float acc[2][4][4] = {};

    #pragma unroll
    for (int p = 0; p < 2; p++) {
        int k0 = p * 16;
        int kga = k0 + c4;
        const float *sa0, *sa1;
        if (kga < 64) {
            sa0 = &g_qf[(row0 + r0) * 64 + kga];
            sa1 = &g_qf[(row0 + r0 + 64) * 64 + kga];
        } else {
            sa0 = &g_scores[sbase + r0 * 128 + kga - 64];
            sa1 = &g_scores[sbase + (r0 + 64) * 128 + kga - 64];
        }
        int kgb = k0 + br;
        const float* sbp = (kgb < 64) ? &g_P[Pbase + kgb * 256 + d0 + bc4]
                                      : &g_vc[(row0 + kgb - 64) * 256 + d0 + bc4];
        cp_async16(&As[p][r0][c4], sa0);
        cp_async16(&As[p][r0+64][c4], sa1);
        cp_async16(&Bs[p][br][bc4], sbp);
        cp_commit();
    }

    for (int s = 0; s < 12; s++) {
        if (s < 11) cp_wait1(); else cp_wait0();
        __syncthreads();
        int cur = s % 3;
        #pragma unroll
        for (int ks = 0; ks < 2; ks++) {
            unsigned a[2][4];
            #pragma unroll
            for (int mt = 0; mt < 2; mt++) {
                int rr = wm + mt*16 + lq;
                int cc = ks*8 + lr;
                a[mt][0] = __float_as_uint(As[cur][rr][cc]);
                a[mt][1] = __float_as_uint(As[cur][rr+8][cc]);
                a[mt][2] = __float_as_uint(As[cur][rr][cc+4]);
                a[mt][3] = __float_as_uint(As[cur][rr+8][cc+4]);
            }
            #pragma unroll
            for (int nt = 0; nt < 4; nt++) {
                int bn = wn + nt*8 + lq;
                unsigned b0 = __float_as_uint(Bs[cur][ks*8+lr][bn]);
                unsigned b1 = __float_as_uint(Bs[cur][ks*8+lr+4][bn]);
                #pragma unroll
                for (int mt = 0; mt < 2; mt++)
                    mma_tf32(acc[mt][nt], a[mt][0], a[mt][1], a[mt][2], a[mt][3], b0, b1);
            }
        }
        if (s < 10) {
            int st = (s + 2) % 3;
            int k0 = (s + 2) * 16;
            int kga = k0 + c4;
            const float *sa0, *sa1;
            if (kga < 64) {
                sa0 = &g_qf[(row0 + r0) * 64 + kga];
                sa1 = &g_qf[(row0 + r0 + 64) * 64 + kga];
            } else {
                sa0 = &g_scores[sbase + r0 * 128 + kga - 64];
                sa1 = &g_scores[sbase + (r0 + 64) * 128 + kga - 64];
            }
            int kgb = k0 + br;
            const float* sbp = (kgb < 64) ? &g_P[Pbase + kgb * 256 + d0 + bc4]
                                          : &g_vc[(row0 + kgb - 64) * 256 + d0 + bc4];
            cp_async16(&As[st][r0][c4], sa0);
            cp_async16(&As[st][r0+64][c4], sa1);
            cp_async16(&Bs[st][br][bc4], sbp);
            cp_commit();
        }
    }
    #pragma unroll
    for (int mt = 0; mt < 2; mt++) {
        #pragma unroll
        for (int nt = 0; nt < 4; nt++) {
            int la = wm + mt*16 + lq;
            int lb = la + 8;
            int cc = d0 + wn + nt*8 + lr*2;
            float sa = rsqrtf((float)((c*CC + la + 1) * KK));
            float sb2 = rsqrtf((float)((c*CC + lb + 1) * KK));
            *(float2*)&g_cont[(row0 + la) * 256 + cc] =
                make_float2(acc[mt][nt][0] * sa, acc[mt][nt][1] * sa);
            *(float2*)&g_cont[(row0 + lb) * 256 + cc] =
                make_float2(acc[mt][nt][2] * sb2, acc[mt][nt][3] * sb2);
        }
    }
}

// ================= Kernel 7: pos scan (8 rows/block) + gate combine + LayerNorm =========
__global__ __launch_bounds__(256) void k7_poscomb(
    const float* __restrict__ base_phases,
    const float* __restrict__ ln_g, const float* __restrict__ ln_b)
{
    __shared__ float comb[8][257];
    int blk = blockIdx.x;
    int j = blk & 3;
    int s = (blk >> 2) & 63;
    int b = blk >> 8;
    int row0 = b * LL + s * 32 + j * 8;
    int l0 = s * 32 + j * 8;
    int d = threadIdx.x;
    float ar = g_pprefix[(b * 64 + s) * 512 + d];
    float ai = g_pprefix[(b * 64 + s) * 512 + 256 + d];
    if (j > 0) {
        int snapbase = ((b * 64 + s) * 4 + j - 1) * 512;
        ar += g_psnap[snapbase + d];
        ai += g_psnap[snapbase + 256 + d];
    }
    float vp[8], ph[8], cv[8];
    #pragma unroll
    for (int lt = 0; lt < 8; lt++) {
        vp[lt] = g_vp[(row0 + lt) * 256 + d];
        ph[lt] = base_phases[(l0 + lt) * 256 + d];
        cv[lt] = g_cont[(row0 + lt) * 256 + d];
    }
    #pragma unroll
    for (int lt = 0; lt < 8; lt++) {
        float sp, cp; __sincosf(ph[lt], &sp, &cp);
        ar += vp[lt] * cp; ai += vp[lt] * sp;
        float pret = (ar * cp + ai * sp) * rsqrtf((float)(l0 + lt + 1));
        float g0 = g_gates[(row0 + lt) * 2], g1v = g_gates[(row0 + lt) * 2 + 1];
        comb[lt][d] = g0 * pret + g1v * cv[lt];
    }
    __syncthreads();
    int w = d >> 5, lane = d & 31;
    int r = row0 + w;
    float vals[8]; float s1 = 0.f, s2 = 0.f;
    #pragma unroll
    for (int k = 0; k < 8; k++) {
        float v = comb[w][lane + 32*k];
        vals[k] = v; s1 += v; s2 += v*v;
    }
    #pragma unroll
    for (int off = 16; off; off >>= 1) {
        s1 += __shfl_xor_sync(~0u, s1, off);
        s2 += __shfl_xor_sync(~0u, s2, off);
    }
    float mu = s1 * (1.f/256.f);
    float var = s2 * (1.f/256.f) - mu*mu;
    float rstd = rsqrtf(var + 1e-5f);
    #pragma unroll
    for (int k = 0; k < 8; k++) {
        int dd = lane + 32*k;
        g_norm[r*256 + dd] = (vals[k] - mu) * rstd * ln_g[dd] + ln_b[dd];
    }
}

// ================= Kernel 8: out = x + normed @ Wo + bo (3-stage cp.async) ============
__global__ __launch_bounds__(256) void k8_mma(
    const float* __restrict__ x, const float* __restrict__ Wo,
    const float* __restrict__ bo, float* __restrict__ out)
{
    __shared__ __align__(16) float As[3][128][20];
    __shared__ __align__(16) float Bs[3][16][68];
    int row0 = blockIdx.x * 128;
    int colbase = blockIdx.y * 64;
    int tid = threadIdx.x;
    int w = tid >> 5, lane = tid & 31;
    int wm = (w & 3) * 32;
    int wn = (w >> 2) * 32;
    int lq = lane >> 2, lr = lane & 3;
    int r0 = tid >> 2, c4 = (tid & 3) * 4;
    int br = tid >> 4, bc4 = (tid & 15) * 4;
    float c[2][4][4] = {};

    #pragma unroll
    for (int p = 0; p < 2; p++) {
        int k0 = p * 16;
        cp_async16(&As[p][r0][c4],    &g_norm[(row0 + r0) * 256 + k0 + c4]);
        cp_async16(&As[p][r0+64][c4], &g_norm[(row0 + r0 + 64) * 256 + k0 + c4]);
        cp_async16(&Bs[p][br][bc4],   &Wo[(k0 + br) * 256 + colbase + bc4]);
        cp_commit();
    }

    for (int s = 0; s < 16; s++) {
        if (s < 15) cp_wait1(); else cp_wait0();
        __syncthreads();
        int cur = s % 3;
        #pragma unroll
        for (int ks = 0; ks < 2; ks++) {
            unsigned a[2][4];
            #pragma unroll
            for (int mt = 0; mt < 2; mt++) {
                int rr = wm + mt*16 + lq;
                int cc = ks*8 + lr;
                a[mt][0] = __float_as_uint(As[cur][rr][cc]);
                a[mt][1] = __float_as_uint(As[cur][rr+8][cc]);
                a[mt][2] = __float_as_uint(As[cur][rr][cc+4]);
                a[mt][3] = __float_as_uint(As[cur][rr+8][cc+4]);
            }
            #pragma unroll
            for (int nt = 0; nt < 4; nt++) {
                int bn = wn + nt*8 + lq;
                unsigned b0 = __float_as_uint(Bs[cur][ks*8+lr][bn]);
                unsigned b1 = __float_as_uint(Bs[cur][ks*8+lr+4][bn]);
                #pragma unroll
                for (int mt = 0; mt < 2; mt++)
                    mma_tf32(c[mt][nt], a[mt][0], a[mt][1], a[mt][2], a[mt][3], b0, b1);
            }
        }
        if (s < 14) {
            int st = (s + 2) % 3;
            int k0 = (s + 2) * 16;
            cp_async16(&As[st][r0][c4],    &g_norm[(row0 + r0) * 256 + k0 + c4]);
            cp_async16(&As[st][r0+64][c4], &g_norm[(row0 + r0 + 64) * 256 + k0 + c4]);
            cp_async16(&Bs[st][br][bc4],   &Wo[(k0 + br) * 256 + colbase + bc4]);
            cp_commit();
        }
    }
    #pragma unroll
    for (int mt = 0; mt < 2; mt++) {
        #pragma unroll
        for (int nt = 0; nt < 4; nt++) {
            int r = row0 + wm + mt*16 + lq;
            int cc = colbase + wn + nt*8 + lr*2;
            float b0v = bo[cc], b1v = bo[cc+1];
            float2 x0 = *(const float2*)&x[r * 256 + cc];
            float2 x1 = *(const float2*)&x[(r+8) * 256 + cc];
            *(float2*)&out[r * 256 + cc] =
                make_float2(c[mt][nt][0] + b0v + x0.x, c[mt][nt][1] + b1v + x0.y);
            *(float2*)&out[(r+8) * 256 + cc] =
                make_float2(c[mt][nt][2] + b0v + x1.x, c[mt][nt][3] + b1v + x1.y);
        }
    }
}

// ================= launcher =================
extern "C" void kernel_launch(void* const* d_in, const int* in_sizes, int n_in,
                              void* d_out, int out_size)
{
    const float* x   = (const float*)d_in[0];
    const float* bp  = (const float*)d_in[1];
    const float* Wk1 = (const float*)d_in[2];
    const float* bk1 = (const float*)d_in[3];
    const float* Wk2 = (const float*)d_in[4];
    const float* bk2 = (const float*)d_in[5];
    const float* Wq1 = (const float*)d_in[6];
    const float* bq1 = (const float*)d_in[7];
    const float* Wq2 = (const float*)d_in[8];
    const float* bq2 = (const float*)d_in[9];
    const float* Wvc = (const float*)d_in[10];
    const float* bvc = (const float*)d_in[11];
    const float* Wvp = (const float*)d_in[12];
    const float* bvp = (const float*)d_in[13];
    const float* Wg1 = (const float*)d_in[14];
    const float* bg1 = (const float*)d_in[15];
    const float* Wg2 = (const float*)d_in[16];
    const float* bg2 = (const float*)d_in[17];
    const float* lng = (const float*)d_in[18];
    const float* lnb = (const float*)d_in[19];
    const float* Wo  = (const float*)d_in[20];
    const float* bo  = (const float*)d_in[21];
    float* out = (float*)d_out;

    k1_mma<<<dim3(32, 17), 256>>>(x, Wk1, bk1, Wq1, bq1, Wvc, bvc, Wvp, bvp, Wg1, bg1);
    k23b_mma<<<192, 256>>>(Wk2, bk2, Wq2, bq2, Wg2, bg2, bp);
    k3a5_mma<<<96, 256>>>();
    k4_prefix<<<132, 256>>>();
    k6_mma<<<dim3(32, 4), 256>>>();
    k7_poscomb<<<512, 256>>>(bp, lng, lnb);
    k8_mma<<<dim3(32, 4), 256>>>(x, Wo, bo, out);
}

// round 13
// speedup vs baseline: 1.4490x; 1.0008x over previous
#include <cuda_runtime.h>
#include <cuda_bf16.h>
#include <math.h>

// Problem constants
#define Bb 2
#define LL 2048
#define DD 256
#define KK 32
#define FF 64          // 2*K feature dim
#define MM (Bb*LL)     // 4096 rows
#define CC 128         // chunk size
#define NC (LL/CC)     // 16 chunks per batch
#define PI_F 3.14159265358979323846f

// ---------------- scratch (device globals; no allocation allowed) ----------------
__device__ float g_hk[MM*DD];
__device__ float g_hq[MM*DD];
__device__ float g_vc[MM*DD];
__device__ float g_vp[MM*DD];
__device__ float g_g1[MM*64];
__device__ float g_kf[MM*FF];
__device__ float g_qf[MM*FF];
__device__ float g_gates[MM*2];
__device__ float g_S[Bb*NC*FF*DD];         // per-chunk content state sums (mma)
__device__ float g_P[Bb*NC*FF*DD];         // chunk-level exclusive prefix of states
__device__ float g_psnap[Bb*64*4*2*DD];    // pos accum snapshots every 8 rows (inclusive)
__device__ float g_pprefix[Bb*64*2*DD];    // exclusive prefix at 32-row granularity
__device__ float g_scores[Bb*NC*CC*CC];    // intra-chunk masked scores
__device__ float g_cont[MM*DD];
__device__ float g_norm[MM*DD];
__device__ float g_cph[LL*DD];             // cached cos(base_phases[:LL])
__device__ float g_sph[LL*DD];             // cached sin(base_phases[:LL])

// mma consumes raw f32 bit patterns as tf32 (HW truncates mantissa; no cvt needed)
__device__ __forceinline__ void mma_tf32(float c[4],
    unsigned a0, unsigned a1, unsigned a2, unsigned a3,
    unsigned b0, unsigned b1)
{
    asm volatile(
        "mma.sync.aligned.m16n8k8.row.col.f32.tf32.tf32.f32 "
        "{%0,%1,%2,%3}, {%4,%5,%6,%7}, {%8,%9}, {%0,%1,%2,%3};"
        : "+f"(c[0]), "+f"(c[1]), "+f"(c[2]), "+f"(c[3])
        : "r"(a0), "r"(a1), "r"(a2), "r"(a3), "r"(b0), "r"(b1));
}

// ---------------- cp.async helpers ----------------
__device__ __forceinline__ void cp_async16(void* smem_dst, const void* gsrc) {
    unsigned saddr = (unsigned)__cvta_generic_to_shared(smem_dst);
    asm volatile("cp.async.cg.shared.global [%0], [%1], 16;" :: "r"(saddr), "l"(gsrc));
}
__device__ __forceinline__ void cp_commit() {
    asm volatile("cp.async.commit_group;");
}
__device__ __forceinline__ void cp_wait1() {
    asm volatile("cp.async.wait_group 1;");
}
__device__ __forceinline__ void cp_wait0() {
    asm volatile("cp.async.wait_group 0;");
}

// ================= Kernel 1: fused first-layer GEMMs (3-stage cp.async) =============
// grid (32, 17): ct<16 -> [hk|hq|vc|vp] x 4 col-quarters; ct==16 -> g1
__global__ __launch_bounds__(256) void k1_mma(
    const float* __restrict__ x,
    const float* __restrict__ Wk1, const float* __restrict__ bk1,
    const float* __restrict__ Wq1, const float* __restrict__ bq1,
    const float* __restrict__ Wvc, const float* __restrict__ bvc,
    const float* __restrict__ Wvp, const float* __restrict__ bvp,
    const float* __restrict__ Wg1, const float* __restrict__ bg1)
{
    __shared__ __align__(16) float As[3][128][20];
    __shared__ __align__(16) float Bs[3][16][68];
    int ct = blockIdx.y;
    const float* W; const float* bias; float* outp; int Nseg; int act; int colbase;
    if (ct < 16) {
        int seg = ct >> 2;
        colbase = (ct & 3) * 64;
        Nseg = 256;
        if (seg == 0)      { W = Wk1; bias = bk1; outp = g_hk; act = 1; }
        else if (seg == 1) { W = Wq1; bias = bq1; outp = g_hq; act = 1; }
        else if (seg == 2) { W = Wvc; bias = bvc; outp = g_vc; act = 0; }
        else               { W = Wvp; bias = bvp; outp = g_vp; act = 0; }
    } else {
        W = Wg1; bias = bg1; outp = g_g1; Nseg = 64; act = 2; colbase = 0;
    }
    int row0 = blockIdx.x * 128;
    int tid = threadIdx.x;
    int w = tid >> 5, lane = tid & 31;
    int wm = (w & 3) * 32;
    int wn = (w >> 2) * 32;
    int lq = lane >> 2, lr = lane & 3;
    int r0 = tid >> 2, c4 = (tid & 3) * 4;
    int br = tid >> 4, bc4 = (tid & 15) * 4;
    float c[2][4][4] = {};

    #pragma unroll
    for (int p = 0; p < 2; p++) {
        int k0 = p * 16;
        cp_async16(&As[p][r0][c4],    &x[(row0 + r0) * 256 + k0 + c4]);
        cp_async16(&As[p][r0+64][c4], &x[(row0 + r0 + 64) * 256 + k0 + c4]);
        cp_async16(&Bs[p][br][bc4],   &W[(k0 + br) * Nseg + colbase + bc4]);
        cp_commit();
    }

    for (int s = 0; s < 16; s++) {
        if (s < 15) cp_wait1(); else cp_wait0();
        __syncthreads();
        int cur = s % 3;
        #pragma unroll
        for (int ks = 0; ks < 2; ks++) {
            unsigned a[2][4];
            #pragma unroll
            for (int mt = 0; mt < 2; mt++) {
                int rr = wm + mt*16 + lq;
                int cc = ks*8 + lr;
                a[mt][0] = __float_as_uint(As[cur][rr][cc]);
                a[mt][1] = __float_as_uint(As[cur][rr+8][cc]);
                a[mt][2] = __float_as_uint(As[cur][rr][cc+4]);
                a[mt][3] = __float_as_uint(As[cur][rr+8][cc+4]);
            }
            #pragma unroll
            for (int nt = 0; nt < 4; nt++) {
                int bn = wn + nt*8 + lq;
                unsigned b0 = __float_as_uint(Bs[cur][ks*8+lr][bn]);
                unsigned b1 = __float_as_uint(Bs[cur][ks*8+lr+4][bn]);
                #pragma unroll
                for (int mt = 0; mt < 2; mt++)
                    mma_tf32(c[mt][nt], a[mt][0], a[mt][1], a[mt][2], a[mt][3], b0, b1);
            }
        }
        if (s < 14) {
            int st = (s + 2) % 3;
            int k0 = (s + 2) * 16;
            cp_async16(&As[st][r0][c4],    &x[(row0 + r0) * 256 + k0 + c4]);
            cp_async16(&As[st][r0+64][c4], &x[(row0 + r0 + 64) * 256 + k0 + c4]);
            cp_async16(&Bs[st][br][bc4],   &W[(k0 + br) * Nseg + colbase + bc4]);
            cp_commit();
        }
    }
    #pragma unroll
    for (int mt = 0; mt < 2; mt++) {
        #pragma unroll
        for (int nt = 0; nt < 4; nt++) {
            int r = row0 + wm + mt*16 + lq;
            int cc = colbase + wn + nt*8 + lr*2;
            float b0v = bias[cc], b1v = bias[cc+1];
            float v00 = c[mt][nt][0] + b0v, v01 = c[mt][nt][1] + b1v;
            float v10 = c[mt][nt][2] + b0v, v11 = c[mt][nt][3] + b1v;
            if (act == 1) { v00 = tanhf(v00); v01 = tanhf(v01); v10 = tanhf(v10); v11 = tanhf(v11); }
            else if (act == 2) { v00 = fmaxf(v00,0.f); v01 = fmaxf(v01,0.f); v10 = fmaxf(v10,0.f); v11 = fmaxf(v11,0.f); }
            *(float2*)&outp[r * Nseg + cc] = make_float2(v00, v01);
            *(float2*)&outp[(r+8) * Nseg + cc] = make_float2(v10, v11);
        }
    }
}

// ===== Kernel 2+3b merged: split phase GEMMs (3-stage cp.async) || pos partials =======
// blocks [0,32): k-path GEMM + gates; [32,64): q-path GEMM;
// blocks [64,128): pos partials for BOTH batches (one sincos, cached to g_cph/g_sph).
__global__ __launch_bounds__(256) void k23b_mma(
    const float* __restrict__ Wk2, const float* __restrict__ bk2,
    const float* __restrict__ Wq2, const float* __restrict__ bq2,
    const float* __restrict__ Wg2, const float* __restrict__ bg2,
    const float* __restrict__ base_phases)
{
    __shared__ __align__(16) float As[3][128][20];
    __shared__ __align__(16) float Bs[3][16][36];
    int tid = threadIdx.x;
    int bx = blockIdx.x;

    if (bx >= 64) {
        // ---- pos partial sums for both batches + sincos cache ----
        int s = bx - 64;            // 0..63
        int l0 = s * 32;
        int row0_0 = l0;            // b = 0
        int row0_1 = LL + l0;       // b = 1
        int d = tid;
        float par0 = 0.f, pai0 = 0.f, par1 = 0.f, pai1 = 0.f;
        #pragma unroll
        for (int g = 0; g < 4; g++) {
            float ph8[8], v0[8], v1[8];
            #pragma unroll
            for (int j = 0; j < 8; j++) {
                ph8[j] = base_phases[(l0 + g*8 + j) * 256 + d];
                v0[j] = g_vp[(row0_0 + g*8 + j) * 256 + d];
                v1[j] = g_vp[(row0_1 + g*8 + j) * 256 + d];
            }
            #pragma unroll
            for (int j = 0; j < 8; j++) {
                float sp, cp; __sincosf(ph8[j], &sp, &cp);
                int l = l0 + g*8 + j;
                g_cph[l*256 + d] = cp;
                g_sph[l*256 + d] = sp;
                par0 += v0[j] * cp; pai0 += v0[j] * sp;
                par1 += v1[j] * cp; pai1 += v1[j] * sp;
            }
            int sb0 = (s * 4 + g) * 512;
            int sb1 = ((64 + s) * 4 + g) * 512;
            g_psnap[sb0 + d] = par0; g_psnap[sb0 + 256 + d] = pai0;
            g_psnap[sb1 + d] = par1; g_psnap[sb1 + 256 + d] = pai1;
        }
        return;
    }

    // ---- phase-feature GEMM: one path per block ----
    bool isq = (bx >= 32);
    int row0 = (bx & 31) * 128;
    const float* H  = isq ? g_hq : g_hk;
    const float* W2 = isq ? Wq2 : Wk2;
    const float* bvec = isq ? bq2 : bk2;
    float* fdst = isq ? g_qf : g_kf;

    int w = tid >> 5, lane = tid & 31;
    int wm = (w & 3) * 32;
    int wn = (w >> 2) * 16;
    int lq = lane >> 2, lr = lane & 3;
    int r0 = tid >> 2, c4 = (tid & 3) * 4;
    int brB = tid >> 3, bc4B = (tid & 7) * 4;   // valid for tid < 128
    float c[2][2][4] = {};

    #pragma unroll
    for (int p = 0; p < 2; p++) {
        int k0 = p * 16;
        cp_async16(&As[p][r0][c4],    &H[(row0 + r0) * 256 + k0 + c4]);
        cp_async16(&As[p][r0+64][c4], &H[(row0 + r0 + 64) * 256 + k0 + c4]);
        if (tid < 128)
            cp_async16(&Bs[p][brB][bc4B], &W2[(k0 + brB) * 32 + bc4B]);
        cp_commit();
    }

    for (int s = 0; s < 16; s++) {
        if (s < 15) cp_wait1(); else cp_wait0();
        __syncthreads();
        int cur = s % 3;
        #pragma unroll
        for (int ks = 0; ks < 2; ks++) {
            unsigned a[2][4];
            #pragma unroll
            for (int mt = 0; mt < 2; mt++) {
                int rr = wm + mt*16 + lq;
                int cc = ks*8 + lr;
                a[mt][0] = __float_as_uint(As[cur][rr][cc]);
                a[mt][1] = __float_as_uint(As[cur][rr+8][cc]);
                a[mt][2] = __float_as_uint(As[cur][rr][cc+4]);
                a[mt][3] = __float_as_uint(As[cur][rr+8][cc+4]);
            }
            #pragma unroll
            for (int nt = 0; nt < 2; nt++) {
                int bn = wn + nt*8 + lq;
                unsigned b0 = __float_as_uint(Bs[cur][ks*8+lr][bn]);
                unsigned b1 = __float_as_uint(Bs[cur][ks*8+lr+4][bn]);
                #pragma unroll
                for (int mt = 0; mt < 2; mt++)
                    mma_tf32(c[mt][nt], a[mt][0], a[mt][1], a[mt][2], a[mt][3], b0, b1);
            }
        }
        if (s < 14) {
            int st = (s + 2) % 3;
            int k0 = (s + 2) * 16;
            cp_async16(&As[st][r0][c4],    &H[(row0 + r0) * 256 + k0 + c4]);
            cp_async16(&As[st][r0+64][c4], &H[(row0 + r0 + 64) * 256 + k0 + c4]);
            if (tid < 128)
                cp_async16(&Bs[st][brB][bc4B], &W2[(k0 + brB) * 32 + bc4B]);
            cp_commit();
        }
    }

    #pragma unroll
    for (int mt = 0; mt < 2; mt++) {
        #pragma unroll
        for (int nt = 0; nt < 2; nt++) {
            int r = row0 + wm + mt*16 + lq;
            int cn = wn + nt*8 + lr*2;
            float b0v = bvec[cn], b1v = bvec[cn+1];
            float ph;
            float sp, cp;
            ph = tanhf(c[mt][nt][0] + b0v) * PI_F; __sincosf(ph, &sp, &cp);
            fdst[r*64 + cn] = cp; fdst[r*64 + 32 + cn] = sp;
            ph = tanhf(c[mt][nt][1] + b1v) * PI_F; __sincosf(ph, &sp, &cp);
            fdst[r*64 + cn+1] = cp; fdst[r*64 + 32 + cn+1] = sp;
            ph = tanhf(c[mt][nt][2] + b0v) * PI_F; __sincosf(ph, &sp, &cp);
            fdst[(r+8)*64 + cn] = cp; fdst[(r+8)*64 + 32 + cn] = sp;
            ph = tanhf(c[mt][nt][3] + b1v) * PI_F; __sincosf(ph, &sp, &cp);
            fdst[(r+8)*64 + cn+1] = cp; fdst[(r+8)*64 + 32 + cn+1] = sp;
        }
    }
    // gates only in the k-path blocks
    if (!isq) {
        for (int rr = 0; rr < 16; rr++) {
            int r = row0 + w*16 + rr;
            float p0 = 0.f, p1 = 0.f;
            #pragma unroll
            for (int i = lane; i < 64; i += 32) {
                float gv = g_g1[r*64 + i];
                p0 += gv * Wg2[i*2 + 0];
                p1 += gv * Wg2[i*2 + 1];
            }
            #pragma unroll
            for (int off = 16; off; off >>= 1) {
                p0 += __shfl_xor_sync(~0u, p0, off);
                p1 += __shfl_xor_sync(~0u, p1, off);
            }
            if (lane == 0) {
                float l0 = p0 + bg2[0], l1 = p1 + bg2[1];
                float m = fmaxf(l0, l1);
                float e0 = __expf(l0 - m), e1 = __expf(l1 - m);
                float inv = 1.f / (e0 + e1);
                g_gates[r*2 + 0] = e0 * inv;
                g_gates[r*2 + 1] = e1 * inv;
            }
        }
    }
}

// ======== Kernel 3a+5 merged (+ pos prefix): chunk states || scores || pos-scan =======
// blocks [0,64): k3a; [64,96): k5 scores; [96,100): pos prefix (needs psnap from k23b).
__global__ __launch_bounds__(256) void k3a5_mma()
{
    __shared__ float sraw[10240];
    int tid = threadIdx.x;
    int w = tid >> 5, lane = tid & 31;
    int lq = lane >> 2, lr = lane & 3;

    if (blockIdx.x >= 96) {
        // ---- pos exclusive prefix over 64 s-groups ----
        int e = (blockIdx.x - 96) * 256 + tid;
        if (e < 1024) {
            int b = e >> 9, rd = e & 511;
            float v[64];
            #pragma unroll
            for (int s = 0; s < 64; s++)
                v[s] = g_psnap[((b * 64 + s) * 4 + 3) * 512 + rd];
            float run = 0.f;
            #pragma unroll
            for (int s = 0; s < 64; s++) {
                g_pprefix[(b * 64 + s) * 512 + rd] = run;
                run += v[s];
            }
        }
        return;
    }

    if (blockIdx.x < 64) {
        float (*Kl)[16][68]  = (float(*)[16][68])sraw;
        float (*Bs)[16][132] = (float(*)[16][132])(sraw + 2176);
        int bc = blockIdx.x & 31;
        int b = bc >> 4, c = bc & 15;
        int d0 = (blockIdx.x >> 5) * 128;
        int row0 = b * LL + c * CC;
        int wm = (w & 1) * 32, wn = (w >> 1) * 32;
        int af4 = (tid & 15) * 4, al = tid >> 4;
        int rB = tid >> 5, cB = (tid & 31) * 4;
        float acc[2][4][4] = {};
        float4 av, bv0, bv1;

        av  = *(const float4*)&g_kf[(row0 + al) * 64 + af4];
        bv0 = *(const float4*)&g_vc[(row0 + rB) * 256 + d0 + cB];
        bv1 = *(const float4*)&g_vc[(row0 + rB + 8) * 256 + d0 + cB];
        *(float4*)&Kl[0][al][af4] = av;
        *(float4*)&Bs[0][rB][cB] = bv0;
        *(float4*)&Bs[0][rB+8][cB] = bv1;
        __syncthreads();

        for (int s = 0; s < 8; s++) {
            int cur = s & 1;
            if (s < 7) {
                int kn = (s + 1) * 16;
                av  = *(const float4*)&g_kf[(row0 + kn + al) * 64 + af4];
                bv0 = *(const float4*)&g_vc[(row0 + kn + rB) * 256 + d0 + cB];
                bv1 = *(const float4*)&g_vc[(row0 + kn + rB + 8) * 256 + d0 + cB];
            }
            #pragma unroll
            for (int ks = 0; ks < 2; ks++) {
                unsigned a[2][4];
                #pragma unroll
                for (int mt = 0; mt < 2; mt++) {
                    int rr = wm + mt*16 + lq;
                    int cc = ks*8 + lr;
                    a[mt][0] = __float_as_uint(Kl[cur][cc][rr]);
                    a[mt][1] = __float_as_uint(Kl[cur][cc][rr+8]);
                    a[mt][2] = __float_as_uint(Kl[cur][cc+4][rr]);
                    a[mt][3] = __float_as_uint(Kl[cur][cc+4][rr+8]);
                }
                #pragma unroll
                for (int nt = 0; nt < 4; nt++) {
                    int bn = wn + nt*8 + lq;
                    unsigned b0 = __float_as_uint(Bs[cur][ks*8+lr][bn]);
                    unsigned b1 = __float_as_uint(Bs[cur][ks*8+lr+4][bn]);
                    #pragma unroll
                    for (int mt = 0; mt < 2; mt++)
                        mma_tf32(acc[mt][nt], a[mt][0], a[mt][1], a[mt][2], a[mt][3], b0, b1);
                }
            }
            if (s < 7) {
                int nb = cur ^ 1;
                *(float4*)&Kl[nb][al][af4] = av;
                *(float4*)&Bs[nb][rB][cB] = bv0;
                *(float4*)&Bs[nb][rB+8][cB] = bv1;
            }
            __syncthreads();
        }
        int base = bc * 64 * 256;
        #pragma unroll
        for (int mt = 0; mt < 2; mt++) {
            #pragma unroll
            for (int nt = 0; nt < 4; nt++) {
                int f = wm + mt*16 + lq;
                int dd = d0 + wn + nt*8 + lr*2;
                *(float2*)&g_S[base + f * 256 + dd] = make_float2(acc[mt][nt][0], acc[mt][nt][1]);
                *(float2*)&g_S[base + (f+8) * 256 + dd] = make_float2(acc[mt][nt][2], acc[mt][nt][3]);
            }
        }
        return;
    }

    {
        float (*As)[128][20] = (float(*)[128][20])sraw;
        float (*Ks)[128][20] = (float(*)[128][20])(sraw + 5120);
        int bc = blockIdx.x - 64;
        int b = bc >> 4, c = bc & 15;
        int row0 = b * LL + c * CC;
        int wm = (w & 3) * 32;
        int wn = (w >> 2) * 64;
        int r0 = tid >> 2, c4 = (tid & 3) * 4;
        float acc[2][8][4] = {};
        float4 a0v, a1v, u0, u1;

        a0v = *(const float4*)&g_qf[(row0 + r0) * 64 + c4];
        a1v = *(const float4*)&g_qf[(row0 + r0 + 64) * 64 + c4];
        u0  = *(const float4*)&g_kf[(row0 + r0) * 64 + c4];
        u1  = *(const float4*)&g_kf[(row0 + r0 + 64) * 64 + c4];
        *(float4*)&As[0][r0][c4] = a0v;
        *(float4*)&As[0][r0+64][c4] = a1v;
        *(float4*)&Ks[0][r0][c4] = u0;
        *(float4*)&Ks[0][r0+64][c4] = u1;
        __syncthreads();

        for (int s = 0; s < 4; s++) {
            int cur = s & 1;
            if (s < 3) {
                int kn = (s + 1) * 16;
                a0v = *(const float4*)&g_qf[(row0 + r0) * 64 + kn + c4];
                a1v = *(const float4*)&g_qf[(row0 + r0 + 64) * 64 + kn + c4];
                u0  = *(const float4*)&g_kf[(row0 + r0) * 64 + kn + c4];
                u1  = *(const float4*)&g_kf[(row0 + r0 + 64) * 64 + kn + c4];
            }
            #pragma unroll
            for (int ks = 0; ks < 2; ks++) {
                unsigned a[2][4];
                #pragma unroll
                for (int mt = 0; mt < 2; mt++) {
                    int rr = wm + mt*16 + lq;
                    int cc = ks*8 + lr;
                    a[mt][0] = __float_as_uint(As[cur][rr][cc]);
                    a[mt][1] = __float_as_uint(As[cur][rr+8][cc]);
                    a[mt][2] = __float_as_uint(As[cur][rr][cc+4]);
                    a[mt][3] = __float_as_uint(As[cur][rr+8][cc+4]);
                }
                #pragma unroll
                for (int nt = 0; nt < 8; nt++) {
                    int bn = wn + nt*8 + lq;
                    unsigned b0 = __float_as_uint(Ks[cur][bn][ks*8+lr]);
                    unsigned b1 = __float_as_uint(Ks[cur][bn][ks*8+lr+4]);
                    #pragma unroll
                    for (int mt = 0; mt < 2; mt++)
                        mma_tf32(acc[mt][nt], a[mt][0], a[mt][1], a[mt][2], a[mt][3], b0, b1);
                }
            }
            if (s < 3) {
                int nb = cur ^ 1;
                *(float4*)&As[nb][r0][c4] = a0v;
                *(float4*)&As[nb][r0+64][c4] = a1v;
                *(float4*)&Ks[nb][r0][c4] = u0;
                *(float4*)&Ks[nb][r0+64][c4] = u1;
            }
            __syncthreads();
        }
        int sb = bc * CC * CC;
        #pragma unroll
        for (int mt = 0; mt < 2; mt++) {
            #pragma unroll
            for (int nt = 0; nt < 8; nt++) {
                int la = wm + mt*16 + lq;
                int lb = la + 8;
                int j0 = wn + nt*8 + lr*2;
                int j1 = j0 + 1;
                *(float2*)&g_scores[sb + la*128 + j0] =
                    make_float2(j0 <= la ? acc[mt][nt][0] : 0.f, j1 <= la ? acc[mt][nt][1] : 0.f);
                *(float2*)&g_scores[sb + lb*128 + j0] =
                    make_float2(j0 <= lb ? acc[mt][nt][2] : 0.f, j1 <= lb ? acc[mt][nt][3] : 0.f);
            }
        }
    }
}

// ================= Kernel 4: content exclusive prefix only =================
__global__ __launch_bounds__(256) void k4_prefix()
{
    int tid = threadIdx.x;
    int idx = blockIdx.x * 256 + tid;
    int b = idx >> 14, rd = idx & 16383;
    float v[16];
    #pragma unroll
    for (int c = 0; c < 16; c++)
        v[c] = g_S[(b * 16 + c) * 16384 + rd];
    float run = 0.f;
    #pragma unroll
    for (int c = 0; c < 16; c++) {
        g_P[(b * 16 + c) * 16384 + rd] = run;
        run += v[c];
    }
}

// ================= Kernel 6: content output (3-stage cp.async) =================
__global__ __launch_bounds__(256) void k6_mma()
{
    __shared__ __align__(16) float As[3][128][20];
    __shared__ __align__(16) float Bs[3][16][68];
    int bc = blockIdx.x; int b = bc >> 4, c = bc & 15;
    int d0 = blockIdx.y * 64;
    int row0 = b * LL + c * CC;
    int tid = threadIdx.x;
    int w = tid >> 5, lane = tid & 31;
    int wm = (w & 3) * 32;
    int wn = (w >> 2) * 32;
    int lq = lane >> 2, lr = lane & 3;
    int r0 = tid >> 2, c4 = (tid & 3) * 4;
    int br = tid >> 4, bc4 = (tid & 15) * 4;
    int Pbase = bc * 64 * 256;
    int sbase = bc * CC * CC;
    float acc[2][4][4] = {};

    #pragma unroll
    for (int p = 0; p < 2; p++) {
        int k0 = p * 16;
        int kga = k0 + c4;
        const float *sa0, *sa1;
        if (kga < 64) {
            sa0 = &g_qf[(row0 + r0) * 64 + kga];
            sa1 = &g_qf[(row0 + r0 + 64) * 64 + kga];
        } else {
            sa0 = &g_scores[sbase + r0 * 128 + kga - 64];
            sa1 = &g_scores[sbase + (r0 + 64) * 128 + kga - 64];
        }
        int kgb = k0 + br;
        const float* sbp = (kgb < 64) ? &g_P[Pbase + kgb * 256 + d0 + bc4]
                                      : &g_vc[(row0 + kgb - 64) * 256 + d0 + bc4];
        cp_async16(&As[p][r0][c4], sa0);
        cp_async16(&As[p][r0+64][c4], sa1);
        cp_async16(&Bs[p][br][bc4], sbp);
        cp_commit();
    }

    for (int s = 0; s < 12; s++) {
        if (s < 11) cp_wait1(); else cp_wait0();
        __syncthreads();
        int cur = s % 3;
        #pragma unroll
        for (int ks = 0; ks < 2; ks++) {
            unsigned a[2][4];
            #pragma unroll
            for (int mt = 0; mt < 2; mt++) {
                int rr = wm + mt*16 + lq;
                int cc = ks*8 + lr;
                a[mt][0] = __float_as_uint(As[cur][rr][cc]);
                a[mt][1] = __float_as_uint(As[cur][rr+8][cc]);
                a[mt][2] = __float_as_uint(As[cur][rr][cc+4]);
                a[mt][3] = __float_as_uint(As[cur][rr+8][cc+4]);
            }
            #pragma unroll
            for (int nt = 0; nt < 4; nt++) {
                int bn = wn + nt*8 + lq;
                unsigned b0 = __float_as_uint(Bs[cur][ks*8+lr][bn]);
                unsigned b1 = __float_as_uint(Bs[cur][ks*8+lr+4][bn]);
                #pragma unroll
                for (int mt = 0; mt < 2; mt++)
                    mma_tf32(acc[mt][nt], a[mt][0], a[mt][1], a[mt][2], a[mt][3], b0, b1);
            }
        }
        if (s < 10) {
            int st = (s + 2) % 3;
            int k0 = (s + 2) * 16;
            int kga = k0 + c4;
            const float *sa0, *sa1;
            if (kga < 64) {
                sa0 = &g_qf[(row0 + r0) * 64 + kga];
                sa1 = &g_qf[(row0 + r0 + 64) * 64 + kga];
            } else {
                sa0 = &g_scores[sbase + r0 * 128 + kga - 64];
                sa1 = &g_scores[sbase + (r0 + 64) * 128 + kga - 64];
            }
            int kgb = k0 + br;
            const float* sbp = (kgb < 64) ? &g_P[Pbase + kgb * 256 + d0 + bc4]
                                          : &g_vc[(row0 + kgb - 64) * 256 + d0 + bc4];
            cp_async16(&As[st][r0][c4], sa0);
            cp_async16(&As[st][r0+64][c4], sa1);
            cp_async16(&Bs[st][br][bc4], sbp);
            cp_commit();
        }
    }
    #pragma unroll
    for (int mt = 0; mt < 2; mt++) {
        #pragma unroll
        for (int nt = 0; nt < 4; nt++) {
            int la = wm + mt*16 + lq;
            int lb = la + 8;
            int cc = d0 + wn + nt*8 + lr*2;
            float sa = rsqrtf((float)((c*CC + la + 1) * KK));
            float sb2 = rsqrtf((float)((c*CC + lb + 1) * KK));
            *(float2*)&g_cont[(row0 + la) * 256 + cc] =
                make_float2(acc[mt][nt][0] * sa, acc[mt][nt][1] * sa);
            *(float2*)&g_cont[(row0 + lb) * 256 + cc] =
                make_float2(acc[mt][nt][2] * sb2, acc[mt][nt][3] * sb2);
        }
    }
}

// ======== Kernel 7: pos scan (cached sincos) + gate combine + LayerNorm =========
__global__ __launch_bounds__(256) void k7_poscomb(
    const float* __restrict__ ln_g, const float* __restrict__ ln_b)
{
    __shared__ float comb[8][257];
    int blk = blockIdx.x;
    int j = blk & 3;
    int s = (blk >> 2) & 63;
    int b = blk >> 8;
    int row0 = b * LL + s * 32 + j * 8;
    int l0 = s * 32 + j * 8;
    int d = threadIdx.x;
    float ar = g_pprefix[(b * 64 + s) * 512 + d];
    float ai = g_pprefix[(b * 64 + s) * 512 + 256 + d];
    if (j > 0) {
        int snapbase = ((b * 64 + s) * 4 + j - 1) * 512;
        ar += g_psnap[snapbase + d];
        ai += g_psnap[snapbase + 256 + d];
    }
    float vp[8], cph[8], sph[8], cv[8];
    #pragma unroll
    for (int lt = 0; lt < 8; lt++) {
        vp[lt]  = g_vp[(row0 + lt) * 256 + d];
        cph[lt] = g_cph[(l0 + lt) * 256 + d];
        sph[lt] = g_sph[(l0 + lt) * 256 + d];
        cv[lt]  = g_cont[(row0 + lt) * 256 + d];
    }
    #pragma unroll
    for (int lt = 0; lt < 8; lt++) {
        ar += vp[lt] * cph[lt]; ai += vp[lt] * sph[lt];
        float pret = (ar * cph[lt] + ai * sph[lt]) * rsqrtf((float)(l0 + lt + 1));
        float g0 = g_gates[(row0 + lt) * 2], g1v = g_gates[(row0 + lt) * 2 + 1];
        comb[lt][d] = g0 * pret + g1v * cv[lt];
    }
    __syncthreads();
    int w = d >> 5, lane = d & 31;
    int r = row0 + w;
    float vals[8]; float s1 = 0.f, s2 = 0.f;
    #pragma unroll
    for (int k = 0; k < 8; k++) {
        float v = comb[w][lane + 32*k];
        vals[k] = v; s1 += v; s2 += v*v;
    }
    #pragma unroll
    for (int off = 16; off; off >>= 1) {
        s1 += __shfl_xor_sync(~0u, s1, off);
        s2 += __shfl_xor_sync(~0u, s2, off);
    }
    float mu = s1 * (1.f/256.f);
    float var = s2 * (1.f/256.f) - mu*mu;
    float rstd = rsqrtf(var + 1e-5f);
    #pragma unroll
    for (int k = 0; k < 8; k++) {
        int dd = lane + 32*k;
        g_norm[r*256 + dd] = (vals[k] - mu) * rstd * ln_g[dd] + ln_b[dd];
    }
}

// ================= Kernel 8: out = x + normed @ Wo + bo (3-stage cp.async) ============
__global__ __launch_bounds__(256) void k8_mma(
    const float* __restrict__ x, const float* __restrict__ Wo,
    const float* __restrict__ bo, float* __restrict__ out)
{
    __shared__ __align__(16) float As[3][128][20];
    __shared__ __align__(16) float Bs[3][16][68];
    int row0 = blockIdx.x * 128;
    int colbase = blockIdx.y * 64;
    int tid = threadIdx.x;
    int w = tid >> 5, lane = tid & 31;
    int wm = (w & 3) * 32;
    int wn = (w >> 2) * 32;
    int lq = lane >> 2, lr = lane & 3;
    int r0 = tid >> 2, c4 = (tid & 3) * 4;
    int br = tid >> 4, bc4 = (tid & 15) * 4;
    float c[2][4][4] = {};

    #pragma unroll
    for (int p = 0; p < 2; p++) {
        int k0 = p * 16;
        cp_async16(&As[p][r0][c4],    &g_norm[(row0 + r0) * 256 + k0 + c4]);
        cp_async16(&As[p][r0+64][c4], &g_norm[(row0 + r0 + 64) * 256 + k0 + c4]);
        cp_async16(&Bs[p][br][bc4],   &Wo[(k0 + br) * 256 + colbase + bc4]);
        cp_commit();
    }

    for (int s = 0; s < 16; s++) {
        if (s < 15) cp_wait1(); else cp_wait0();
        __syncthreads();
        int cur = s % 3;
        #pragma unroll
        for (int ks = 0; ks < 2; ks++) {
            unsigned a[2][4];
            #pragma unroll
            for (int mt = 0; mt < 2; mt++) {
                int rr = wm + mt*16 + lq;
                int cc = ks*8 + lr;
                a[mt][0] = __float_as_uint(As[cur][rr][cc]);
                a[mt][1] = __float_as_uint(As[cur][rr+8][cc]);
                a[mt][2] = __float_as_uint(As[cur][rr][cc+4]);
                a[mt][3] = __float_as_uint(As[cur][rr+8][cc+4]);
            }
            #pragma unroll
            for (int nt = 0; nt < 4; nt++) {
                int bn = wn + nt*8 + lq;
                unsigned b0 = __float_as_uint(Bs[cur][ks*8+lr][bn]);
                unsigned b1 = __float_as_uint(Bs[cur][ks*8+lr+4][bn]);
                #pragma unroll
                for (int mt = 0; mt < 2; mt++)
                    mma_tf32(c[mt][nt], a[mt][0], a[mt][1], a[mt][2], a[mt][3], b0, b1);
            }
        }
        if (s < 14) {
            int st = (s + 2) % 3;
            int k0 = (s + 2) * 16;
            cp_async16(&As[st][r0][c4],    &g_norm[(row0 + r0) * 256 + k0 + c4]);
            cp_async16(&As[st][r0+64][c4], &g_norm[(row0 + r0 + 64) * 256 + k0 + c4]);
            cp_async16(&Bs[st][br][bc4],   &Wo[(k0 + br) * 256 + colbase + bc4]);
            cp_commit();
        }
    }
    #pragma unroll
    for (int mt = 0; mt < 2; mt++) {
        #pragma unroll
        for (int nt = 0; nt < 4; nt++) {
            int r = row0 + wm + mt*16 + lq;
            int cc = colbase + wn + nt*8 + lr*2;
            float b0v = bo[cc], b1v = bo[cc+1];
            float2 x0 = *(const float2*)&x[r * 256 + cc];
            float2 x1 = *(const float2*)&x[(r+8) * 256 + cc];
            *(float2*)&out[r * 256 + cc] =
                make_float2(c[mt][nt][0] + b0v + x0.x, c[mt][nt][1] + b1v + x0.y);
            *(float2*)&out[(r+8) * 256 + cc] =
                make_float2(c[mt][nt][2] + b0v + x1.x, c[mt][nt][3] + b1v + x1.y);
        }
    }
}

// ================= launcher =================
extern "C" void kernel_launch(void* const* d_in, const int* in_sizes, int n_in,
                              void* d_out, int out_size)
{
    const float* x   = (const float*)d_in[0];
    const float* bp  = (const float*)d_in[1];
    const float* Wk1 = (const float*)d_in[2];
    const float* bk1 = (const float*)d_in[3];
    const float* Wk2 = (const float*)d_in[4];
    const float* bk2 = (const float*)d_in[5];
    const float* Wq1 = (const float*)d_in[6];
    const float* bq1 = (const float*)d_in[7];
    const float* Wq2 = (const float*)d_in[8];
    const float* bq2 = (const float*)d_in[9];
    const float* Wvc = (const float*)d_in[10];
    const float* bvc = (const float*)d_in[11];
    const float* Wvp = (const float*)d_in[12];
    const float* bvp = (const float*)d_in[13];
    const float* Wg1 = (const float*)d_in[14];
    const float* bg1 = (const float*)d_in[15];
    const float* Wg2 = (const float*)d_in[16];
    const float* bg2 = (const float*)d_in[17];
    const float* lng = (const float*)d_in[18];
    const float* lnb = (const float*)d_in[19];
    const float* Wo  = (const float*)d_in[20];
    const float* bo  = (const float*)d_in[21];
    float* out = (float*)d_out;

    k1_mma<<<dim3(32, 17), 256>>>(x, Wk1, bk1, Wq1, bq1, Wvc, bvc, Wvp, bvp, Wg1, bg1);
    k23b_mma<<<128, 256>>>(Wk2, bk2, Wq2, bq2, Wg2, bg2, bp);
    k3a5_mma<<<100, 256>>>();
    k4_prefix<<<128, 256>>>();
    k6_mma<<<dim3(32, 4), 256>>>();
    k7_poscomb<<<512, 256>>>(lng, lnb);
    k8_mma<<<dim3(32, 4), 256>>>(x, Wo, bo, out);
}

// round 14
// speedup vs baseline: 1.5259x; 1.0530x over previous
#include <cuda_runtime.h>
#include <cuda_bf16.h>
#include <math.h>

// Problem constants
#define Bb 2
#define LL 2048
#define DD 256
#define KK 32
#define FF 64          // 2*K feature dim
#define MM (Bb*LL)     // 4096 rows
#define CC 128         // chunk size
#define NC (LL/CC)     // 16 chunks per batch
#define PI_F 3.14159265358979323846f

// ---------------- scratch (device globals; no allocation allowed) ----------------
__device__ float g_hk[MM*DD];
__device__ float g_hq[MM*DD];
__device__ float g_vc[MM*DD];
__device__ float g_vp[MM*DD];
__device__ float g_g1[MM*64];
__device__ float g_kf[MM*FF];
__device__ float g_qf[MM*FF];
__device__ float g_gates[MM*2];
__device__ float g_S[Bb*NC*FF*DD];         // per-chunk content state sums (mma)
__device__ float g_P[Bb*NC*FF*DD];         // chunk-level exclusive prefix of states
__device__ float g_psnap[Bb*64*4*2*DD];    // pos accum snapshots every 8 rows (inclusive)
__device__ float g_pprefix[Bb*64*2*DD];    // exclusive prefix at 32-row granularity
__device__ float g_scores[Bb*NC*CC*CC];    // intra-chunk masked scores
__device__ float g_cont[MM*DD];
__device__ float g_norm[MM*DD];
__device__ float g_cph[LL*DD];             // cached cos(base_phases[:LL])
__device__ float g_sph[LL*DD];             // cached sin(base_phases[:LL])

// mma consumes raw f32 bit patterns as tf32 (HW truncates mantissa; no cvt needed)
__device__ __forceinline__ void mma_tf32(float c[4],
    unsigned a0, unsigned a1, unsigned a2, unsigned a3,
    unsigned b0, unsigned b1)
{
    asm volatile(
        "mma.sync.aligned.m16n8k8.row.col.f32.tf32.tf32.f32 "
        "{%0,%1,%2,%3}, {%4,%5,%6,%7}, {%8,%9}, {%0,%1,%2,%3};"
        : "+f"(c[0]), "+f"(c[1]), "+f"(c[2]), "+f"(c[3])
        : "r"(a0), "r"(a1), "r"(a2), "r"(a3), "r"(b0), "r"(b1));
}

// ---------------- cp.async helpers ----------------
__device__ __forceinline__ void cp_async16(void* smem_dst, const void* gsrc) {
    unsigned saddr = (unsigned)__cvta_generic_to_shared(smem_dst);
    asm volatile("cp.async.cg.shared.global [%0], [%1], 16;" :: "r"(saddr), "l"(gsrc));
}
__device__ __forceinline__ void cp_commit() {
    asm volatile("cp.async.commit_group;");
}
__device__ __forceinline__ void cp_wait1() {
    asm volatile("cp.async.wait_group 1;");
}
__device__ __forceinline__ void cp_wait0() {
    asm volatile("cp.async.wait_group 0;");
}

// ================= Kernel 1: fused first-layer GEMMs, 128x128 tiles (3-stage) =========
// grid (32, 9): ct<8 -> [hk|hq|vc|vp] x 2 col-halves; ct==8 -> g1 (64 cols, predicated)
__global__ __launch_bounds__(256) void k1_mma(
    const float* __restrict__ x,
    const float* __restrict__ Wk1, const float* __restrict__ bk1,
    const float* __restrict__ Wq1, const float* __restrict__ bq1,
    const float* __restrict__ Wvc, const float* __restrict__ bvc,
    const float* __restrict__ Wvp, const float* __restrict__ bvp,
    const float* __restrict__ Wg1, const float* __restrict__ bg1)
{
    extern __shared__ __align__(16) float smem[];
    float (*As)[128][20] = (float(*)[128][20])smem;            // 3*2560 floats
    float (*Bs)[16][132] = (float(*)[16][132])(smem + 7680);   // 3*2112 floats
    int ct = blockIdx.y;
    const float* W; const float* bias; float* outp; int Nseg; int act; int colbase;
    if (ct < 8) {
        int seg = ct >> 1;
        colbase = (ct & 1) * 128;
        Nseg = 256;
        if (seg == 0)      { W = Wk1; bias = bk1; outp = g_hk; act = 1; }
        else if (seg == 1) { W = Wq1; bias = bq1; outp = g_hq; act = 1; }
        else if (seg == 2) { W = Wvc; bias = bvc; outp = g_vc; act = 0; }
        else               { W = Wvp; bias = bvp; outp = g_vp; act = 0; }
    } else {
        W = Wg1; bias = bg1; outp = g_g1; Nseg = 64; act = 2; colbase = 0;
    }
    int row0 = blockIdx.x * 128;
    int tid = threadIdx.x;
    int w = tid >> 5, lane = tid & 31;
    int wm = (w & 3) * 32;
    int wn = (w >> 2) * 64;
    int lq = lane >> 2, lr = lane & 3;
    int r0 = tid >> 2, c4 = (tid & 3) * 4;
    int rB = tid >> 5, cB = (tid & 31) * 4;
    bool bok = (colbase + cB) < Nseg;
    float c[2][8][4] = {};

    #pragma unroll
    for (int p = 0; p < 2; p++) {
        int k0 = p * 16;
        cp_async16(&As[p][r0][c4],    &x[(row0 + r0) * 256 + k0 + c4]);
        cp_async16(&As[p][r0+64][c4], &x[(row0 + r0 + 64) * 256 + k0 + c4]);
        if (bok) {
            cp_async16(&Bs[p][rB][cB],   &W[(k0 + rB) * Nseg + colbase + cB]);
            cp_async16(&Bs[p][rB+8][cB], &W[(k0 + rB + 8) * Nseg + colbase + cB]);
        }
        cp_commit();
    }

    for (int s = 0; s < 16; s++) {
        if (s < 15) cp_wait1(); else cp_wait0();
        __syncthreads();
        int cur = s % 3;
        #pragma unroll
        for (int ks = 0; ks < 2; ks++) {
            unsigned a[2][4];
            #pragma unroll
            for (int mt = 0; mt < 2; mt++) {
                int rr = wm + mt*16 + lq;
                int cc = ks*8 + lr;
                a[mt][0] = __float_as_uint(As[cur][rr][cc]);
                a[mt][1] = __float_as_uint(As[cur][rr+8][cc]);
                a[mt][2] = __float_as_uint(As[cur][rr][cc+4]);
                a[mt][3] = __float_as_uint(As[cur][rr+8][cc+4]);
            }
            #pragma unroll
            for (int nt = 0; nt < 8; nt++) {
                int bn = wn + nt*8 + lq;
                unsigned b0 = __float_as_uint(Bs[cur][ks*8+lr][bn]);
                unsigned b1 = __float_as_uint(Bs[cur][ks*8+lr+4][bn]);
                #pragma unroll
                for (int mt = 0; mt < 2; mt++)
                    mma_tf32(c[mt][nt], a[mt][0], a[mt][1], a[mt][2], a[mt][3], b0, b1);
            }
        }
        if (s < 14) {
            int st = (s + 2) % 3;
            int k0 = (s + 2) * 16;
            cp_async16(&As[st][r0][c4],    &x[(row0 + r0) * 256 + k0 + c4]);
            cp_async16(&As[st][r0+64][c4], &x[(row0 + r0 + 64) * 256 + k0 + c4]);
            if (bok) {
                cp_async16(&Bs[st][rB][cB],   &W[(k0 + rB) * Nseg + colbase + cB]);
                cp_async16(&Bs[st][rB+8][cB], &W[(k0 + rB + 8) * Nseg + colbase + cB]);
            }
            cp_commit();
        }
    }
    #pragma unroll
    for (int mt = 0; mt < 2; mt++) {
        #pragma unroll
        for (int nt = 0; nt < 8; nt++) {
            int cc = colbase + wn + nt*8 + lr*2;
            if (cc < Nseg) {
                int r = row0 + wm + mt*16 + lq;
                float b0v = bias[cc], b1v = bias[cc+1];
                float v00 = c[mt][nt][0] + b0v, v01 = c[mt][nt][1] + b1v;
                float v10 = c[mt][nt][2] + b0v, v11 = c[mt][nt][3] + b1v;
                if (act == 1) { v00 = tanhf(v00); v01 = tanhf(v01); v10 = tanhf(v10); v11 = tanhf(v11); }
                else if (act == 2) { v00 = fmaxf(v00,0.f); v01 = fmaxf(v01,0.f); v10 = fmaxf(v10,0.f); v11 = fmaxf(v11,0.f); }
                *(float2*)&outp[r * Nseg + cc] = make_float2(v00, v01);
                *(float2*)&outp[(r+8) * Nseg + cc] = make_float2(v10, v11);
            }
        }
    }
}

// ===== Kernel 2+3b merged: split phase GEMMs (3-stage cp.async) || pos partials =======
// blocks [0,32): k-path GEMM + gates; [32,64): q-path GEMM;
// blocks [64,128): pos partials for BOTH batches (one sincos, cached to g_cph/g_sph).
__global__ __launch_bounds__(256) void k23b_mma(
    const float* __restrict__ Wk2, const float* __restrict__ bk2,
    const float* __restrict__ Wq2, const float* __restrict__ bq2,
    const float* __restrict__ Wg2, const float* __restrict__ bg2,
    const float* __restrict__ base_phases)
{
    __shared__ __align__(16) float As[3][128][20];
    __shared__ __align__(16) float Bs[3][16][36];
    int tid = threadIdx.x;
    int bx = blockIdx.x;

    if (bx >= 64) {
        // ---- pos partial sums for both batches + sincos cache ----
        int s = bx - 64;            // 0..63
        int l0 = s * 32;
        int row0_0 = l0;            // b = 0
        int row0_1 = LL + l0;       // b = 1
        int d = tid;
        float par0 = 0.f, pai0 = 0.f, par1 = 0.f, pai1 = 0.f;
        #pragma unroll
        for (int g = 0; g < 4; g++) {
            float ph8[8], v0[8], v1[8];
            #pragma unroll
            for (int j = 0; j < 8; j++) {
                ph8[j] = base_phases[(l0 + g*8 + j) * 256 + d];
                v0[j] = g_vp[(row0_0 + g*8 + j) * 256 + d];
                v1[j] = g_vp[(row0_1 + g*8 + j) * 256 + d];
            }
            #pragma unroll
            for (int j = 0; j < 8; j++) {
                float sp, cp; __sincosf(ph8[j], &sp, &cp);
                int l = l0 + g*8 + j;
                g_cph[l*256 + d] = cp;
                g_sph[l*256 + d] = sp;
                par0 += v0[j] * cp; pai0 += v0[j] * sp;
                par1 += v1[j] * cp; pai1 += v1[j] * sp;
            }
            int sb0 = (s * 4 + g) * 512;
            int sb1 = ((64 + s) * 4 + g) * 512;
            g_psnap[sb0 + d] = par0; g_psnap[sb0 + 256 + d] = pai0;
            g_psnap[sb1 + d] = par1; g_psnap[sb1 + 256 + d] = pai1;
        }
        return;
    }

    // ---- phase-feature GEMM: one path per block ----
    bool isq = (bx >= 32);
    int row0 = (bx & 31) * 128;
    const float* H  = isq ? g_hq : g_hk;
    const float* W2 = isq ? Wq2 : Wk2;
    const float* bvec = isq ? bq2 : bk2;
    float* fdst = isq ? g_qf : g_kf;

    int w = tid >> 5, lane = tid & 31;
    int wm = (w & 3) * 32;
    int wn = (w >> 2) * 16;
    int lq = lane >> 2, lr = lane & 3;
    int r0 = tid >> 2, c4 = (tid & 3) * 4;
    int brB = tid >> 3, bc4B = (tid & 7) * 4;   // valid for tid < 128
    float c[2][2][4] = {};

    #pragma unroll
    for (int p = 0; p < 2; p++) {
        int k0 = p * 16;
        cp_async16(&As[p][r0][c4],    &H[(row0 + r0) * 256 + k0 + c4]);
        cp_async16(&As[p][r0+64][c4], &H[(row0 + r0 + 64) * 256 + k0 + c4]);
        if (tid < 128)
            cp_async16(&Bs[p][brB][bc4B], &W2[(k0 + brB) * 32 + bc4B]);
        cp_commit();
    }

    for (int s = 0; s < 16; s++) {
        if (s < 15) cp_wait1(); else cp_wait0();
        __syncthreads();
        int cur = s % 3;
        #pragma unroll
        for (int ks = 0; ks < 2; ks++) {
            unsigned a[2][4];
            #pragma unroll
            for (int mt = 0; mt < 2; mt++) {
                int rr = wm + mt*16 + lq;
                int cc = ks*8 + lr;
                a[mt][0] = __float_as_uint(As[cur][rr][cc]);
                a[mt][1] = __float_as_uint(As[cur][rr+8][cc]);
                a[mt][2] = __float_as_uint(As[cur][rr][cc+4]);
                a[mt][3] = __float_as_uint(As[cur][rr+8][cc+4]);
            }
            #pragma unroll
            for (int nt = 0; nt < 2; nt++) {
                int bn = wn + nt*8 + lq;
                unsigned b0 = __float_as_uint(Bs[cur][ks*8+lr][bn]);
                unsigned b1 = __float_as_uint(Bs[cur][ks*8+lr+4][bn]);
                #pragma unroll
                for (int mt = 0; mt < 2; mt++)
                    mma_tf32(c[mt][nt], a[mt][0], a[mt][1], a[mt][2], a[mt][3], b0, b1);
            }
        }
        if (s < 14) {
            int st = (s + 2) % 3;
            int k0 = (s + 2) * 16;
            cp_async16(&As[st][r0][c4],    &H[(row0 + r0) * 256 + k0 + c4]);
            cp_async16(&As[st][r0+64][c4], &H[(row0 + r0 + 64) * 256 + k0 + c4]);
            if (tid < 128)
                cp_async16(&Bs[st][brB][bc4B], &W2[(k0 + brB) * 32 + bc4B]);
            cp_commit();
        }
    }

    #pragma unroll
    for (int mt = 0; mt < 2; mt++) {
        #pragma unroll
        for (int nt = 0; nt < 2; nt++) {
            int r = row0 + wm + mt*16 + lq;
            int cn = wn + nt*8 + lr*2;
            float b0v = bvec[cn], b1v = bvec[cn+1];
            float ph;
            float sp, cp;
            ph = tanhf(c[mt][nt][0] + b0v) * PI_F; __sincosf(ph, &sp, &cp);
            fdst[r*64 + cn] = cp; fdst[r*64 + 32 + cn] = sp;
            ph = tanhf(c[mt][nt][1] + b1v) * PI_F; __sincosf(ph, &sp, &cp);
            fdst[r*64 + cn+1] = cp; fdst[r*64 + 32 + cn+1] = sp;
            ph = tanhf(c[mt][nt][2] + b0v) * PI_F; __sincosf(ph, &sp, &cp);
            fdst[(r+8)*64 + cn] = cp; fdst[(r+8)*64 + 32 + cn] = sp;
            ph = tanhf(c[mt][nt][3] + b1v) * PI_F; __sincosf(ph, &sp, &cp);
            fdst[(r+8)*64 + cn+1] = cp; fdst[(r+8)*64 + 32 + cn+1] = sp;
        }
    }
    // gates only in the k-path blocks
    if (!isq) {
        for (int rr = 0; rr < 16; rr++) {
            int r = row0 + w*16 + rr;
            float p0 = 0.f, p1 = 0.f;
            #pragma unroll
            for (int i = lane; i < 64; i += 32) {
                float gv = g_g1[r*64 + i];
                p0 += gv * Wg2[i*2 + 0];
                p1 += gv * Wg2[i*2 + 1];
            }
            #pragma unroll
            for (int off = 16; off; off >>= 1) {
                p0 += __shfl_xor_sync(~0u, p0, off);
                p1 += __shfl_xor_sync(~0u, p1, off);
            }
            if (lane == 0) {
                float l0 = p0 + bg2[0], l1 = p1 + bg2[1];
                float m = fmaxf(l0, l1);
                float e0 = __expf(l0 - m), e1 = __expf(l1 - m);
                float inv = 1.f / (e0 + e1);
                g_gates[r*2 + 0] = e0 * inv;
                g_gates[r*2 + 1] = e1 * inv;
            }
        }
    }
}

// ======== Kernel 3a+5 merged (+ pos prefix): chunk states || scores || pos-scan =======
// blocks [0,64): k3a; [64,96): k5 scores; [96,100): pos prefix (needs psnap from k23b).
__global__ __launch_bounds__(256) void k3a5_mma()
{
    __shared__ float sraw[10240];
    int tid = threadIdx.x;
    int w = tid >> 5, lane = tid & 31;
    int lq = lane >> 2, lr = lane & 3;

    if (blockIdx.x >= 96) {
        // ---- pos exclusive prefix over 64 s-groups ----
        int e = (blockIdx.x - 96) * 256 + tid;
        if (e < 1024) {
            int b = e >> 9, rd = e & 511;
            float v[64];
            #pragma unroll
            for (int s = 0; s < 64; s++)
                v[s] = g_psnap[((b * 64 + s) * 4 + 3) * 512 + rd];
            float run = 0.f;
            #pragma unroll
            for (int s = 0; s < 64; s++) {
                g_pprefix[(b * 64 + s) * 512 + rd] = run;
                run += v[s];
            }
        }
        return;
    }

    if (blockIdx.x < 64) {
        float (*Kl)[16][68]  = (float(*)[16][68])sraw;
        float (*Bs)[16][132] = (float(*)[16][132])(sraw + 2176);
        int bc = blockIdx.x & 31;
        int b = bc >> 4, c = bc & 15;
        int d0 = (blockIdx.x >> 5) * 128;
        int row0 = b * LL + c * CC;
        int wm = (w & 1) * 32, wn = (w >> 1) * 32;
        int af4 = (tid & 15) * 4, al = tid >> 4;
        int rB = tid >> 5, cB = (tid & 31) * 4;
        float acc[2][4][4] = {};
        float4 av, bv0, bv1;

        av  = *(const float4*)&g_kf[(row0 + al) * 64 + af4];
        bv0 = *(const float4*)&g_vc[(row0 + rB) * 256 + d0 + cB];
        bv1 = *(const float4*)&g_vc[(row0 + rB + 8) * 256 + d0 + cB];
        *(float4*)&Kl[0][al][af4] = av;
        *(float4*)&Bs[0][rB][cB] = bv0;
        *(float4*)&Bs[0][rB+8][cB] = bv1;
        __syncthreads();

        for (int s = 0; s < 8; s++) {
            int cur = s & 1;
            if (s < 7) {
                int kn = (s + 1) * 16;
                av  = *(const float4*)&g_kf[(row0 + kn + al) * 64 + af4];
                bv0 = *(const float4*)&g_vc[(row0 + kn + rB) * 256 + d0 + cB];
                bv1 = *(const float4*)&g_vc[(row0 + kn + rB + 8) * 256 + d0 + cB];
            }
            #pragma unroll
            for (int ks = 0; ks < 2; ks++) {
                unsigned a[2][4];
                #pragma unroll
                for (int mt = 0; mt < 2; mt++) {
                    int rr = wm + mt*16 + lq;
                    int cc = ks*8 + lr;
                    a[mt][0] = __float_as_uint(Kl[cur][cc][rr]);
                    a[mt][1] = __float_as_uint(Kl[cur][cc][rr+8]);
                    a[mt][2] = __float_as_uint(Kl[cur][cc+4][rr]);
                    a[mt][3] = __float_as_uint(Kl[cur][cc+4][rr+8]);
                }
                #pragma unroll
                for (int nt = 0; nt < 4; nt++) {
                    int bn = wn + nt*8 + lq;
                    unsigned b0 = __float_as_uint(Bs[cur][ks*8+lr][bn]);
                    unsigned b1 = __float_as_uint(Bs[cur][ks*8+lr+4][bn]);
                    #pragma unroll
                    for (int mt = 0; mt < 2; mt++)
                        mma_tf32(acc[mt][nt], a[mt][0], a[mt][1], a[mt][2], a[mt][3], b0, b1);
                }
            }
            if (s < 7) {
                int nb = cur ^ 1;
                *(float4*)&Kl[nb][al][af4] = av;
                *(float4*)&Bs[nb][rB][cB] = bv0;
                *(float4*)&Bs[nb][rB+8][cB] = bv1;
            }
            __syncthreads();
        }
        int base = bc * 64 * 256;
        #pragma unroll
        for (int mt = 0; mt < 2; mt++) {
            #pragma unroll
            for (int nt = 0; nt < 4; nt++) {
                int f = wm + mt*16 + lq;
                int dd = d0 + wn + nt*8 + lr*2;
                *(float2*)&g_S[base + f * 256 + dd] = make_float2(acc[mt][nt][0], acc[mt][nt][1]);
                *(float2*)&g_S[base + (f+8) * 256 + dd] = make_float2(acc[mt][nt][2], acc[mt][nt][3]);
            }
        }
        return;
    }

    {
        float (*As)[128][20] = (float(*)[128][20])sraw;
        float (*Ks)[128][20] = (float(*)[128][20])(sraw + 5120);
        int bc = blockIdx.x - 64;
        int b = bc >> 4, c = bc & 15;
        int row0 = b * LL + c * CC;
        int wm = (w & 3) * 32;
        int wn = (w >> 2) * 64;
        int r0 = tid >> 2, c4 = (tid & 3) * 4;
        float acc[2][8][4] = {};
        float4 a0v, a1v, u0, u1;

        a0v = *(const float4*)&g_qf[(row0 + r0) * 64 + c4];
        a1v = *(const float4*)&g_qf[(row0 + r0 + 64) * 64 + c4];
        u0  = *(const float4*)&g_kf[(row0 + r0) * 64 + c4];
        u1  = *(const float4*)&g_kf[(row0 + r0 + 64) * 64 + c4];
        *(float4*)&As[0][r0][c4] = a0v;
        *(float4*)&As[0][r0+64][c4] = a1v;
        *(float4*)&Ks[0][r0][c4] = u0;
        *(float4*)&Ks[0][r0+64][c4] = u1;
        __syncthreads();

        for (int s = 0; s < 4; s++) {
            int cur = s & 1;
            if (s < 3) {
                int kn = (s + 1) * 16;
                a0v = *(const float4*)&g_qf[(row0 + r0) * 64 + kn + c4];
                a1v = *(const float4*)&g_qf[(row0 + r0 + 64) * 64 + kn + c4];
                u0  = *(const float4*)&g_kf[(row0 + r0) * 64 + kn + c4];
                u1  = *(const float4*)&g_kf[(row0 + r0 + 64) * 64 + kn + c4];
            }
            #pragma unroll
            for (int ks = 0; ks < 2; ks++) {
                unsigned a[2][4];
                #pragma unroll
                for (int mt = 0; mt < 2; mt++) {
                    int rr = wm + mt*16 + lq;
                    int cc = ks*8 + lr;
                    a[mt][0] = __float_as_uint(As[cur][rr][cc]);
                    a[mt][1] = __float_as_uint(As[cur][rr+8][cc]);
                    a[mt][2] = __float_as_uint(As[cur][rr][cc+4]);
                    a[mt][3] = __float_as_uint(As[cur][rr+8][cc+4]);
                }
                #pragma unroll
                for (int nt = 0; nt < 8; nt++) {
                    int bn = wn + nt*8 + lq;
                    unsigned b0 = __float_as_uint(Ks[cur][bn][ks*8+lr]);
                    unsigned b1 = __float_as_uint(Ks[cur][bn][ks*8+lr+4]);
                    #pragma unroll
                    for (int mt = 0; mt < 2; mt++)
                        mma_tf32(acc[mt][nt], a[mt][0], a[mt][1], a[mt][2], a[mt][3], b0, b1);
                }
            }
            if (s < 3) {
                int nb = cur ^ 1;
                *(float4*)&As[nb][r0][c4] = a0v;
                *(float4*)&As[nb][r0+64][c4] = a1v;
                *(float4*)&Ks[nb][r0][c4] = u0;
                *(float4*)&Ks[nb][r0+64][c4] = u1;
            }
            __syncthreads();
        }
        int sb = bc * CC * CC;
        #pragma unroll
        for (int mt = 0; mt < 2; mt++) {
            #pragma unroll
            for (int nt = 0; nt < 8; nt++) {
                int la = wm + mt*16 + lq;
                int lb = la + 8;
                int j0 = wn + nt*8 + lr*2;
                int j1 = j0 + 1;
                *(float2*)&g_scores[sb + la*128 + j0] =
                    make_float2(j0 <= la ? acc[mt][nt][0] : 0.f, j1 <= la ? acc[mt][nt][1] : 0.f);
                *(float2*)&g_scores[sb + lb*128 + j0] =
                    make_float2(j0 <= lb ? acc[mt][nt][2] : 0.f, j1 <= lb ? acc[mt][nt][3] : 0.f);
            }
        }
    }
}

// ================= Kernel 4: content exclusive prefix only =================
__global__ __launch_bounds__(256) void k4_prefix()
{
    int tid = threadIdx.x;
    int idx = blockIdx.x * 256 + tid;
    int b = idx >> 14, rd = idx & 16383;
    float v[16];
    #pragma unroll
    for (int c = 0; c < 16; c++)
        v[c] = g_S[(b * 16 + c) * 16384 + rd];
    float run = 0.f;
    #pragma unroll
    for (int c = 0; c < 16; c++) {
        g_P[(b * 16 + c) * 16384 + rd] = run;
        run += v[c];
    }
}

// ================= Kernel 6: content output (3-stage cp.async) =================
__global__ __launch_bounds__(256) void k6_mma()
{
    __shared__ __align__(16) float As[3][128][20];
    __shared__ __align__(16) float Bs[3][16][68];
    int bc = blockIdx.x; int b = bc >> 4, c = bc & 15;
    int d0 = blockIdx.y * 64;
    int row0 = b * LL + c * CC;
    int tid = threadIdx.x;
    int w = tid >> 5, lane = tid & 31;
    int wm = (w & 3) * 32;
    int wn = (w >> 2) * 32;
    int lq = lane >> 2, lr = lane & 3;
    int r0 = tid >> 2, c4 = (tid & 3) * 4;
    int br = tid >> 4, bc4 = (tid & 15) * 4;
    int Pbase = bc * 64 * 256;
    int sbase = bc * CC * CC;
    float acc[2][4][4] = {};

    #pragma unroll
    for (int p = 0; p < 2; p++) {
        int k0 = p * 16;
        int kga = k0 + c4;
        const float *sa0, *sa1;
        if (kga < 64) {
            sa0 = &g_qf[(row0 + r0) * 64 + kga];
            sa1 = &g_qf[(row0 + r0 + 64) * 64 + kga];
        } else {
            sa0 = &g_scores[sbase + r0 * 128 + kga - 64];
            sa1 = &g_scores[sbase + (r0 + 64) * 128 + kga - 64];
        }
        int kgb = k0 + br;
        const float* sbp = (kgb < 64) ? &g_P[Pbase + kgb * 256 + d0 + bc4]
                                      : &g_vc[(row0 + kgb - 64) * 256 + d0 + bc4];
        cp_async16(&As[p][r0][c4], sa0);
        cp_async16(&As[p][r0+64][c4], sa1);
        cp_async16(&Bs[p][br][bc4], sbp);
        cp_commit();
    }

    for (int s = 0; s < 12; s++) {
        if (s < 11) cp_wait1(); else cp_wait0();
        __syncthreads();
        int cur = s % 3;
        #pragma unroll
        for (int ks = 0; ks < 2; ks++) {
            unsigned a[2][4];
            #pragma unroll
            for (int mt = 0; mt < 2; mt++) {
                int rr = wm + mt*16 + lq;
                int cc = ks*8 + lr;
                a[mt][0] = __float_as_uint(As[cur][rr][cc]);
                a[mt][1] = __float_as_uint(As[cur][rr+8][cc]);
                a[mt][2] = __float_as_uint(As[cur][rr][cc+4]);
                a[mt][3] = __float_as_uint(As[cur][rr+8][cc+4]);
            }
            #pragma unroll
            for (int nt = 0; nt < 4; nt++) {
                int bn = wn + nt*8 + lq;
                unsigned b0 = __float_as_uint(Bs[cur][ks*8+lr][bn]);
                unsigned b1 = __float_as_uint(Bs[cur][ks*8+lr+4][bn]);
                #pragma unroll
                for (int mt = 0; mt < 2; mt++)
                    mma_tf32(acc[mt][nt], a[mt][0], a[mt][1], a[mt][2], a[mt][3], b0, b1);
            }
        }
        if (s < 10) {
            int st = (s + 2) % 3;
            int k0 = (s + 2) * 16;
            int kga = k0 + c4;
            const float *sa0, *sa1;
            if (kga < 64) {
                sa0 = &g_qf[(row0 + r0) * 64 + kga];
                sa1 = &g_qf[(row0 + r0 + 64) * 64 + kga];
            } else {
                sa0 = &g_scores[sbase + r0 * 128 + kga - 64];
                sa1 = &g_scores[sbase + (r0 + 64) * 128 + kga - 64];
            }
            int kgb = k0 + br;
            const float* sbp = (kgb < 64) ? &g_P[Pbase + kgb * 256 + d0 + bc4]
                                          : &g_vc[(row0 + kgb - 64) * 256 + d0 + bc4];
            cp_async16(&As[st][r0][c4], sa0);
            cp_async16(&As[st][r0+64][c4], sa1);
            cp_async16(&Bs[st][br][bc4], sbp);
            cp_commit();
        }
    }
    #pragma unroll
    for (int mt = 0; mt < 2; mt++) {
        #pragma unroll
        for (int nt = 0; nt < 4; nt++) {
            int la = wm + mt*16 + lq;
            int lb = la + 8;
            int cc = d0 + wn + nt*8 + lr*2;
            float sa = rsqrtf((float)((c*CC + la + 1) * KK));
            float sb2 = rsqrtf((float)((c*CC + lb + 1) * KK));
            *(float2*)&g_cont[(row0 + la) * 256 + cc] =
                make_float2(acc[mt][nt][0] * sa, acc[mt][nt][1] * sa);
            *(float2*)&g_cont[(row0 + lb) * 256 + cc] =
                make_float2(acc[mt][nt][2] * sb2, acc[mt][nt][3] * sb2);
        }
    }
}

// ======== Kernel 7: pos scan (cached sincos) + gate combine + LayerNorm =========
__global__ __launch_bounds__(256) void k7_poscomb(
    const float* __restrict__ ln_g, const float* __restrict__ ln_b)
{
    __shared__ float comb[8][257];
    int blk = blockIdx.x;
    int j = blk & 3;
    int s = (blk >> 2) & 63;
    int b = blk >> 8;
    int row0 = b * LL + s * 32 + j * 8;
    int l0 = s * 32 + j * 8;
    int d = threadIdx.x;
    float ar = g_pprefix[(b * 64 + s) * 512 + d];
    float ai = g_pprefix[(b * 64 + s) * 512 + 256 + d];
    if (j > 0) {
        int snapbase = ((b * 64 + s) * 4 + j - 1) * 512;
        ar += g_psnap[snapbase + d];
        ai += g_psnap[snapbase + 256 + d];
    }
    float vp[8], cph[8], sph[8], cv[8];
    #pragma unroll
    for (int lt = 0; lt < 8; lt++) {
        vp[lt]  = g_vp[(row0 + lt) * 256 + d];
        cph[lt] = g_cph[(l0 + lt) * 256 + d];
        sph[lt] = g_sph[(l0 + lt) * 256 + d];
        cv[lt]  = g_cont[(row0 + lt) * 256 + d];
    }
    #pragma unroll
    for (int lt = 0; lt < 8; lt++) {
        ar += vp[lt] * cph[lt]; ai += vp[lt] * sph[lt];
        float pret = (ar * cph[lt] + ai * sph[lt]) * rsqrtf((float)(l0 + lt + 1));
        float g0 = g_gates[(row0 + lt) * 2], g1v = g_gates[(row0 + lt) * 2 + 1];
        comb[lt][d] = g0 * pret + g1v * cv[lt];
    }
    __syncthreads();
    int w = d >> 5, lane = d & 31;
    int r = row0 + w;
    float vals[8]; float s1 = 0.f, s2 = 0.f;
    #pragma unroll
    for (int k = 0; k < 8; k++) {
        float v = comb[w][lane + 32*k];
        vals[k] = v; s1 += v; s2 += v*v;
    }
    #pragma unroll
    for (int off = 16; off; off >>= 1) {
        s1 += __shfl_xor_sync(~0u, s1, off);
        s2 += __shfl_xor_sync(~0u, s2, off);
    }
    float mu = s1 * (1.f/256.f);
    float var = s2 * (1.f/256.f) - mu*mu;
    float rstd = rsqrtf(var + 1e-5f);
    #pragma unroll
    for (int k = 0; k < 8; k++) {
        int dd = lane + 32*k;
        g_norm[r*256 + dd] = (vals[k] - mu) * rstd * ln_g[dd] + ln_b[dd];
    }
}

// ================= Kernel 8: out = x + normed @ Wo + bo (3-stage cp.async) ============
__global__ __launch_bounds__(256) void k8_mma(
    const float* __restrict__ x, const float* __restrict__ Wo,
    const float* __restrict__ bo, float* __restrict__ out)
{
    __shared__ __align__(16) float As[3][128][20];
    __shared__ __align__(16) float Bs[3][16][68];
    int row0 = blockIdx.x * 128;
    int colbase = blockIdx.y * 64;
    int tid = threadIdx.x;
    int w = tid >> 5, lane = tid & 31;
    int wm = (w & 3) * 32;
    int wn = (w >> 2) * 32;
    int lq = lane >> 2, lr = lane & 3;
    int r0 = tid >> 2, c4 = (tid & 3) * 4;
    int br = tid >> 4, bc4 = (tid & 15) * 4;
    float c[2][4][4] = {};

    #pragma unroll
    for (int p = 0; p < 2; p++) {
        int k0 = p * 16;
        cp_async16(&As[p][r0][c4],    &g_norm[(row0 + r0) * 256 + k0 + c4]);
        cp_async16(&As[p][r0+64][c4], &g_norm[(row0 + r0 + 64) * 256 + k0 + c4]);
        cp_async16(&Bs[p][br][bc4],   &Wo[(k0 + br) * 256 + colbase + bc4]);
        cp_commit();
    }

    for (int s = 0; s < 16; s++) {
        if (s < 15) cp_wait1(); else cp_wait0();
        __syncthreads();
        int cur = s % 3;
        #pragma unroll
        for (int ks = 0; ks < 2; ks++) {
            unsigned a[2][4];
            #pragma unroll
            for (int mt = 0; mt < 2; mt++) {
                int rr = wm + mt*16 + lq;
                int cc = ks*8 + lr;
                a[mt][0] = __float_as_uint(As[cur][rr][cc]);
                a[mt][1] = __float_as_uint(As[cur][rr+8][cc]);
                a[mt][2] = __float_as_uint(As[cur][rr][cc+4]);
                a[mt][3] = __float_as_uint(As[cur][rr+8][cc+4]);
            }
            #pragma unroll
            for (int nt = 0; nt < 4; nt++) {
                int bn = wn + nt*8 + lq;
                unsigned b0 = __float_as_uint(Bs[cur][ks*8+lr][bn]);
                unsigned b1 = __float_as_uint(Bs[cur][ks*8+lr+4][bn]);
                #pragma unroll
                for (int mt = 0; mt < 2; mt++)
                    mma_tf32(c[mt][nt], a[mt][0], a[mt][1], a[mt][2], a[mt][3], b0, b1);
            }
        }
        if (s < 14) {
            int st = (s + 2) % 3;
            int k0 = (s + 2) * 16;
            cp_async16(&As[st][r0][c4],    &g_norm[(row0 + r0) * 256 + k0 + c4]);
            cp_async16(&As[st][r0+64][c4], &g_norm[(row0 + r0 + 64) * 256 + k0 + c4]);
            cp_async16(&Bs[st][br][bc4],   &Wo[(k0 + br) * 256 + colbase + bc4]);
            cp_commit();
        }
    }
    #pragma unroll
    for (int mt = 0; mt < 2; mt++) {
        #pragma unroll
        for (int nt = 0; nt < 4; nt++) {
            int r = row0 + wm + mt*16 + lq;
            int cc = colbase + wn + nt*8 + lr*2;
            float b0v = bo[cc], b1v = bo[cc+1];
            float2 x0 = *(const float2*)&x[r * 256 + cc];
            float2 x1 = *(const float2*)&x[(r+8) * 256 + cc];
            *(float2*)&out[r * 256 + cc] =
                make_float2(c[mt][nt][0] + b0v + x0.x, c[mt][nt][1] + b1v + x0.y);
            *(float2*)&out[(r+8) * 256 + cc] =
                make_float2(c[mt][nt][2] + b0v + x1.x, c[mt][nt][3] + b1v + x1.y);
        }
    }
}

// ================= launcher =================
extern "C" void kernel_launch(void* const* d_in, const int* in_sizes, int n_in,
                              void* d_out, int out_size)
{
    const float* x   = (const float*)d_in[0];
    const float* bp  = (const float*)d_in[1];
    const float* Wk1 = (const float*)d_in[2];
    const float* bk1 = (const float*)d_in[3];
    const float* Wk2 = (const float*)d_in[4];
    const float* bk2 = (const float*)d_in[5];
    const float* Wq1 = (const float*)d_in[6];
    const float* bq1 = (const float*)d_in[7];
    const float* Wq2 = (const float*)d_in[8];
    const float* bq2 = (const float*)d_in[9];
    const float* Wvc = (const float*)d_in[10];
    const float* bvc = (const float*)d_in[11];
    const float* Wvp = (const float*)d_in[12];
    const float* bvp = (const float*)d_in[13];
    const float* Wg1 = (const float*)d_in[14];
    const float* bg1 = (const float*)d_in[15];
    const float* Wg2 = (const float*)d_in[16];
    const float* bg2 = (const float*)d_in[17];
    const float* lng = (const float*)d_in[18];
    const float* lnb = (const float*)d_in[19];
    const float* Wo  = (const float*)d_in[20];
    const float* bo  = (const float*)d_in[21];
    float* out = (float*)d_out;

    cudaFuncSetAttribute(k1_mma, cudaFuncAttributeMaxDynamicSharedMemorySize, 57344);
    k1_mma<<<dim3(32, 9), 256, 56064>>>(x, Wk1, bk1, Wq1, bq1, Wvc, bvc, Wvp, bvp, Wg1, bg1);
    k23b_mma<<<128, 256>>>(Wk2, bk2, Wq2, bq2, Wg2, bg2, bp);
    k3a5_mma<<<100, 256>>>();
    k4_prefix<<<128, 256>>>();
    k6_mma<<<dim3(32, 4), 256>>>();
    k7_poscomb<<<512, 256>>>(lng, lnb);
    k8_mma<<<dim3(32, 4), 256>>>(x, Wo, bo, out);
}